// round 5
// baseline (speedup 1.0000x reference)
#include <cuda_runtime.h>
#include <cuda_bf16.h>
#include <cstdint>

// Problem constants
#define BB 4
#define SS 2048
#define DD 1024
#define HH 16
#define HD 64
#define MM (BB * SS)   // 8192 rows

typedef unsigned long long u64;

// ---------------- scratch (device globals; allocation-free rule) ----------------
__device__ float g_Q[MM * DD];
__device__ float g_K[MM * DD];
__device__ float g_V[MM * DD];
__device__ float g_Oa[MM * DD];

__device__ __nv_bfloat16 g_xhi[MM * DD];
__device__ __nv_bfloat16 g_xlo[MM * DD];
__device__ __nv_bfloat16 g_oahi[MM * DD];
__device__ __nv_bfloat16 g_oalo[MM * DD];

// weights: transposed [n][k] for q/k/v; plain [n][k] (= row-major Wo) for o
__device__ __nv_bfloat16 g_wq_hi[DD * DD];
__device__ __nv_bfloat16 g_wq_lo[DD * DD];
__device__ __nv_bfloat16 g_wk_hi[DD * DD];
__device__ __nv_bfloat16 g_wk_lo[DD * DD];
__device__ __nv_bfloat16 g_wv_hi[DD * DD];
__device__ __nv_bfloat16 g_wv_lo[DD * DD];
__device__ __nv_bfloat16 g_wo_hi[DD * DD];
__device__ __nv_bfloat16 g_wo_lo[DD * DD];

// ---------------- PTX helpers (all plain sm_80/90 features, no 'a' suffix) ------
__device__ __forceinline__ uint32_t smem_u32(const void* p) {
    uint32_t a;
    asm("{ .reg .u64 t; cvta.to.shared.u64 t, %1; cvt.u32.u64 %0, t; }" : "=r"(a) : "l"(p));
    return a;
}
__device__ __forceinline__ void cp16(uint32_t dst, const void* src) {
    asm volatile("cp.async.cg.shared.global [%0], [%1], 16;" :: "r"(dst), "l"(src) : "memory");
}
#define CP_COMMIT() asm volatile("cp.async.commit_group;" ::: "memory")
#define CP_WAIT(n) asm volatile("cp.async.wait_group %0;" :: "n"(n) : "memory")

__device__ __forceinline__ void ldm4(uint32_t* d, uint32_t addr) {
    asm volatile("ldmatrix.sync.aligned.m8n8.x4.shared.b16 {%0,%1,%2,%3}, [%4];"
                 : "=r"(d[0]), "=r"(d[1]), "=r"(d[2]), "=r"(d[3]) : "r"(addr));
}
__device__ __forceinline__ void mma16816(float* c, const uint32_t* a, uint32_t b0, uint32_t b1) {
    asm volatile(
        "mma.sync.aligned.m16n8k16.row.col.f32.bf16.bf16.f32 "
        "{%0,%1,%2,%3}, {%4,%5,%6,%7}, {%8,%9}, {%0,%1,%2,%3};"
        : "+f"(c[0]), "+f"(c[1]), "+f"(c[2]), "+f"(c[3])
        : "r"(a[0]), "r"(a[1]), "r"(a[2]), "r"(a[3]), "r"(b0), "r"(b1));
}

// ---------------- packed f32x2 helpers (attention) ----------------
__device__ __forceinline__ u64 ffma2(u64 a, u64 b, u64 c) {
    u64 d;
    asm("fma.rn.f32x2 %0, %1, %2, %3;" : "=l"(d) : "l"(a), "l"(b), "l"(c));
    return d;
}
__device__ __forceinline__ u64 fadd2(u64 a, u64 b) {
    u64 d;
    asm("add.rn.f32x2 %0, %1, %2;" : "=l"(d) : "l"(a), "l"(b));
    return d;
}
__device__ __forceinline__ u64 fdup2(float a) {
    u64 r;
    asm("mov.b64 %0, {%1, %1};" : "=l"(r) : "f"(a));
    return r;
}
__device__ __forceinline__ float2 unpack2(u64 a) {
    float2 f;
    asm("mov.b64 {%0, %1}, %2;" : "=f"(f.x), "=f"(f.y) : "l"(a));
    return f;
}

// ---------------- split / transpose prep kernels ----------------
__global__ void __launch_bounds__(256)
split_kernel(const float* __restrict__ src, __nv_bfloat16* __restrict__ hi,
             __nv_bfloat16* __restrict__ lo, int n4) {
    int i = blockIdx.x * 256 + threadIdx.x;
    if (i >= n4) return;
    float4 v = ((const float4*)src)[i];
    __nv_bfloat16 h0 = __float2bfloat16(v.x);
    __nv_bfloat16 h1 = __float2bfloat16(v.y);
    __nv_bfloat16 h2 = __float2bfloat16(v.z);
    __nv_bfloat16 h3 = __float2bfloat16(v.w);
    __nv_bfloat16 l0 = __float2bfloat16(v.x - __bfloat162float(h0));
    __nv_bfloat16 l1 = __float2bfloat16(v.y - __bfloat162float(h1));
    __nv_bfloat16 l2 = __float2bfloat16(v.z - __bfloat162float(h2));
    __nv_bfloat16 l3 = __float2bfloat16(v.w - __bfloat162float(h3));
    ushort4 hv, lv;
    hv.x = __bfloat16_as_ushort(h0); hv.y = __bfloat16_as_ushort(h1);
    hv.z = __bfloat16_as_ushort(h2); hv.w = __bfloat16_as_ushort(h3);
    lv.x = __bfloat16_as_ushort(l0); lv.y = __bfloat16_as_ushort(l1);
    lv.z = __bfloat16_as_ushort(l2); lv.w = __bfloat16_as_ushort(l3);
    ((ushort4*)hi)[i] = hv;
    ((ushort4*)lo)[i] = lv;
}

// Wt[n][k] = W[k][n], split into hi/lo bf16 (for q/k/v weights)
__global__ void __launch_bounds__(256)
transpose_split_kernel(const float* __restrict__ Wq, const float* __restrict__ Wk,
                       const float* __restrict__ Wv) {
    const float* W = (blockIdx.z == 0) ? Wq : ((blockIdx.z == 1) ? Wk : Wv);
    __nv_bfloat16* hi = (blockIdx.z == 0) ? g_wq_hi : ((blockIdx.z == 1) ? g_wk_hi : g_wv_hi);
    __nv_bfloat16* lo = (blockIdx.z == 0) ? g_wq_lo : ((blockIdx.z == 1) ? g_wk_lo : g_wv_lo);
    __shared__ float t[32][33];
    int tx = threadIdx.x & 31;
    int ty = threadIdx.x >> 5;   // 0..7
    int k0 = blockIdx.y * 32;
    int n0 = blockIdx.x * 32;
#pragma unroll
    for (int i = 0; i < 4; i++)
        t[ty + i * 8][tx] = W[(size_t)(k0 + ty + i * 8) * DD + n0 + tx];
    __syncthreads();
#pragma unroll
    for (int i = 0; i < 4; i++) {
        int n = n0 + ty + i * 8;
        int k = k0 + tx;
        float v = t[tx][ty + i * 8];
        __nv_bfloat16 h = __float2bfloat16(v);
        hi[(size_t)n * DD + k] = h;
        lo[(size_t)n * DD + k] = __float2bfloat16(v - __bfloat162float(h));
    }
}

// ---------------- HMMA split-bf16 GEMM ----------------
// C[M,N] = A @ B^T, A=[M,K] hi/lo bf16, B=[N,K] hi/lo bf16, fp32 accum.
// 128x128 tile, BK=32, 256 threads (8 warps as 4m x 2n), warp tile 32x64.
// SMEM rows padded to 80B (stride 40 bf16) -> conflict-free ldmatrix.
#define BK 32
#define ROWB 80                       // bytes per smem row (32 bf16 + 8 pad)
#define MAT_BYTES (128 * ROWB)        // 10240
#define OFF_AH 0
#define OFF_AL (1 * MAT_BYTES)
#define OFF_BH (2 * MAT_BYTES)
#define OFF_BL (3 * MAT_BYTES)
#define STAGE_BYTES (4 * MAT_BYTES)   // 40960
#define GSMEM_TOTAL (2 * STAGE_BYTES) // 81920

__device__ __forceinline__ void load_stage(uint32_t sb,
                                           const __nv_bfloat16* __restrict__ ahi,
                                           const __nv_bfloat16* __restrict__ alo,
                                           const __nv_bfloat16* __restrict__ bhi,
                                           const __nv_bfloat16* __restrict__ blo,
                                           int m0, int n0, int kt, int tid) {
#pragma unroll
    for (int i = 0; i < 2; i++) {
        int idx = tid + i * 256;          // 0..511
        int r = idx >> 2;                 // 0..127
        int c = idx & 3;                  // 16B chunk
        uint32_t so = (uint32_t)(r * ROWB + c * 16);
        size_t goA = (size_t)(m0 + r) * DD + kt + c * 8;
        size_t goB = (size_t)(n0 + r) * DD + kt + c * 8;
        cp16(sb + OFF_AH + so, ahi + goA);
        cp16(sb + OFF_AL + so, alo + goA);
        cp16(sb + OFF_BH + so, bhi + goB);
        cp16(sb + OFF_BL + so, blo + goB);
    }
}

__device__ __forceinline__ void gemm_core(const __nv_bfloat16* __restrict__ ahi,
                                          const __nv_bfloat16* __restrict__ alo,
                                          const __nv_bfloat16* __restrict__ bhi,
                                          const __nv_bfloat16* __restrict__ blo,
                                          float* __restrict__ C) {
    extern __shared__ char sm[];
    uint32_t sbase = smem_u32(sm);
    const int tid = threadIdx.x;
    const int wid = tid >> 5;
    const int lane = tid & 31;
    const int wm = wid & 3;               // 4 m-blocks of 32 rows
    const int wn = wid >> 2;              // 2 n-blocks of 64 cols
    const int m0 = blockIdx.y * 128;
    const int n0 = blockIdx.x * 128;

    // ldmatrix per-thread address components
    const int g = lane >> 3;              // tile group 0..3
    const int rr = lane & 7;
    // A: g=0: m-lo@k0, g=1: m-hi@k0, g=2: m-lo@k8, g=3: m-hi@k8
    const uint32_t aoff = (uint32_t)((wm * 32 + (g & 1) * 8 + rr) * ROWB + (g >> 1) * 16);
    // B: g=0: n-lo@k0, g=1: n-lo@k8, g=2: n-hi@k0, g=3: n-hi@k8
    const uint32_t boff = (uint32_t)((wn * 64 + (g >> 1) * 8 + rr) * ROWB + (g & 1) * 16);

    float acc[2][8][4];
#pragma unroll
    for (int mi = 0; mi < 2; mi++)
#pragma unroll
        for (int ni = 0; ni < 8; ni++)
#pragma unroll
            for (int j = 0; j < 4; j++) acc[mi][ni][j] = 0.0f;

    const int NST = DD / BK;              // 32
    load_stage(sbase, ahi, alo, bhi, blo, m0, n0, 0, tid);
    CP_COMMIT();

    for (int s = 0; s < NST; s++) {
        if (s + 1 < NST) {
            load_stage(sbase + ((s + 1) & 1) * STAGE_BYTES,
                       ahi, alo, bhi, blo, m0, n0, (s + 1) * BK, tid);
            CP_COMMIT();
            CP_WAIT(1);
        } else {
            CP_WAIT(0);
        }
        __syncthreads();
        uint32_t sb = sbase + (s & 1) * STAGE_BYTES;

#pragma unroll
        for (int kk = 0; kk < 2; kk++) {  // two k16 steps
            uint32_t ah[2][4], al[2][4], bh[4][4], bl[4][4];
#pragma unroll
            for (int mi = 0; mi < 2; mi++) {
                uint32_t ao = sb + aoff + (uint32_t)(mi * 16 * ROWB + kk * 32);
                ldm4(ah[mi], ao + OFF_AH);
                ldm4(al[mi], ao + OFF_AL);
            }
#pragma unroll
            for (int np = 0; np < 4; np++) {
                uint32_t bo = sb + boff + (uint32_t)(np * 16 * ROWB + kk * 32);
                ldm4(bh[np], bo + OFF_BH);
                ldm4(bl[np], bo + OFF_BL);
            }
#pragma unroll
            for (int mi = 0; mi < 2; mi++)
#pragma unroll
                for (int ni = 0; ni < 8; ni++) {
                    int np = ni >> 1;
                    int h = (ni & 1) * 2;
                    mma16816(acc[mi][ni], ah[mi], bh[np][h], bh[np][h + 1]);
                    mma16816(acc[mi][ni], ah[mi], bl[np][h], bl[np][h + 1]);
                    mma16816(acc[mi][ni], al[mi], bh[np][h], bh[np][h + 1]);
                }
        }
        __syncthreads();
    }

    // epilogue
    const int row_b = m0 + wm * 32 + (lane >> 2);
    const int col_b = n0 + wn * 64 + (lane & 3) * 2;
#pragma unroll
    for (int mi = 0; mi < 2; mi++)
#pragma unroll
        for (int ni = 0; ni < 8; ni++) {
            int row = row_b + mi * 16;
            int col = col_b + ni * 8;
            *(float2*)&C[(size_t)row * DD + col] =
                make_float2(acc[mi][ni][0], acc[mi][ni][1]);
            *(float2*)&C[(size_t)(row + 8) * DD + col] =
                make_float2(acc[mi][ni][2], acc[mi][ni][3]);
        }
}

__global__ void __launch_bounds__(256)
gemm_qkv_kernel() {
    const __nv_bfloat16* bhi = (blockIdx.z == 0) ? g_wq_hi : ((blockIdx.z == 1) ? g_wk_hi : g_wv_hi);
    const __nv_bfloat16* blo = (blockIdx.z == 0) ? g_wq_lo : ((blockIdx.z == 1) ? g_wk_lo : g_wv_lo);
    float* C = (blockIdx.z == 0) ? g_Q : ((blockIdx.z == 1) ? g_K : g_V);
    gemm_core(g_xhi, g_xlo, bhi, blo, C);
}

__global__ void __launch_bounds__(256)
gemm_out_kernel(float* __restrict__ out) {
    gemm_core(g_oahi, g_oalo, g_wo_hi, g_wo_lo, out);
}

// ---------------- Causal flash attention, fp32, 1 thread = 1 query row ----------------
#define ATTN_SMEM_FLOATS (64 * 64 * 2 + 128 * 65)
#define ATTN_SMEM_BYTES (ATTN_SMEM_FLOATS * 4)

__global__ void __launch_bounds__(128)
attn_kernel() {
    extern __shared__ float sh[];
    float* k_sh = sh;                  // [64][64]
    float* v_sh = sh + 64 * 64;        // [64][64]
    float* p_sh = sh + 2 * 64 * 64;    // [128][65]

    const int tid = threadIdx.x;
    const int bh = blockIdx.y;
    const int b = bh >> 4;
    const int h = bh & 15;
    const int q0 = blockIdx.x * 128;
    const int qg = q0 + tid;

    const float* Qrow = g_Q + ((size_t)(b * SS + qg)) * DD + h * HD;
    u64 q2[32];
    {
        const u64* qp = (const u64*)Qrow;
#pragma unroll
        for (int i = 0; i < 32; i++) q2[i] = qp[i];
    }
    u64 acc2[32];
#pragma unroll
    for (int i = 0; i < 32; i++) acc2[i] = 0ull;
    float m = -1e30f, l = 0.0f;
    float* prow = p_sh + tid * 65;

    const float* Kbase = g_K + ((size_t)(b * SS)) * DD + h * HD;
    const float* Vbase = g_V + ((size_t)(b * SS)) * DD + h * HD;

    const int k_end = q0 + 128;
    for (int k0 = 0; k0 < k_end; k0 += 64) {
#pragma unroll
        for (int i = 0; i < 8; i++) {
            int idx = i * 128 + tid;
            int r = idx >> 4, c = (idx & 15) * 4;
            *(float4*)&k_sh[r * 64 + c] =
                *(const float4*)&Kbase[(size_t)(k0 + r) * DD + c];
        }
        __syncthreads();

        float mt = -1e30f;
        for (int j = 0; j < 64; j++) {
            const u64* kr = (const u64*)&k_sh[j * 64];
            u64 s0 = 0ull, s1 = 0ull, s2 = 0ull, s3 = 0ull;
#pragma unroll
            for (int i = 0; i < 8; i++) {
                s0 = ffma2(q2[i * 4 + 0], kr[i * 4 + 0], s0);
                s1 = ffma2(q2[i * 4 + 1], kr[i * 4 + 1], s1);
                s2 = ffma2(q2[i * 4 + 2], kr[i * 4 + 2], s2);
                s3 = ffma2(q2[i * 4 + 3], kr[i * 4 + 3], s3);
            }
            u64 st = fadd2(fadd2(s0, s1), fadd2(s2, s3));
            float2 sp = unpack2(st);
            float s = (sp.x + sp.y) * 0.125f;
            if (k0 + j > qg) s = -1e30f;
            prow[j] = s;
            mt = fmaxf(mt, s);
        }

        float mn = fmaxf(m, mt);
        float alpha = __expf(m - mn);
        float l0 = 0.0f, l1 = 0.0f;
#pragma unroll 8
        for (int j = 0; j < 64; j += 2) {
            float e0 = __expf(prow[j] - mn);
            float e1 = __expf(prow[j + 1] - mn);
            prow[j] = e0;
            prow[j + 1] = e1;
            l0 += e0;
            l1 += e1;
        }
        l = l * alpha + l0 + l1;
        m = mn;
        u64 a2 = fdup2(alpha);
        u64 z = 0ull;
#pragma unroll
        for (int i = 0; i < 32; i++) acc2[i] = ffma2(acc2[i], a2, z);

#pragma unroll
        for (int i = 0; i < 8; i++) {
            int idx = i * 128 + tid;
            int r = idx >> 4, c = (idx & 15) * 4;
            *(float4*)&v_sh[r * 64 + c] =
                *(const float4*)&Vbase[(size_t)(k0 + r) * DD + c];
        }
        __syncthreads();

        for (int j = 0; j < 64; j++) {
            u64 p2 = fdup2(prow[j]);
            const u64* vr = (const u64*)&v_sh[j * 64];
#pragma unroll
            for (int i = 0; i < 32; i++) acc2[i] = ffma2(p2, vr[i], acc2[i]);
        }
    }

    float inv = 1.0f / l;
    u64 inv2 = fdup2(inv);
    u64 z = 0ull;
    u64* op = (u64*)(g_Oa + ((size_t)(b * SS + qg)) * DD + h * HD);
#pragma unroll
    for (int i = 0; i < 32; i++) op[i] = ffma2(acc2[i], inv2, z);
}

// ---------------- launch ----------------
extern "C" void kernel_launch(void* const* d_in, const int* in_sizes, int n_in,
                              void* d_out, int out_size) {
    const float* x  = (const float*)d_in[0];
    const float* Wq = (const float*)d_in[1];
    const float* Wk = (const float*)d_in[2];
    const float* Wv = (const float*)d_in[3];
    const float* Wo = (const float*)d_in[4];
    float* out = (float*)d_out;

    cudaFuncSetAttribute(attn_kernel,
                         cudaFuncAttributeMaxDynamicSharedMemorySize, ATTN_SMEM_BYTES);
    cudaFuncSetAttribute(gemm_qkv_kernel,
                         cudaFuncAttributeMaxDynamicSharedMemorySize, GSMEM_TOTAL);
    cudaFuncSetAttribute(gemm_out_kernel,
                         cudaFuncAttributeMaxDynamicSharedMemorySize, GSMEM_TOTAL);

    __nv_bfloat16 *p_xhi, *p_xlo, *p_oahi, *p_oalo, *p_wohi, *p_wolo;
    float* p_oa;
    cudaGetSymbolAddress((void**)&p_xhi, g_xhi);
    cudaGetSymbolAddress((void**)&p_xlo, g_xlo);
    cudaGetSymbolAddress((void**)&p_oahi, g_oahi);
    cudaGetSymbolAddress((void**)&p_oalo, g_oalo);
    cudaGetSymbolAddress((void**)&p_wohi, g_wo_hi);
    cudaGetSymbolAddress((void**)&p_wolo, g_wo_lo);
    cudaGetSymbolAddress((void**)&p_oa, g_Oa);

    split_kernel<<<(MM * DD / 4 + 255) / 256, 256>>>(x, p_xhi, p_xlo, MM * DD / 4);
    split_kernel<<<(DD * DD / 4 + 255) / 256, 256>>>(Wo, p_wohi, p_wolo, DD * DD / 4);
    transpose_split_kernel<<<dim3(32, 32, 3), 256>>>(Wq, Wk, Wv);

    dim3 gq(DD / 128, MM / 128, 3);       // (8, 64, 3)
    gemm_qkv_kernel<<<gq, 256, GSMEM_TOTAL>>>();

    dim3 ga(SS / 128, BB * HH);           // (16, 64)
    attn_kernel<<<ga, 128, ATTN_SMEM_BYTES>>>();

    split_kernel<<<(MM * DD / 4 + 255) / 256, 256>>>(p_oa, p_oahi, p_oalo, MM * DD / 4);

    dim3 go(DD / 128, MM / 128, 1);       // (8, 64)
    gemm_out_kernel<<<go, 256, GSMEM_TOTAL>>>(out);
}

// round 7
// speedup vs baseline: 2.4432x; 2.4432x over previous
#include <cuda_runtime.h>
#include <cuda_bf16.h>
#include <cstdint>

// Problem constants
#define BB 4
#define SS 2048
#define DD 1024
#define HH 16
#define HD 64
#define MM (BB * SS)   // 8192 rows

typedef unsigned long long u64;

// ---------------- scratch (device globals; allocation-free rule) ----------------
// Q/K/V live only as bf16 hi/lo splits (Q pre-scaled by 0.125)
__device__ __nv_bfloat16 g_qhi[MM * DD];
__device__ __nv_bfloat16 g_qlo[MM * DD];
__device__ __nv_bfloat16 g_khi[MM * DD];
__device__ __nv_bfloat16 g_klo[MM * DD];
__device__ __nv_bfloat16 g_vhi[MM * DD];
__device__ __nv_bfloat16 g_vlo[MM * DD];

__device__ __nv_bfloat16 g_xhi[MM * DD];
__device__ __nv_bfloat16 g_xlo[MM * DD];
__device__ __nv_bfloat16 g_oahi[MM * DD];
__device__ __nv_bfloat16 g_oalo[MM * DD];

// weights: transposed [n][k] for q/k/v; plain [n][k] (= row-major Wo) for o
__device__ __nv_bfloat16 g_wq_hi[DD * DD];
__device__ __nv_bfloat16 g_wq_lo[DD * DD];
__device__ __nv_bfloat16 g_wk_hi[DD * DD];
__device__ __nv_bfloat16 g_wk_lo[DD * DD];
__device__ __nv_bfloat16 g_wv_hi[DD * DD];
__device__ __nv_bfloat16 g_wv_lo[DD * DD];
__device__ __nv_bfloat16 g_wo_hi[DD * DD];
__device__ __nv_bfloat16 g_wo_lo[DD * DD];

// ---------------- PTX helpers (plain sm_80/90 features only) ----------------
__device__ __forceinline__ uint32_t smem_u32(const void* p) {
    uint32_t a;
    asm("{ .reg .u64 t; cvta.to.shared.u64 t, %1; cvt.u32.u64 %0, t; }" : "=r"(a) : "l"(p));
    return a;
}
__device__ __forceinline__ void cp16(uint32_t dst, const void* src) {
    asm volatile("cp.async.cg.shared.global [%0], [%1], 16;" :: "r"(dst), "l"(src) : "memory");
}
#define CP_COMMIT() asm volatile("cp.async.commit_group;" ::: "memory")
#define CP_WAIT(n) asm volatile("cp.async.wait_group %0;" :: "n"(n) : "memory")

__device__ __forceinline__ void ldm4(uint32_t* d, uint32_t addr) {
    asm volatile("ldmatrix.sync.aligned.m8n8.x4.shared.b16 {%0,%1,%2,%3}, [%4];"
                 : "=r"(d[0]), "=r"(d[1]), "=r"(d[2]), "=r"(d[3]) : "r"(addr));
}
__device__ __forceinline__ void ldm4t(uint32_t* d, uint32_t addr) {
    asm volatile("ldmatrix.sync.aligned.m8n8.x4.trans.shared.b16 {%0,%1,%2,%3}, [%4];"
                 : "=r"(d[0]), "=r"(d[1]), "=r"(d[2]), "=r"(d[3]) : "r"(addr));
}
__device__ __forceinline__ void mma16816(float* c, const uint32_t* a, uint32_t b0, uint32_t b1) {
    asm volatile(
        "mma.sync.aligned.m16n8k16.row.col.f32.bf16.bf16.f32 "
        "{%0,%1,%2,%3}, {%4,%5,%6,%7}, {%8,%9}, {%0,%1,%2,%3};"
        : "+f"(c[0]), "+f"(c[1]), "+f"(c[2]), "+f"(c[3])
        : "r"(a[0]), "r"(a[1]), "r"(a[2]), "r"(a[3]), "r"(b0), "r"(b1));
}
__device__ __forceinline__ uint32_t pack_bf16_hi(float x, float y, float& rx, float& ry) {
    __nv_bfloat162 h = __float22bfloat162_rn(make_float2(x, y));
    float2 f = __bfloat1622float2(h);
    rx = x - f.x;
    ry = y - f.y;
    return *(uint32_t*)&h;
}
__device__ __forceinline__ uint32_t pack_bf16(float x, float y) {
    __nv_bfloat162 h = __float22bfloat162_rn(make_float2(x, y));
    return *(uint32_t*)&h;
}

// ---------------- split / transpose prep kernels ----------------
__global__ void __launch_bounds__(256)
split_kernel(const float* __restrict__ src, __nv_bfloat16* __restrict__ hi,
             __nv_bfloat16* __restrict__ lo, int n4) {
    int i = blockIdx.x * 256 + threadIdx.x;
    if (i >= n4) return;
    float4 v = ((const float4*)src)[i];
    __nv_bfloat16 h0 = __float2bfloat16(v.x);
    __nv_bfloat16 h1 = __float2bfloat16(v.y);
    __nv_bfloat16 h2 = __float2bfloat16(v.z);
    __nv_bfloat16 h3 = __float2bfloat16(v.w);
    __nv_bfloat16 l0 = __float2bfloat16(v.x - __bfloat162float(h0));
    __nv_bfloat16 l1 = __float2bfloat16(v.y - __bfloat162float(h1));
    __nv_bfloat16 l2 = __float2bfloat16(v.z - __bfloat162float(h2));
    __nv_bfloat16 l3 = __float2bfloat16(v.w - __bfloat162float(h3));
    ushort4 hv, lv;
    hv.x = __bfloat16_as_ushort(h0); hv.y = __bfloat16_as_ushort(h1);
    hv.z = __bfloat16_as_ushort(h2); hv.w = __bfloat16_as_ushort(h3);
    lv.x = __bfloat16_as_ushort(l0); lv.y = __bfloat16_as_ushort(l1);
    lv.z = __bfloat16_as_ushort(l2); lv.w = __bfloat16_as_ushort(l3);
    ((ushort4*)hi)[i] = hv;
    ((ushort4*)lo)[i] = lv;
}

__global__ void __launch_bounds__(256)
transpose_split_kernel(const float* __restrict__ Wq, const float* __restrict__ Wk,
                       const float* __restrict__ Wv) {
    const float* W = (blockIdx.z == 0) ? Wq : ((blockIdx.z == 1) ? Wk : Wv);
    __nv_bfloat16* hi = (blockIdx.z == 0) ? g_wq_hi : ((blockIdx.z == 1) ? g_wk_hi : g_wv_hi);
    __nv_bfloat16* lo = (blockIdx.z == 0) ? g_wq_lo : ((blockIdx.z == 1) ? g_wk_lo : g_wv_lo);
    __shared__ float t[32][33];
    int tx = threadIdx.x & 31;
    int ty = threadIdx.x >> 5;
    int k0 = blockIdx.y * 32;
    int n0 = blockIdx.x * 32;
#pragma unroll
    for (int i = 0; i < 4; i++)
        t[ty + i * 8][tx] = W[(size_t)(k0 + ty + i * 8) * DD + n0 + tx];
    __syncthreads();
#pragma unroll
    for (int i = 0; i < 4; i++) {
        int n = n0 + ty + i * 8;
        int k = k0 + tx;
        float v = t[tx][ty + i * 8];
        __nv_bfloat16 h = __float2bfloat16(v);
        hi[(size_t)n * DD + k] = h;
        lo[(size_t)n * DD + k] = __float2bfloat16(v - __bfloat162float(h));
    }
}

// ---------------- HMMA split-bf16 GEMM ----------------
#define BK 32
#define ROWB 80
#define MAT_BYTES (128 * ROWB)
#define OFF_AH 0
#define OFF_AL (1 * MAT_BYTES)
#define OFF_BH (2 * MAT_BYTES)
#define OFF_BL (3 * MAT_BYTES)
#define STAGE_BYTES (4 * MAT_BYTES)
#define GSMEM_TOTAL (2 * STAGE_BYTES)

__device__ __forceinline__ void load_stage(uint32_t sb,
                                           const __nv_bfloat16* __restrict__ ahi,
                                           const __nv_bfloat16* __restrict__ alo,
                                           const __nv_bfloat16* __restrict__ bhi,
                                           const __nv_bfloat16* __restrict__ blo,
                                           int m0, int n0, int kt, int tid) {
#pragma unroll
    for (int i = 0; i < 2; i++) {
        int idx = tid + i * 256;
        int r = idx >> 2;
        int c = idx & 3;
        uint32_t so = (uint32_t)(r * ROWB + c * 16);
        size_t goA = (size_t)(m0 + r) * DD + kt + c * 8;
        size_t goB = (size_t)(n0 + r) * DD + kt + c * 8;
        cp16(sb + OFF_AH + so, ahi + goA);
        cp16(sb + OFF_AL + so, alo + goA);
        cp16(sb + OFF_BH + so, bhi + goB);
        cp16(sb + OFF_BL + so, blo + goB);
    }
}

// OUT_MODE 0: fp32 C.  OUT_MODE 1: split hi/lo bf16 (with scale).
template <int OUT_MODE>
__device__ __forceinline__ void gemm_core(const __nv_bfloat16* __restrict__ ahi,
                                          const __nv_bfloat16* __restrict__ alo,
                                          const __nv_bfloat16* __restrict__ bhi,
                                          const __nv_bfloat16* __restrict__ blo,
                                          float* __restrict__ C,
                                          __nv_bfloat16* __restrict__ Chi,
                                          __nv_bfloat16* __restrict__ Clo,
                                          float scale) {
    extern __shared__ char sm[];
    uint32_t sbase = smem_u32(sm);
    const int tid = threadIdx.x;
    const int wid = tid >> 5;
    const int lane = tid & 31;
    const int wm = wid & 3;
    const int wn = wid >> 2;
    const int m0 = blockIdx.y * 128;
    const int n0 = blockIdx.x * 128;

    const int g = lane >> 3;
    const int rr = lane & 7;
    const uint32_t aoff = (uint32_t)((wm * 32 + (g & 1) * 8 + rr) * ROWB + (g >> 1) * 16);
    const uint32_t boff = (uint32_t)((wn * 64 + (g >> 1) * 8 + rr) * ROWB + (g & 1) * 16);

    float acc[2][8][4];
#pragma unroll
    for (int mi = 0; mi < 2; mi++)
#pragma unroll
        for (int ni = 0; ni < 8; ni++)
#pragma unroll
            for (int j = 0; j < 4; j++) acc[mi][ni][j] = 0.0f;

    const int NST = DD / BK;
    load_stage(sbase, ahi, alo, bhi, blo, m0, n0, 0, tid);
    CP_COMMIT();

    for (int s = 0; s < NST; s++) {
        if (s + 1 < NST) {
            load_stage(sbase + ((s + 1) & 1) * STAGE_BYTES,
                       ahi, alo, bhi, blo, m0, n0, (s + 1) * BK, tid);
            CP_COMMIT();
            CP_WAIT(1);
        } else {
            CP_WAIT(0);
        }
        __syncthreads();
        uint32_t sb = sbase + (s & 1) * STAGE_BYTES;

#pragma unroll
        for (int kk = 0; kk < 2; kk++) {
            uint32_t ah[2][4], al[2][4], bh[4][4], bl[4][4];
#pragma unroll
            for (int mi = 0; mi < 2; mi++) {
                uint32_t ao = sb + aoff + (uint32_t)(mi * 16 * ROWB + kk * 32);
                ldm4(ah[mi], ao + OFF_AH);
                ldm4(al[mi], ao + OFF_AL);
            }
#pragma unroll
            for (int np = 0; np < 4; np++) {
                uint32_t bo = sb + boff + (uint32_t)(np * 16 * ROWB + kk * 32);
                ldm4(bh[np], bo + OFF_BH);
                ldm4(bl[np], bo + OFF_BL);
            }
#pragma unroll
            for (int mi = 0; mi < 2; mi++)
#pragma unroll
                for (int ni = 0; ni < 8; ni++) {
                    int np = ni >> 1;
                    int h = (ni & 1) * 2;
                    mma16816(acc[mi][ni], ah[mi], bh[np][h], bh[np][h + 1]);
                    mma16816(acc[mi][ni], ah[mi], bl[np][h], bl[np][h + 1]);
                    mma16816(acc[mi][ni], al[mi], bh[np][h], bh[np][h + 1]);
                }
        }
        __syncthreads();
    }

    const int row_b = m0 + wm * 32 + (lane >> 2);
    const int col_b = n0 + wn * 64 + (lane & 3) * 2;
#pragma unroll
    for (int mi = 0; mi < 2; mi++)
#pragma unroll
        for (int ni = 0; ni < 8; ni++) {
            int row = row_b + mi * 16;
            int col = col_b + ni * 8;
            if (OUT_MODE == 0) {
                *(float2*)&C[(size_t)row * DD + col] =
                    make_float2(acc[mi][ni][0], acc[mi][ni][1]);
                *(float2*)&C[(size_t)(row + 8) * DD + col] =
                    make_float2(acc[mi][ni][2], acc[mi][ni][3]);
            } else {
#pragma unroll
                for (int rh = 0; rh < 2; rh++) {
                    float v0 = acc[mi][ni][rh * 2 + 0] * scale;
                    float v1 = acc[mi][ni][rh * 2 + 1] * scale;
                    float r0, r1;
                    uint32_t hp = pack_bf16_hi(v0, v1, r0, r1);
                    uint32_t lp = pack_bf16(r0, r1);
                    size_t off = (size_t)(row + rh * 8) * DD + col;
                    *(uint32_t*)&Chi[off] = hp;
                    *(uint32_t*)&Clo[off] = lp;
                }
            }
        }
}

__global__ void __launch_bounds__(256)
gemm_qkv_kernel() {
    const __nv_bfloat16* bhi = (blockIdx.z == 0) ? g_wq_hi : ((blockIdx.z == 1) ? g_wk_hi : g_wv_hi);
    const __nv_bfloat16* blo = (blockIdx.z == 0) ? g_wq_lo : ((blockIdx.z == 1) ? g_wk_lo : g_wv_lo);
    __nv_bfloat16* chi = (blockIdx.z == 0) ? g_qhi : ((blockIdx.z == 1) ? g_khi : g_vhi);
    __nv_bfloat16* clo = (blockIdx.z == 0) ? g_qlo : ((blockIdx.z == 1) ? g_klo : g_vlo);
    float scale = (blockIdx.z == 0) ? 0.125f : 1.0f;  // 1/sqrt(HD), exact pow2
    gemm_core<1>(g_xhi, g_xlo, bhi, blo, nullptr, chi, clo, scale);
}

__global__ void __launch_bounds__(256)
gemm_out_kernel(float* __restrict__ out) {
    gemm_core<0>(g_oahi, g_oalo, g_wo_hi, g_wo_lo, out, nullptr, nullptr, 1.0f);
}

// ---------------- HMMA flash attention ----------------
// BM=128 (8 warps x 16 rows), BN=64. 3-pass split-bf16 for QK^T and PV.
#define AROWB 144                    // 128B data + 16B pad (conflict-free ldmatrix)
#define QT (128 * AROWB)             // 18432
#define KVT (64 * AROWB)             // 9216
#define OFF_Q 0
#define OFF_ST (2 * QT)              // 36864
#define STG (4 * KVT)                // 36864
#define ATTN_SMEM (OFF_ST + 2 * STG) // 110592

__device__ __forceinline__ void kv_load(uint32_t stage, size_t gkv, int k0, int tid) {
    const __nv_bfloat16* b0 = g_khi;
    const __nv_bfloat16* b1 = g_klo;
    const __nv_bfloat16* b2 = g_vhi;
    const __nv_bfloat16* b3 = g_vlo;
#pragma unroll
    for (int i = 0; i < 8; i++) {
        int tile = i >> 1;
        int r = (i & 1) * 32 + (tid >> 3);
        int c = tid & 7;
        const __nv_bfloat16* src = (tile == 0) ? b0 : (tile == 1) ? b1 : (tile == 2) ? b2 : b3;
        cp16(stage + (uint32_t)(tile * KVT + r * AROWB + c * 16),
             src + gkv + (size_t)(k0 + r) * DD + c * 8);
    }
}

__global__ void __launch_bounds__(256)
attn_kernel() {
    extern __shared__ char sm[];
    uint32_t sb = smem_u32(sm);
    const int tid = threadIdx.x;
    const int wid = tid >> 5;
    const int lane = tid & 31;
    const int bh = blockIdx.y;
    const int b = bh >> 4;
    const int h = bh & 15;
    const int q0 = blockIdx.x * 128;

    const size_t gq = (size_t)(b * SS + q0) * DD + h * HD;
    const size_t gkv = (size_t)(b * SS) * DD + h * HD;

    // load Q tile (hi/lo)
#pragma unroll
    for (int i = 0; i < 8; i++) {
        int half = i >> 2;
        int r = (i & 3) * 32 + (tid >> 3);
        int c = tid & 7;
        const __nv_bfloat16* src = (half ? g_qlo : g_qhi) + gq + (size_t)r * DD + c * 8;
        cp16(sb + (uint32_t)(OFF_Q + half * QT + r * AROWB + c * 16), src);
    }
    kv_load(sb + OFF_ST, gkv, 0, tid);
    CP_COMMIT();
    CP_WAIT(0);
    __syncthreads();

    // Q A-fragments (held in registers for whole kernel)
    uint32_t qh[4][4], ql[4][4];
    {
        uint32_t qbase = sb + OFF_Q + (uint32_t)((16 * wid + (lane & 15)) * AROWB + (lane >> 4) * 16);
#pragma unroll
        for (int q = 0; q < 4; q++) {
            ldm4(qh[q], qbase + q * 32);
            ldm4(ql[q], qbase + QT + q * 32);
        }
    }

    // per-thread fragment address components
    const uint32_t kfb = (uint32_t)((((lane >> 4) << 3) + (lane & 7)) * AROWB + ((lane >> 3) & 1) * 16);
    const uint32_t vfb = (uint32_t)((lane & 15) * AROWB + (lane >> 4) * 16);

    float o[8][4];
#pragma unroll
    for (int nt = 0; nt < 8; nt++)
#pragma unroll
        for (int j = 0; j < 4; j++) o[nt][j] = 0.0f;
    float m0 = -1e30f, m1 = -1e30f, l0 = 0.0f, l1 = 0.0f;

    const int row0 = q0 + 16 * wid + (lane >> 2);   // this thread's even row
    const int row_min = q0 + 16 * wid;              // warp's first row
    const int qrow_hi = q0 + 16 * wid + 15;         // warp's last row
    const int ntiles = q0 / 64 + 2;

    for (int it = 0; it < ntiles; it++) {
        const int k0 = it * 64;
        if (it + 1 < ntiles) {
            kv_load(sb + OFF_ST + ((it + 1) & 1) * STG, gkv, (it + 1) * 64, tid);
            CP_COMMIT();
            CP_WAIT(1);
        } else {
            CP_WAIT(0);
        }
        __syncthreads();

        if (k0 <= qrow_hi) {  // warp has at least one unmasked row in this tile
            const uint32_t stage = sb + OFF_ST + (it & 1) * STG;

            // ---- S = Q K^T (3-pass) ----
            float s[8][4];
#pragma unroll
            for (int nt = 0; nt < 8; nt++)
#pragma unroll
                for (int j = 0; j < 4; j++) s[nt][j] = 0.0f;

#pragma unroll
            for (int q = 0; q < 4; q++)
#pragma unroll
                for (int p = 0; p < 4; p++) {
                    uint32_t a = kfb + (uint32_t)(p * 16 * AROWB + q * 32);
                    uint32_t kh4[4], kl4[4];
                    ldm4(kh4, stage + 0 * KVT + a);
                    ldm4(kl4, stage + 1 * KVT + a);
                    mma16816(s[2 * p], qh[q], kh4[0], kh4[1]);
                    mma16816(s[2 * p + 1], qh[q], kh4[2], kh4[3]);
                    mma16816(s[2 * p], qh[q], kl4[0], kl4[1]);
                    mma16816(s[2 * p + 1], qh[q], kl4[2], kl4[3]);
                    mma16816(s[2 * p], ql[q], kh4[0], kh4[1]);
                    mma16816(s[2 * p + 1], ql[q], kh4[2], kh4[3]);
                }

            // ---- causal mask (needed whenever tile's max key exceeds warp's first row) ----
            if (k0 + 63 > row_min) {
#pragma unroll
                for (int nt = 0; nt < 8; nt++) {
                    int key = k0 + nt * 8 + (lane & 3) * 2;
#pragma unroll
                    for (int j = 0; j < 4; j++) {
                        int r = row0 + (j >> 1) * 8;
                        if (key + (j & 1) > r) s[nt][j] = -1e30f;
                    }
                }
            }

            // ---- online softmax (register-resident, quad shuffles) ----
            float mt0 = -1e30f, mt1 = -1e30f;
#pragma unroll
            for (int nt = 0; nt < 8; nt++) {
                mt0 = fmaxf(mt0, fmaxf(s[nt][0], s[nt][1]));
                mt1 = fmaxf(mt1, fmaxf(s[nt][2], s[nt][3]));
            }
            mt0 = fmaxf(mt0, __shfl_xor_sync(0xffffffffu, mt0, 1));
            mt0 = fmaxf(mt0, __shfl_xor_sync(0xffffffffu, mt0, 2));
            mt1 = fmaxf(mt1, __shfl_xor_sync(0xffffffffu, mt1, 1));
            mt1 = fmaxf(mt1, __shfl_xor_sync(0xffffffffu, mt1, 2));

            float mn0 = fmaxf(m0, mt0);
            float mn1 = fmaxf(m1, mt1);
            float al0 = __expf(m0 - mn0);
            float al1 = __expf(m1 - mn1);
            m0 = mn0; m1 = mn1;

            float ls0 = 0.0f, ls1 = 0.0f;
#pragma unroll
            for (int nt = 0; nt < 8; nt++) {
                s[nt][0] = __expf(s[nt][0] - mn0);
                s[nt][1] = __expf(s[nt][1] - mn0);
                s[nt][2] = __expf(s[nt][2] - mn1);
                s[nt][3] = __expf(s[nt][3] - mn1);
                ls0 += s[nt][0] + s[nt][1];
                ls1 += s[nt][2] + s[nt][3];
            }
            l0 = l0 * al0 + ls0;
            l1 = l1 * al1 + ls1;
#pragma unroll
            for (int nt = 0; nt < 8; nt++) {
                o[nt][0] *= al0; o[nt][1] *= al0;
                o[nt][2] *= al1; o[nt][3] *= al1;
            }

            // ---- PV (3-pass), P repacked in registers ----
#pragma unroll
            for (int kk = 0; kk < 4; kk++) {
                uint32_t pah[4], pal[4];
                float r0, r1;
                pah[0] = pack_bf16_hi(s[2 * kk][0], s[2 * kk][1], r0, r1);
                pal[0] = pack_bf16(r0, r1);
                pah[1] = pack_bf16_hi(s[2 * kk][2], s[2 * kk][3], r0, r1);
                pal[1] = pack_bf16(r0, r1);
                pah[2] = pack_bf16_hi(s[2 * kk + 1][0], s[2 * kk + 1][1], r0, r1);
                pal[2] = pack_bf16(r0, r1);
                pah[3] = pack_bf16_hi(s[2 * kk + 1][2], s[2 * kk + 1][3], r0, r1);
                pal[3] = pack_bf16(r0, r1);
#pragma unroll
                for (int u = 0; u < 4; u++) {
                    uint32_t a = vfb + (uint32_t)(kk * 16 * AROWB + u * 32);
                    uint32_t vh4[4], vl4[4];
                    ldm4t(vh4, stage + 2 * KVT + a);
                    ldm4t(vl4, stage + 3 * KVT + a);
                    mma16816(o[2 * u], pah, vh4[0], vh4[1]);
                    mma16816(o[2 * u + 1], pah, vh4[2], vh4[3]);
                    mma16816(o[2 * u], pah, vl4[0], vl4[1]);
                    mma16816(o[2 * u + 1], pah, vl4[2], vl4[3]);
                    mma16816(o[2 * u], pal, vh4[0], vh4[1]);
                    mma16816(o[2 * u + 1], pal, vh4[2], vh4[3]);
                }
            }
        }
        __syncthreads();
    }

    // ---- finalize: 1/l, split to bf16 hi/lo, store ----
    l0 += __shfl_xor_sync(0xffffffffu, l0, 1);
    l0 += __shfl_xor_sync(0xffffffffu, l0, 2);
    l1 += __shfl_xor_sync(0xffffffffu, l1, 1);
    l1 += __shfl_xor_sync(0xffffffffu, l1, 2);
    float inv0 = 1.0f / l0;
    float inv1 = 1.0f / l1;

    const int grow0 = b * SS + q0 + 16 * wid + (lane >> 2);
    const int gcol = h * HD + (lane & 3) * 2;
#pragma unroll
    for (int nt = 0; nt < 8; nt++) {
#pragma unroll
        for (int rh = 0; rh < 2; rh++) {
            float inv = rh ? inv1 : inv0;
            float v0 = o[nt][rh * 2 + 0] * inv;
            float v1 = o[nt][rh * 2 + 1] * inv;
            float r0, r1;
            uint32_t hp = pack_bf16_hi(v0, v1, r0, r1);
            uint32_t lp = pack_bf16(r0, r1);
            size_t off = (size_t)(grow0 + rh * 8) * DD + gcol + nt * 8;
            *(uint32_t*)&g_oahi[off] = hp;
            *(uint32_t*)&g_oalo[off] = lp;
        }
    }
}

// ---------------- launch ----------------
extern "C" void kernel_launch(void* const* d_in, const int* in_sizes, int n_in,
                              void* d_out, int out_size) {
    const float* x  = (const float*)d_in[0];
    const float* Wq = (const float*)d_in[1];
    const float* Wk = (const float*)d_in[2];
    const float* Wv = (const float*)d_in[3];
    const float* Wo = (const float*)d_in[4];
    float* out = (float*)d_out;

    cudaFuncSetAttribute(attn_kernel,
                         cudaFuncAttributeMaxDynamicSharedMemorySize, ATTN_SMEM);
    cudaFuncSetAttribute(gemm_qkv_kernel,
                         cudaFuncAttributeMaxDynamicSharedMemorySize, GSMEM_TOTAL);
    cudaFuncSetAttribute(gemm_out_kernel,
                         cudaFuncAttributeMaxDynamicSharedMemorySize, GSMEM_TOTAL);

    __nv_bfloat16 *p_xhi, *p_xlo, *p_wohi, *p_wolo;
    cudaGetSymbolAddress((void**)&p_xhi, g_xhi);
    cudaGetSymbolAddress((void**)&p_xlo, g_xlo);
    cudaGetSymbolAddress((void**)&p_wohi, g_wo_hi);
    cudaGetSymbolAddress((void**)&p_wolo, g_wo_lo);

    split_kernel<<<(MM * DD / 4 + 255) / 256, 256>>>(x, p_xhi, p_xlo, MM * DD / 4);
    split_kernel<<<(DD * DD / 4 + 255) / 256, 256>>>(Wo, p_wohi, p_wolo, DD * DD / 4);
    transpose_split_kernel<<<dim3(32, 32, 3), 256>>>(Wq, Wk, Wv);

    dim3 gq(DD / 128, MM / 128, 3);       // (8, 64, 3)
    gemm_qkv_kernel<<<gq, 256, GSMEM_TOTAL>>>();

    dim3 ga(SS / 128, BB * HH);           // (16, 64)
    attn_kernel<<<ga, 256, ATTN_SMEM>>>();

    dim3 go(DD / 128, MM / 128, 1);       // (8, 64)
    gemm_out_kernel<<<go, 256, GSMEM_TOTAL>>>(out);
}

// round 8
// speedup vs baseline: 2.8139x; 1.1518x over previous
#include <cuda_runtime.h>
#include <cuda_bf16.h>
#include <cstdint>

// Problem constants
#define BB 4
#define SS 2048
#define DD 1024
#define HH 16
#define HD 64
#define MM (BB * SS)   // 8192 rows

typedef unsigned long long u64;

// ---------------- scratch (device globals; allocation-free rule) ----------------
__device__ __nv_bfloat16 g_qhi[MM * DD];
__device__ __nv_bfloat16 g_qlo[MM * DD];
__device__ __nv_bfloat16 g_khi[MM * DD];
__device__ __nv_bfloat16 g_klo[MM * DD];
__device__ __nv_bfloat16 g_vhi[MM * DD];
__device__ __nv_bfloat16 g_vlo[MM * DD];

__device__ __nv_bfloat16 g_xhi[MM * DD];
__device__ __nv_bfloat16 g_xlo[MM * DD];
__device__ __nv_bfloat16 g_oahi[MM * DD];
__device__ __nv_bfloat16 g_oalo[MM * DD];

__device__ __nv_bfloat16 g_wq_hi[DD * DD];
__device__ __nv_bfloat16 g_wq_lo[DD * DD];
__device__ __nv_bfloat16 g_wk_hi[DD * DD];
__device__ __nv_bfloat16 g_wk_lo[DD * DD];
__device__ __nv_bfloat16 g_wv_hi[DD * DD];
__device__ __nv_bfloat16 g_wv_lo[DD * DD];
__device__ __nv_bfloat16 g_wo_hi[DD * DD];
__device__ __nv_bfloat16 g_wo_lo[DD * DD];

// ---------------- PTX helpers ----------------
__device__ __forceinline__ uint32_t smem_u32(const void* p) {
    uint32_t a;
    asm("{ .reg .u64 t; cvta.to.shared.u64 t, %1; cvt.u32.u64 %0, t; }" : "=r"(a) : "l"(p));
    return a;
}
__device__ __forceinline__ void cp16(uint32_t dst, const void* src) {
    asm volatile("cp.async.cg.shared.global [%0], [%1], 16;" :: "r"(dst), "l"(src) : "memory");
}
#define CP_COMMIT() asm volatile("cp.async.commit_group;" ::: "memory")
#define CP_WAIT(n) asm volatile("cp.async.wait_group %0;" :: "n"(n) : "memory")

__device__ __forceinline__ void ldm4(uint32_t* d, uint32_t addr) {
    asm volatile("ldmatrix.sync.aligned.m8n8.x4.shared.b16 {%0,%1,%2,%3}, [%4];"
                 : "=r"(d[0]), "=r"(d[1]), "=r"(d[2]), "=r"(d[3]) : "r"(addr));
}
__device__ __forceinline__ void ldm4t(uint32_t* d, uint32_t addr) {
    asm volatile("ldmatrix.sync.aligned.m8n8.x4.trans.shared.b16 {%0,%1,%2,%3}, [%4];"
                 : "=r"(d[0]), "=r"(d[1]), "=r"(d[2]), "=r"(d[3]) : "r"(addr));
}
__device__ __forceinline__ void mma16816(float* c, const uint32_t* a, uint32_t b0, uint32_t b1) {
    asm volatile(
        "mma.sync.aligned.m16n8k16.row.col.f32.bf16.bf16.f32 "
        "{%0,%1,%2,%3}, {%4,%5,%6,%7}, {%8,%9}, {%0,%1,%2,%3};"
        : "+f"(c[0]), "+f"(c[1]), "+f"(c[2]), "+f"(c[3])
        : "r"(a[0]), "r"(a[1]), "r"(a[2]), "r"(a[3]), "r"(b0), "r"(b1));
}
__device__ __forceinline__ uint32_t pack_bf16_hi(float x, float y, float& rx, float& ry) {
    __nv_bfloat162 h = __float22bfloat162_rn(make_float2(x, y));
    float2 f = __bfloat1622float2(h);
    rx = x - f.x;
    ry = y - f.y;
    return *(uint32_t*)&h;
}
__device__ __forceinline__ uint32_t pack_bf16(float x, float y) {
    __nv_bfloat162 h = __float22bfloat162_rn(make_float2(x, y));
    return *(uint32_t*)&h;
}

// ---------------- split / transpose prep kernels ----------------
__global__ void __launch_bounds__(256)
split_kernel(const float* __restrict__ src, __nv_bfloat16* __restrict__ hi,
             __nv_bfloat16* __restrict__ lo, int n4) {
    int i = blockIdx.x * 256 + threadIdx.x;
    if (i >= n4) return;
    float4 v = ((const float4*)src)[i];
    __nv_bfloat16 h0 = __float2bfloat16(v.x);
    __nv_bfloat16 h1 = __float2bfloat16(v.y);
    __nv_bfloat16 h2 = __float2bfloat16(v.z);
    __nv_bfloat16 h3 = __float2bfloat16(v.w);
    __nv_bfloat16 l0 = __float2bfloat16(v.x - __bfloat162float(h0));
    __nv_bfloat16 l1 = __float2bfloat16(v.y - __bfloat162float(h1));
    __nv_bfloat16 l2 = __float2bfloat16(v.z - __bfloat162float(h2));
    __nv_bfloat16 l3 = __float2bfloat16(v.w - __bfloat162float(h3));
    ushort4 hv, lv;
    hv.x = __bfloat16_as_ushort(h0); hv.y = __bfloat16_as_ushort(h1);
    hv.z = __bfloat16_as_ushort(h2); hv.w = __bfloat16_as_ushort(h3);
    lv.x = __bfloat16_as_ushort(l0); lv.y = __bfloat16_as_ushort(l1);
    lv.z = __bfloat16_as_ushort(l2); lv.w = __bfloat16_as_ushort(l3);
    ((ushort4*)hi)[i] = hv;
    ((ushort4*)lo)[i] = lv;
}

__global__ void __launch_bounds__(256)
transpose_split_kernel(const float* __restrict__ Wq, const float* __restrict__ Wk,
                       const float* __restrict__ Wv) {
    const float* W = (blockIdx.z == 0) ? Wq : ((blockIdx.z == 1) ? Wk : Wv);
    __nv_bfloat16* hi = (blockIdx.z == 0) ? g_wq_hi : ((blockIdx.z == 1) ? g_wk_hi : g_wv_hi);
    __nv_bfloat16* lo = (blockIdx.z == 0) ? g_wq_lo : ((blockIdx.z == 1) ? g_wk_lo : g_wv_lo);
    __shared__ float t[32][33];
    int tx = threadIdx.x & 31;
    int ty = threadIdx.x >> 5;
    int k0 = blockIdx.y * 32;
    int n0 = blockIdx.x * 32;
#pragma unroll
    for (int i = 0; i < 4; i++)
        t[ty + i * 8][tx] = W[(size_t)(k0 + ty + i * 8) * DD + n0 + tx];
    __syncthreads();
#pragma unroll
    for (int i = 0; i < 4; i++) {
        int n = n0 + ty + i * 8;
        int k = k0 + tx;
        float v = t[tx][ty + i * 8];
        __nv_bfloat16 h = __float2bfloat16(v);
        hi[(size_t)n * DD + k] = h;
        lo[(size_t)n * DD + k] = __float2bfloat16(v - __bfloat162float(h));
    }
}

// ---------------- HMMA split-bf16 GEMM (swizzled, 3-stage) ----------------
// Tile 128x128, BK=32. SMEM: 64B rows, XOR swizzle (chunk' = c ^ ((r>>1)&3)).
#define BK 32
#define MAT 8192                    // 128 rows x 64B
#define OFF_AH 0
#define OFF_AL (1 * MAT)
#define OFF_BH (2 * MAT)
#define OFF_BL (3 * MAT)
#define STAGE_BYTES (4 * MAT)       // 32768
#define GSMEM_TOTAL (3 * STAGE_BYTES)  // 98304

__device__ __forceinline__ void load_stage(uint32_t sb,
                                           const __nv_bfloat16* __restrict__ ahi,
                                           const __nv_bfloat16* __restrict__ alo,
                                           const __nv_bfloat16* __restrict__ bhi,
                                           const __nv_bfloat16* __restrict__ blo,
                                           int m0, int n0, int kt, int tid) {
#pragma unroll
    for (int i = 0; i < 2; i++) {
        int idx = tid + i * 256;          // 0..511
        int r = idx >> 2;                 // 0..127
        int c = idx & 3;
        uint32_t so = (uint32_t)(r * 64 + ((c ^ ((r >> 1) & 3)) << 4));
        size_t goA = (size_t)(m0 + r) * DD + kt + c * 8;
        size_t goB = (size_t)(n0 + r) * DD + kt + c * 8;
        cp16(sb + OFF_AH + so, ahi + goA);
        cp16(sb + OFF_AL + so, alo + goA);
        cp16(sb + OFF_BH + so, bhi + goB);
        cp16(sb + OFF_BL + so, blo + goB);
    }
}

template <int OUT_MODE>
__device__ __forceinline__ void gemm_core(const __nv_bfloat16* __restrict__ ahi,
                                          const __nv_bfloat16* __restrict__ alo,
                                          const __nv_bfloat16* __restrict__ bhi,
                                          const __nv_bfloat16* __restrict__ blo,
                                          float* __restrict__ C,
                                          __nv_bfloat16* __restrict__ Chi,
                                          __nv_bfloat16* __restrict__ Clo,
                                          float scale) {
    extern __shared__ char sm[];
    uint32_t sbase = smem_u32(sm);
    const int tid = threadIdx.x;
    const int wid = tid >> 5;
    const int lane = tid & 31;
    const int wm = wid & 3;
    const int wn = wid >> 2;
    const int m0 = blockIdx.y * 128;
    const int n0 = blockIdx.x * 128;

    const int g = lane >> 3;
    const int rr = lane & 7;
    const int rA = wm * 32 + (g & 1) * 8 + rr;
    const uint32_t aBase = (uint32_t)(rA * 64);
    const uint32_t aSw = (uint32_t)((((g >> 1) ^ ((rA >> 1) & 3)) << 4));
    const int rB = wn * 64 + (g >> 1) * 8 + rr;
    const uint32_t bBase = (uint32_t)(rB * 64);
    const uint32_t bSw = (uint32_t)((((g & 1) ^ ((rB >> 1) & 3)) << 4));

    float acc[2][8][4];
#pragma unroll
    for (int mi = 0; mi < 2; mi++)
#pragma unroll
        for (int ni = 0; ni < 8; ni++)
#pragma unroll
            for (int j = 0; j < 4; j++) acc[mi][ni][j] = 0.0f;

    const int NST = DD / BK;   // 32
    load_stage(sbase + 0 * STAGE_BYTES, ahi, alo, bhi, blo, m0, n0, 0, tid);
    CP_COMMIT();
    load_stage(sbase + 1 * STAGE_BYTES, ahi, alo, bhi, blo, m0, n0, BK, tid);
    CP_COMMIT();

    int sidx = 0;
    for (int s = 0; s < NST; s++) {
        if (s < NST - 1) { CP_WAIT(1); } else { CP_WAIT(0); }
        __syncthreads();
        if (s + 2 < NST) {
            int nb = sidx + 2; if (nb >= 3) nb -= 3;
            load_stage(sbase + nb * STAGE_BYTES, ahi, alo, bhi, blo, m0, n0, (s + 2) * BK, tid);
            CP_COMMIT();
        }
        uint32_t sb = sbase + sidx * STAGE_BYTES;

#pragma unroll
        for (int kk = 0; kk < 2; kk++) {
            uint32_t ah[2][4], al[2][4], bh[4][4], bl[4][4];
            const uint32_t asw = kk ? (aSw ^ 32u) : aSw;
            const uint32_t bsw = kk ? (bSw ^ 32u) : bSw;
#pragma unroll
            for (int mi = 0; mi < 2; mi++) {
                uint32_t ao = sb + aBase + (uint32_t)(mi * 1024) + asw;
                ldm4(ah[mi], ao + OFF_AH);
                ldm4(al[mi], ao + OFF_AL);
            }
#pragma unroll
            for (int np = 0; np < 4; np++) {
                uint32_t bo = sb + bBase + (uint32_t)(np * 1024) + bsw;
                ldm4(bh[np], bo + OFF_BH);
                ldm4(bl[np], bo + OFF_BL);
            }
            // pass-major ordering: dep distance 16
#pragma unroll
            for (int mi = 0; mi < 2; mi++)
#pragma unroll
                for (int ni = 0; ni < 8; ni++)
                    mma16816(acc[mi][ni], ah[mi], bh[ni >> 1][(ni & 1) * 2], bh[ni >> 1][(ni & 1) * 2 + 1]);
#pragma unroll
            for (int mi = 0; mi < 2; mi++)
#pragma unroll
                for (int ni = 0; ni < 8; ni++)
                    mma16816(acc[mi][ni], ah[mi], bl[ni >> 1][(ni & 1) * 2], bl[ni >> 1][(ni & 1) * 2 + 1]);
#pragma unroll
            for (int mi = 0; mi < 2; mi++)
#pragma unroll
                for (int ni = 0; ni < 8; ni++)
                    mma16816(acc[mi][ni], al[mi], bh[ni >> 1][(ni & 1) * 2], bh[ni >> 1][(ni & 1) * 2 + 1]);
        }
        sidx++; if (sidx == 3) sidx = 0;
    }

    const int row_b = m0 + wm * 32 + (lane >> 2);
    const int col_b = n0 + wn * 64 + (lane & 3) * 2;
#pragma unroll
    for (int mi = 0; mi < 2; mi++)
#pragma unroll
        for (int ni = 0; ni < 8; ni++) {
            int row = row_b + mi * 16;
            int col = col_b + ni * 8;
            if (OUT_MODE == 0) {
                *(float2*)&C[(size_t)row * DD + col] =
                    make_float2(acc[mi][ni][0], acc[mi][ni][1]);
                *(float2*)&C[(size_t)(row + 8) * DD + col] =
                    make_float2(acc[mi][ni][2], acc[mi][ni][3]);
            } else {
#pragma unroll
                for (int rh = 0; rh < 2; rh++) {
                    float v0 = acc[mi][ni][rh * 2 + 0] * scale;
                    float v1 = acc[mi][ni][rh * 2 + 1] * scale;
                    float r0, r1;
                    uint32_t hp = pack_bf16_hi(v0, v1, r0, r1);
                    uint32_t lp = pack_bf16(r0, r1);
                    size_t off = (size_t)(row + rh * 8) * DD + col;
                    *(uint32_t*)&Chi[off] = hp;
                    *(uint32_t*)&Clo[off] = lp;
                }
            }
        }
}

__global__ void __launch_bounds__(256, 2)
gemm_qkv_kernel() {
    const __nv_bfloat16* bhi = (blockIdx.z == 0) ? g_wq_hi : ((blockIdx.z == 1) ? g_wk_hi : g_wv_hi);
    const __nv_bfloat16* blo = (blockIdx.z == 0) ? g_wq_lo : ((blockIdx.z == 1) ? g_wk_lo : g_wv_lo);
    __nv_bfloat16* chi = (blockIdx.z == 0) ? g_qhi : ((blockIdx.z == 1) ? g_khi : g_vhi);
    __nv_bfloat16* clo = (blockIdx.z == 0) ? g_qlo : ((blockIdx.z == 1) ? g_klo : g_vlo);
    float scale = (blockIdx.z == 0) ? 0.125f : 1.0f;
    gemm_core<1>(g_xhi, g_xlo, bhi, blo, nullptr, chi, clo, scale);
}

__global__ void __launch_bounds__(256, 2)
gemm_out_kernel(float* __restrict__ out) {
    gemm_core<0>(g_oahi, g_oalo, g_wo_hi, g_wo_lo, out, nullptr, nullptr, 1.0f);
}

// ---------------- HMMA flash attention (swizzled, 2 CTA/SM) ----------------
// BM=128 (8 warps x 16 rows), BN=64. 128B rows, SW128 swizzle (c' = c ^ (r&7)).
#define QT 16384                     // 128 x 128B
#define KVT 8192                     // 64 x 128B
#define OFF_Q 0
#define OFF_ST (2 * QT)              // 32768
#define STG (4 * KVT)                // 32768
#define ATTN_SMEM (OFF_ST + 2 * STG) // 98304

__device__ __forceinline__ void kv_load(uint32_t stage, size_t gkv, int k0, int tid) {
#pragma unroll
    for (int i = 0; i < 8; i++) {
        int tile = i >> 1;
        int r = (i & 1) * 32 + (tid >> 3);
        int c = tid & 7;
        const __nv_bfloat16* src = (tile == 0) ? g_khi : (tile == 1) ? g_klo
                                 : (tile == 2) ? g_vhi : g_vlo;
        cp16(stage + (uint32_t)(tile * KVT + r * 128 + ((c ^ (r & 7)) << 4)),
             src + gkv + (size_t)(k0 + r) * DD + c * 8);
    }
}

__global__ void __launch_bounds__(256, 2)
attn_kernel() {
    extern __shared__ char sm[];
    uint32_t sb = smem_u32(sm);
    const int tid = threadIdx.x;
    const int wid = tid >> 5;
    const int lane = tid & 31;
    const int bh = blockIdx.y;
    const int b = bh >> 4;
    const int h = bh & 15;
    const int q0 = blockIdx.x * 128;

    const size_t gq = (size_t)(b * SS + q0) * DD + h * HD;
    const size_t gkv = (size_t)(b * SS) * DD + h * HD;

    // load Q tile (hi/lo), swizzled
#pragma unroll
    for (int i = 0; i < 8; i++) {
        int half = i >> 2;
        int r = (i & 3) * 32 + (tid >> 3);
        int c = tid & 7;
        const __nv_bfloat16* src = (half ? g_qlo : g_qhi) + gq + (size_t)r * DD + c * 8;
        cp16(sb + (uint32_t)(OFF_Q + half * QT + r * 128 + ((c ^ (r & 7)) << 4)), src);
    }
    kv_load(sb + OFF_ST, gkv, 0, tid);
    CP_COMMIT();
    CP_WAIT(0);
    __syncthreads();

    // Q A-fragments
    uint32_t qh[4][4], ql[4][4];
    {
        const int rQ = 16 * wid + (lane & 15);
        const int tQ = lane >> 4;
        const uint32_t qrow = sb + OFF_Q + (uint32_t)(rQ * 128);
        const int sQ = rQ & 7;
#pragma unroll
        for (int q = 0; q < 4; q++) {
            uint32_t cofs = (uint32_t)(((tQ + 2 * q) ^ sQ) << 4);
            ldm4(qh[q], qrow + cofs);
            ldm4(ql[q], qrow + QT + cofs);
        }
    }

    // K-frag components
    const int rK = ((lane >> 4) << 3) + (lane & 7);
    const int tK = (lane >> 3) & 1;
    const int sK = rK & 7;
    const uint32_t kBase = (uint32_t)(rK * 128);
    // V-frag components
    const int rV = lane & 15;
    const int tV = lane >> 4;
    const int sV = rV & 7;
    const uint32_t vBase = (uint32_t)(rV * 128);

    float o[8][4];
#pragma unroll
    for (int nt = 0; nt < 8; nt++)
#pragma unroll
        for (int j = 0; j < 4; j++) o[nt][j] = 0.0f;
    float m0 = -1e30f, m1 = -1e30f, l0 = 0.0f, l1 = 0.0f;

    const int row0 = q0 + 16 * wid + (lane >> 2);
    const int row_min = q0 + 16 * wid;
    const int qrow_hi = q0 + 16 * wid + 15;
    const int ntiles = q0 / 64 + 2;

    for (int it = 0; it < ntiles; it++) {
        const int k0 = it * 64;
        if (it + 1 < ntiles) {
            kv_load(sb + OFF_ST + ((it + 1) & 1) * STG, gkv, (it + 1) * 64, tid);
            CP_COMMIT();
            CP_WAIT(1);
        } else {
            CP_WAIT(0);
        }
        __syncthreads();

        if (k0 <= qrow_hi) {
            const uint32_t stage = sb + OFF_ST + (it & 1) * STG;

            // ---- S = Q K^T, 3-pass, pair-blocked pass-major ----
            float s[8][4];
#pragma unroll
            for (int nt = 0; nt < 8; nt++)
#pragma unroll
                for (int j = 0; j < 4; j++) s[nt][j] = 0.0f;

#pragma unroll
            for (int q = 0; q < 4; q++) {
                const uint32_t kc = (uint32_t)((((2 * q) + tK) ^ sK) << 4);
#pragma unroll
                for (int pp = 0; pp < 2; pp++) {
                    uint32_t kh4[2][4], kl4[2][4];
#pragma unroll
                    for (int p2 = 0; p2 < 2; p2++) {
                        int p = pp * 2 + p2;
                        uint32_t a = stage + kBase + (uint32_t)(p * 2048) + kc;
                        ldm4(kh4[p2], a);
                        ldm4(kl4[p2], a + KVT);
                    }
#pragma unroll
                    for (int p2 = 0; p2 < 2; p2++) {
                        int p = pp * 2 + p2;
                        mma16816(s[2 * p], qh[q], kh4[p2][0], kh4[p2][1]);
                        mma16816(s[2 * p + 1], qh[q], kh4[p2][2], kh4[p2][3]);
                    }
#pragma unroll
                    for (int p2 = 0; p2 < 2; p2++) {
                        int p = pp * 2 + p2;
                        mma16816(s[2 * p], qh[q], kl4[p2][0], kl4[p2][1]);
                        mma16816(s[2 * p + 1], qh[q], kl4[p2][2], kl4[p2][3]);
                    }
#pragma unroll
                    for (int p2 = 0; p2 < 2; p2++) {
                        int p = pp * 2 + p2;
                        mma16816(s[2 * p], ql[q], kh4[p2][0], kh4[p2][1]);
                        mma16816(s[2 * p + 1], ql[q], kh4[p2][2], kh4[p2][3]);
                    }
                }
            }

            // ---- causal mask ----
            if (k0 + 63 > row_min) {
#pragma unroll
                for (int nt = 0; nt < 8; nt++) {
                    int key = k0 + nt * 8 + (lane & 3) * 2;
#pragma unroll
                    for (int j = 0; j < 4; j++) {
                        int r = row0 + (j >> 1) * 8;
                        if (key + (j & 1) > r) s[nt][j] = -1e30f;
                    }
                }
            }

            // ---- online softmax ----
            float mt0 = -1e30f, mt1 = -1e30f;
#pragma unroll
            for (int nt = 0; nt < 8; nt++) {
                mt0 = fmaxf(mt0, fmaxf(s[nt][0], s[nt][1]));
                mt1 = fmaxf(mt1, fmaxf(s[nt][2], s[nt][3]));
            }
            mt0 = fmaxf(mt0, __shfl_xor_sync(0xffffffffu, mt0, 1));
            mt0 = fmaxf(mt0, __shfl_xor_sync(0xffffffffu, mt0, 2));
            mt1 = fmaxf(mt1, __shfl_xor_sync(0xffffffffu, mt1, 1));
            mt1 = fmaxf(mt1, __shfl_xor_sync(0xffffffffu, mt1, 2));

            float mn0 = fmaxf(m0, mt0);
            float mn1 = fmaxf(m1, mt1);
            float al0 = __expf(m0 - mn0);
            float al1 = __expf(m1 - mn1);
            m0 = mn0; m1 = mn1;

            float ls0 = 0.0f, ls1 = 0.0f;
#pragma unroll
            for (int nt = 0; nt < 8; nt++) {
                s[nt][0] = __expf(s[nt][0] - mn0);
                s[nt][1] = __expf(s[nt][1] - mn0);
                s[nt][2] = __expf(s[nt][2] - mn1);
                s[nt][3] = __expf(s[nt][3] - mn1);
                ls0 += s[nt][0] + s[nt][1];
                ls1 += s[nt][2] + s[nt][3];
            }
            l0 = l0 * al0 + ls0;
            l1 = l1 * al1 + ls1;
#pragma unroll
            for (int nt = 0; nt < 8; nt++) {
                o[nt][0] *= al0; o[nt][1] *= al0;
                o[nt][2] *= al1; o[nt][3] *= al1;
            }

            // ---- PV, 3-pass, pair-blocked pass-major ----
#pragma unroll
            for (int kk = 0; kk < 4; kk++) {
                uint32_t pah[4], pal[4];
                float r0, r1;
                pah[0] = pack_bf16_hi(s[2 * kk][0], s[2 * kk][1], r0, r1);
                pal[0] = pack_bf16(r0, r1);
                pah[1] = pack_bf16_hi(s[2 * kk][2], s[2 * kk][3], r0, r1);
                pal[1] = pack_bf16(r0, r1);
                pah[2] = pack_bf16_hi(s[2 * kk + 1][0], s[2 * kk + 1][1], r0, r1);
                pal[2] = pack_bf16(r0, r1);
                pah[3] = pack_bf16_hi(s[2 * kk + 1][2], s[2 * kk + 1][3], r0, r1);
                pal[3] = pack_bf16(r0, r1);
                const uint32_t vrow = stage + 2 * KVT + vBase + (uint32_t)(kk * 2048);
#pragma unroll
                for (int uu = 0; uu < 2; uu++) {
                    uint32_t vh4[2][4], vl4[2][4];
#pragma unroll
                    for (int u2 = 0; u2 < 2; u2++) {
                        int u = uu * 2 + u2;
                        uint32_t a = vrow + (uint32_t)((((2 * u) + tV) ^ sV) << 4);
                        ldm4t(vh4[u2], a);
                        ldm4t(vl4[u2], a + KVT);
                    }
#pragma unroll
                    for (int u2 = 0; u2 < 2; u2++) {
                        int u = uu * 2 + u2;
                        mma16816(o[2 * u], pah, vh4[u2][0], vh4[u2][1]);
                        mma16816(o[2 * u + 1], pah, vh4[u2][2], vh4[u2][3]);
                    }
#pragma unroll
                    for (int u2 = 0; u2 < 2; u2++) {
                        int u = uu * 2 + u2;
                        mma16816(o[2 * u], pah, vl4[u2][0], vl4[u2][1]);
                        mma16816(o[2 * u + 1], pah, vl4[u2][2], vl4[u2][3]);
                    }
#pragma unroll
                    for (int u2 = 0; u2 < 2; u2++) {
                        int u = uu * 2 + u2;
                        mma16816(o[2 * u], pal, vh4[u2][0], vh4[u2][1]);
                        mma16816(o[2 * u + 1], pal, vh4[u2][2], vh4[u2][3]);
                    }
                }
            }
        }
        __syncthreads();
    }

    // ---- finalize ----
    l0 += __shfl_xor_sync(0xffffffffu, l0, 1);
    l0 += __shfl_xor_sync(0xffffffffu, l0, 2);
    l1 += __shfl_xor_sync(0xffffffffu, l1, 1);
    l1 += __shfl_xor_sync(0xffffffffu, l1, 2);
    float inv0 = 1.0f / l0;
    float inv1 = 1.0f / l1;

    const int grow0 = b * SS + q0 + 16 * wid + (lane >> 2);
    const int gcol = h * HD + (lane & 3) * 2;
#pragma unroll
    for (int nt = 0; nt < 8; nt++) {
#pragma unroll
        for (int rh = 0; rh < 2; rh++) {
            float inv = rh ? inv1 : inv0;
            float v0 = o[nt][rh * 2 + 0] * inv;
            float v1 = o[nt][rh * 2 + 1] * inv;
            float r0, r1;
            uint32_t hp = pack_bf16_hi(v0, v1, r0, r1);
            uint32_t lp = pack_bf16(r0, r1);
            size_t off = (size_t)(grow0 + rh * 8) * DD + gcol + nt * 8;
            *(uint32_t*)&g_oahi[off] = hp;
            *(uint32_t*)&g_oalo[off] = lp;
        }
    }
}

// ---------------- launch ----------------
extern "C" void kernel_launch(void* const* d_in, const int* in_sizes, int n_in,
                              void* d_out, int out_size) {
    const float* x  = (const float*)d_in[0];
    const float* Wq = (const float*)d_in[1];
    const float* Wk = (const float*)d_in[2];
    const float* Wv = (const float*)d_in[3];
    const float* Wo = (const float*)d_in[4];
    float* out = (float*)d_out;

    cudaFuncSetAttribute(attn_kernel,
                         cudaFuncAttributeMaxDynamicSharedMemorySize, ATTN_SMEM);
    cudaFuncSetAttribute(gemm_qkv_kernel,
                         cudaFuncAttributeMaxDynamicSharedMemorySize, GSMEM_TOTAL);
    cudaFuncSetAttribute(gemm_out_kernel,
                         cudaFuncAttributeMaxDynamicSharedMemorySize, GSMEM_TOTAL);

    __nv_bfloat16 *p_xhi, *p_xlo, *p_wohi, *p_wolo;
    cudaGetSymbolAddress((void**)&p_xhi, g_xhi);
    cudaGetSymbolAddress((void**)&p_xlo, g_xlo);
    cudaGetSymbolAddress((void**)&p_wohi, g_wo_hi);
    cudaGetSymbolAddress((void**)&p_wolo, g_wo_lo);

    split_kernel<<<(MM * DD / 4 + 255) / 256, 256>>>(x, p_xhi, p_xlo, MM * DD / 4);
    split_kernel<<<(DD * DD / 4 + 255) / 256, 256>>>(Wo, p_wohi, p_wolo, DD * DD / 4);
    transpose_split_kernel<<<dim3(32, 32, 3), 256>>>(Wq, Wk, Wv);

    dim3 gq(DD / 128, MM / 128, 3);       // (8, 64, 3)
    gemm_qkv_kernel<<<gq, 256, GSMEM_TOTAL>>>();

    dim3 ga(SS / 128, BB * HH);           // (16, 64)
    attn_kernel<<<ga, 256, ATTN_SMEM>>>();

    dim3 go(DD / 128, MM / 128, 1);       // (8, 64)
    gemm_out_kernel<<<go, 256, GSMEM_TOTAL>>>(out);
}

// round 9
// speedup vs baseline: 2.9142x; 1.0356x over previous
#include <cuda_runtime.h>
#include <cuda_bf16.h>
#include <cstdint>

// Problem constants
#define BB 4
#define SS 2048
#define DD 1024
#define HH 16
#define HD 64
#define MM (BB * SS)   // 8192 rows

typedef unsigned long long u64;

// ---------------- scratch (device globals; allocation-free rule) ----------------
__device__ __nv_bfloat16 g_qhi[MM * DD];
__device__ __nv_bfloat16 g_qlo[MM * DD];
__device__ __nv_bfloat16 g_khi[MM * DD];
__device__ __nv_bfloat16 g_klo[MM * DD];
__device__ __nv_bfloat16 g_vhi[MM * DD];
__device__ __nv_bfloat16 g_vlo[MM * DD];

__device__ __nv_bfloat16 g_xhi[MM * DD];
__device__ __nv_bfloat16 g_xlo[MM * DD];
__device__ __nv_bfloat16 g_oahi[MM * DD];
__device__ __nv_bfloat16 g_oalo[MM * DD];

__device__ __nv_bfloat16 g_wq_hi[DD * DD];
__device__ __nv_bfloat16 g_wq_lo[DD * DD];
__device__ __nv_bfloat16 g_wk_hi[DD * DD];
__device__ __nv_bfloat16 g_wk_lo[DD * DD];
__device__ __nv_bfloat16 g_wv_hi[DD * DD];
__device__ __nv_bfloat16 g_wv_lo[DD * DD];
__device__ __nv_bfloat16 g_wo_hi[DD * DD];
__device__ __nv_bfloat16 g_wo_lo[DD * DD];

// ---------------- PTX helpers ----------------
__device__ __forceinline__ uint32_t smem_u32(const void* p) {
    uint32_t a;
    asm("{ .reg .u64 t; cvta.to.shared.u64 t, %1; cvt.u32.u64 %0, t; }" : "=r"(a) : "l"(p));
    return a;
}
__device__ __forceinline__ void cp16(uint32_t dst, const void* src) {
    asm volatile("cp.async.cg.shared.global [%0], [%1], 16;" :: "r"(dst), "l"(src) : "memory");
}
#define CP_COMMIT() asm volatile("cp.async.commit_group;" ::: "memory")
#define CP_WAIT(n) asm volatile("cp.async.wait_group %0;" :: "n"(n) : "memory")

__device__ __forceinline__ void ldm4(uint32_t* d, uint32_t addr) {
    asm volatile("ldmatrix.sync.aligned.m8n8.x4.shared.b16 {%0,%1,%2,%3}, [%4];"
                 : "=r"(d[0]), "=r"(d[1]), "=r"(d[2]), "=r"(d[3]) : "r"(addr));
}
__device__ __forceinline__ void ldm4t(uint32_t* d, uint32_t addr) {
    asm volatile("ldmatrix.sync.aligned.m8n8.x4.trans.shared.b16 {%0,%1,%2,%3}, [%4];"
                 : "=r"(d[0]), "=r"(d[1]), "=r"(d[2]), "=r"(d[3]) : "r"(addr));
}
__device__ __forceinline__ void mma16816(float* c, const uint32_t* a, uint32_t b0, uint32_t b1) {
    asm volatile(
        "mma.sync.aligned.m16n8k16.row.col.f32.bf16.bf16.f32 "
        "{%0,%1,%2,%3}, {%4,%5,%6,%7}, {%8,%9}, {%0,%1,%2,%3};"
        : "+f"(c[0]), "+f"(c[1]), "+f"(c[2]), "+f"(c[3])
        : "r"(a[0]), "r"(a[1]), "r"(a[2]), "r"(a[3]), "r"(b0), "r"(b1));
}
__device__ __forceinline__ float ex2f(float x) {
    float r;
    asm("ex2.approx.f32 %0, %1;" : "=f"(r) : "f"(x));
    return r;
}
__device__ __forceinline__ uint32_t pack_bf16_hi(float x, float y, float& rx, float& ry) {
    __nv_bfloat162 h = __float22bfloat162_rn(make_float2(x, y));
    float2 f = __bfloat1622float2(h);
    rx = x - f.x;
    ry = y - f.y;
    return *(uint32_t*)&h;
}
__device__ __forceinline__ uint32_t pack_bf16(float x, float y) {
    __nv_bfloat162 h = __float22bfloat162_rn(make_float2(x, y));
    return *(uint32_t*)&h;
}

// ---------------- split / transpose prep kernels ----------------
__global__ void __launch_bounds__(256)
split_kernel(const float* __restrict__ src, __nv_bfloat16* __restrict__ hi,
             __nv_bfloat16* __restrict__ lo, int n4) {
    int i = blockIdx.x * 256 + threadIdx.x;
    if (i >= n4) return;
    float4 v = ((const float4*)src)[i];
    __nv_bfloat16 h0 = __float2bfloat16(v.x);
    __nv_bfloat16 h1 = __float2bfloat16(v.y);
    __nv_bfloat16 h2 = __float2bfloat16(v.z);
    __nv_bfloat16 h3 = __float2bfloat16(v.w);
    __nv_bfloat16 l0 = __float2bfloat16(v.x - __bfloat162float(h0));
    __nv_bfloat16 l1 = __float2bfloat16(v.y - __bfloat162float(h1));
    __nv_bfloat16 l2 = __float2bfloat16(v.z - __bfloat162float(h2));
    __nv_bfloat16 l3 = __float2bfloat16(v.w - __bfloat162float(h3));
    ushort4 hv, lv;
    hv.x = __bfloat16_as_ushort(h0); hv.y = __bfloat16_as_ushort(h1);
    hv.z = __bfloat16_as_ushort(h2); hv.w = __bfloat16_as_ushort(h3);
    lv.x = __bfloat16_as_ushort(l0); lv.y = __bfloat16_as_ushort(l1);
    lv.z = __bfloat16_as_ushort(l2); lv.w = __bfloat16_as_ushort(l3);
    ((ushort4*)hi)[i] = hv;
    ((ushort4*)lo)[i] = lv;
}

__global__ void __launch_bounds__(256)
transpose_split_kernel(const float* __restrict__ Wq, const float* __restrict__ Wk,
                       const float* __restrict__ Wv) {
    const float* W = (blockIdx.z == 0) ? Wq : ((blockIdx.z == 1) ? Wk : Wv);
    __nv_bfloat16* hi = (blockIdx.z == 0) ? g_wq_hi : ((blockIdx.z == 1) ? g_wk_hi : g_wv_hi);
    __nv_bfloat16* lo = (blockIdx.z == 0) ? g_wq_lo : ((blockIdx.z == 1) ? g_wk_lo : g_wv_lo);
    __shared__ float t[32][33];
    int tx = threadIdx.x & 31;
    int ty = threadIdx.x >> 5;
    int k0 = blockIdx.y * 32;
    int n0 = blockIdx.x * 32;
#pragma unroll
    for (int i = 0; i < 4; i++)
        t[ty + i * 8][tx] = W[(size_t)(k0 + ty + i * 8) * DD + n0 + tx];
    __syncthreads();
#pragma unroll
    for (int i = 0; i < 4; i++) {
        int n = n0 + ty + i * 8;
        int k = k0 + tx;
        float v = t[tx][ty + i * 8];
        __nv_bfloat16 h = __float2bfloat16(v);
        hi[(size_t)n * DD + k] = h;
        lo[(size_t)n * DD + k] = __float2bfloat16(v - __bfloat162float(h));
    }
}

// ---------------- HMMA split-bf16 GEMM (swizzled, 3-stage) ----------------
#define BK 32
#define MAT 8192
#define OFF_AH 0
#define OFF_AL (1 * MAT)
#define OFF_BH (2 * MAT)
#define OFF_BL (3 * MAT)
#define STAGE_BYTES (4 * MAT)
#define GSMEM_TOTAL (3 * STAGE_BYTES)

__device__ __forceinline__ void load_stage(uint32_t sb,
                                           const __nv_bfloat16* __restrict__ ahi,
                                           const __nv_bfloat16* __restrict__ alo,
                                           const __nv_bfloat16* __restrict__ bhi,
                                           const __nv_bfloat16* __restrict__ blo,
                                           int m0, int n0, int kt, int tid) {
#pragma unroll
    for (int i = 0; i < 2; i++) {
        int idx = tid + i * 256;
        int r = idx >> 2;
        int c = idx & 3;
        uint32_t so = (uint32_t)(r * 64 + ((c ^ ((r >> 1) & 3)) << 4));
        size_t goA = (size_t)(m0 + r) * DD + kt + c * 8;
        size_t goB = (size_t)(n0 + r) * DD + kt + c * 8;
        cp16(sb + OFF_AH + so, ahi + goA);
        cp16(sb + OFF_AL + so, alo + goA);
        cp16(sb + OFF_BH + so, bhi + goB);
        cp16(sb + OFF_BL + so, blo + goB);
    }
}

template <int OUT_MODE>
__device__ __forceinline__ void gemm_core(const __nv_bfloat16* __restrict__ ahi,
                                          const __nv_bfloat16* __restrict__ alo,
                                          const __nv_bfloat16* __restrict__ bhi,
                                          const __nv_bfloat16* __restrict__ blo,
                                          float* __restrict__ C,
                                          __nv_bfloat16* __restrict__ Chi,
                                          __nv_bfloat16* __restrict__ Clo,
                                          float scale) {
    extern __shared__ char sm[];
    uint32_t sbase = smem_u32(sm);
    const int tid = threadIdx.x;
    const int wid = tid >> 5;
    const int lane = tid & 31;
    const int wm = wid & 3;
    const int wn = wid >> 2;
    const int m0 = blockIdx.y * 128;
    const int n0 = blockIdx.x * 128;

    const int g = lane >> 3;
    const int rr = lane & 7;
    const int rA = wm * 32 + (g & 1) * 8 + rr;
    const uint32_t aBase = (uint32_t)(rA * 64);
    const uint32_t aSw = (uint32_t)((((g >> 1) ^ ((rA >> 1) & 3)) << 4));
    const int rB = wn * 64 + (g >> 1) * 8 + rr;
    const uint32_t bBase = (uint32_t)(rB * 64);
    const uint32_t bSw = (uint32_t)((((g & 1) ^ ((rB >> 1) & 3)) << 4));

    float acc[2][8][4];
#pragma unroll
    for (int mi = 0; mi < 2; mi++)
#pragma unroll
        for (int ni = 0; ni < 8; ni++)
#pragma unroll
            for (int j = 0; j < 4; j++) acc[mi][ni][j] = 0.0f;

    const int NST = DD / BK;   // 32
    load_stage(sbase + 0 * STAGE_BYTES, ahi, alo, bhi, blo, m0, n0, 0, tid);
    CP_COMMIT();
    load_stage(sbase + 1 * STAGE_BYTES, ahi, alo, bhi, blo, m0, n0, BK, tid);
    CP_COMMIT();

    int sidx = 0;
    for (int s = 0; s < NST; s++) {
        if (s < NST - 1) { CP_WAIT(1); } else { CP_WAIT(0); }
        __syncthreads();
        if (s + 2 < NST) {
            int nb = sidx + 2; if (nb >= 3) nb -= 3;
            load_stage(sbase + nb * STAGE_BYTES, ahi, alo, bhi, blo, m0, n0, (s + 2) * BK, tid);
            CP_COMMIT();
        }
        uint32_t sb = sbase + sidx * STAGE_BYTES;

#pragma unroll
        for (int kk = 0; kk < 2; kk++) {
            uint32_t ah[2][4], al[2][4], bh[4][4], bl[4][4];
            const uint32_t asw = kk ? (aSw ^ 32u) : aSw;
            const uint32_t bsw = kk ? (bSw ^ 32u) : bSw;
#pragma unroll
            for (int mi = 0; mi < 2; mi++) {
                uint32_t ao = sb + aBase + (uint32_t)(mi * 1024) + asw;
                ldm4(ah[mi], ao + OFF_AH);
                ldm4(al[mi], ao + OFF_AL);
            }
#pragma unroll
            for (int np = 0; np < 4; np++) {
                uint32_t bo = sb + bBase + (uint32_t)(np * 1024) + bsw;
                ldm4(bh[np], bo + OFF_BH);
                ldm4(bl[np], bo + OFF_BL);
            }
#pragma unroll
            for (int mi = 0; mi < 2; mi++)
#pragma unroll
                for (int ni = 0; ni < 8; ni++)
                    mma16816(acc[mi][ni], ah[mi], bh[ni >> 1][(ni & 1) * 2], bh[ni >> 1][(ni & 1) * 2 + 1]);
#pragma unroll
            for (int mi = 0; mi < 2; mi++)
#pragma unroll
                for (int ni = 0; ni < 8; ni++)
                    mma16816(acc[mi][ni], ah[mi], bl[ni >> 1][(ni & 1) * 2], bl[ni >> 1][(ni & 1) * 2 + 1]);
#pragma unroll
            for (int mi = 0; mi < 2; mi++)
#pragma unroll
                for (int ni = 0; ni < 8; ni++)
                    mma16816(acc[mi][ni], al[mi], bh[ni >> 1][(ni & 1) * 2], bh[ni >> 1][(ni & 1) * 2 + 1]);
        }
        sidx++; if (sidx == 3) sidx = 0;
    }

    const int row_b = m0 + wm * 32 + (lane >> 2);
    const int col_b = n0 + wn * 64 + (lane & 3) * 2;
#pragma unroll
    for (int mi = 0; mi < 2; mi++)
#pragma unroll
        for (int ni = 0; ni < 8; ni++) {
            int row = row_b + mi * 16;
            int col = col_b + ni * 8;
            if (OUT_MODE == 0) {
                *(float2*)&C[(size_t)row * DD + col] =
                    make_float2(acc[mi][ni][0], acc[mi][ni][1]);
                *(float2*)&C[(size_t)(row + 8) * DD + col] =
                    make_float2(acc[mi][ni][2], acc[mi][ni][3]);
            } else {
#pragma unroll
                for (int rh = 0; rh < 2; rh++) {
                    float v0 = acc[mi][ni][rh * 2 + 0] * scale;
                    float v1 = acc[mi][ni][rh * 2 + 1] * scale;
                    float r0, r1;
                    uint32_t hp = pack_bf16_hi(v0, v1, r0, r1);
                    uint32_t lp = pack_bf16(r0, r1);
                    size_t off = (size_t)(row + rh * 8) * DD + col;
                    *(uint32_t*)&Chi[off] = hp;
                    *(uint32_t*)&Clo[off] = lp;
                }
            }
        }
}

__global__ void __launch_bounds__(256, 2)
gemm_qkv_kernel() {
    const __nv_bfloat16* bhi = (blockIdx.z == 0) ? g_wq_hi : ((blockIdx.z == 1) ? g_wk_hi : g_wv_hi);
    const __nv_bfloat16* blo = (blockIdx.z == 0) ? g_wq_lo : ((blockIdx.z == 1) ? g_wk_lo : g_wv_lo);
    __nv_bfloat16* chi = (blockIdx.z == 0) ? g_qhi : ((blockIdx.z == 1) ? g_khi : g_vhi);
    __nv_bfloat16* clo = (blockIdx.z == 0) ? g_qlo : ((blockIdx.z == 1) ? g_klo : g_vlo);
    // Q pre-scaled by (1/sqrt(HD)) * log2(e) so attention uses ex2 directly
    float scale = (blockIdx.z == 0) ? 0.125f * 1.4426950408889634f : 1.0f;
    gemm_core<1>(g_xhi, g_xlo, bhi, blo, nullptr, chi, clo, scale);
}

__global__ void __launch_bounds__(256, 2)
gemm_out_kernel(float* __restrict__ out) {
    gemm_core<0>(g_oahi, g_oalo, g_wo_hi, g_wo_lo, out, nullptr, nullptr, 1.0f);
}

// ---------------- HMMA flash attention (no-max softmax, swizzled, 2 CTA/SM) ----------------
#define QT 16384
#define KVT 8192
#define OFF_Q 0
#define OFF_ST (2 * QT)
#define STG (4 * KVT)
#define ATTN_SMEM (OFF_ST + 2 * STG)  // 98304

__device__ __forceinline__ void kv_load(uint32_t stage, size_t gkv, int k0, int tid) {
#pragma unroll
    for (int i = 0; i < 8; i++) {
        int tile = i >> 1;
        int r = (i & 1) * 32 + (tid >> 3);
        int c = tid & 7;
        const __nv_bfloat16* src = (tile == 0) ? g_khi : (tile == 1) ? g_klo
                                 : (tile == 2) ? g_vhi : g_vlo;
        cp16(stage + (uint32_t)(tile * KVT + r * 128 + ((c ^ (r & 7)) << 4)),
             src + gkv + (size_t)(k0 + r) * DD + c * 8);
    }
}

__global__ void __launch_bounds__(256, 2)
attn_kernel() {
    extern __shared__ char sm[];
    uint32_t sb = smem_u32(sm);
    const int tid = threadIdx.x;
    const int wid = tid >> 5;
    const int lane = tid & 31;
    const int bh = blockIdx.y;
    const int b = bh >> 4;
    const int h = bh & 15;
    // reversed order: longest blocks (largest q0) launch first
    const int q0 = ((int)gridDim.x - 1 - (int)blockIdx.x) * 128;

    const size_t gq = (size_t)(b * SS + q0) * DD + h * HD;
    const size_t gkv = (size_t)(b * SS) * DD + h * HD;

    // load Q tile (hi/lo), swizzled
#pragma unroll
    for (int i = 0; i < 8; i++) {
        int half = i >> 2;
        int r = (i & 3) * 32 + (tid >> 3);
        int c = tid & 7;
        const __nv_bfloat16* src = (half ? g_qlo : g_qhi) + gq + (size_t)r * DD + c * 8;
        cp16(sb + (uint32_t)(OFF_Q + half * QT + r * 128 + ((c ^ (r & 7)) << 4)), src);
    }
    kv_load(sb + OFF_ST, gkv, 0, tid);
    CP_COMMIT();
    CP_WAIT(0);
    __syncthreads();

    // Q A-fragments
    uint32_t qh[4][4], ql[4][4];
    {
        const int rQ = 16 * wid + (lane & 15);
        const int tQ = lane >> 4;
        const uint32_t qrow = sb + OFF_Q + (uint32_t)(rQ * 128);
        const int sQ = rQ & 7;
#pragma unroll
        for (int q = 0; q < 4; q++) {
            uint32_t cofs = (uint32_t)(((tQ + 2 * q) ^ sQ) << 4);
            ldm4(qh[q], qrow + cofs);
            ldm4(ql[q], qrow + QT + cofs);
        }
    }

    const int rK = ((lane >> 4) << 3) + (lane & 7);
    const int tK = (lane >> 3) & 1;
    const int sK = rK & 7;
    const uint32_t kBase = (uint32_t)(rK * 128);
    const int rV = lane & 15;
    const int tV = lane >> 4;
    const int sV = rV & 7;
    const uint32_t vBase = (uint32_t)(rV * 128);

    float o[8][4];
#pragma unroll
    for (int nt = 0; nt < 8; nt++)
#pragma unroll
        for (int j = 0; j < 4; j++) o[nt][j] = 0.0f;
    float l0 = 0.0f, l1 = 0.0f;

    const int row0 = q0 + 16 * wid + (lane >> 2);
    const int row_min = q0 + 16 * wid;
    const int qrow_hi = q0 + 16 * wid + 15;
    const int ntiles = q0 / 64 + 2;

    for (int it = 0; it < ntiles; it++) {
        const int k0 = it * 64;
        if (it + 1 < ntiles) {
            kv_load(sb + OFF_ST + ((it + 1) & 1) * STG, gkv, (it + 1) * 64, tid);
            CP_COMMIT();
            CP_WAIT(1);
        } else {
            CP_WAIT(0);
        }
        __syncthreads();

        if (k0 <= qrow_hi) {
            const uint32_t stage = sb + OFF_ST + (it & 1) * STG;

            // ---- S = Q K^T, 3-pass, pair-blocked pass-major ----
            float s[8][4];
#pragma unroll
            for (int nt = 0; nt < 8; nt++)
#pragma unroll
                for (int j = 0; j < 4; j++) s[nt][j] = 0.0f;

#pragma unroll
            for (int q = 0; q < 4; q++) {
                const uint32_t kc = (uint32_t)((((2 * q) + tK) ^ sK) << 4);
#pragma unroll
                for (int pp = 0; pp < 2; pp++) {
                    uint32_t kh4[2][4], kl4[2][4];
#pragma unroll
                    for (int p2 = 0; p2 < 2; p2++) {
                        int p = pp * 2 + p2;
                        uint32_t a = stage + kBase + (uint32_t)(p * 2048) + kc;
                        ldm4(kh4[p2], a);
                        ldm4(kl4[p2], a + KVT);
                    }
#pragma unroll
                    for (int p2 = 0; p2 < 2; p2++) {
                        int p = pp * 2 + p2;
                        mma16816(s[2 * p], qh[q], kh4[p2][0], kh4[p2][1]);
                        mma16816(s[2 * p + 1], qh[q], kh4[p2][2], kh4[p2][3]);
                    }
#pragma unroll
                    for (int p2 = 0; p2 < 2; p2++) {
                        int p = pp * 2 + p2;
                        mma16816(s[2 * p], qh[q], kl4[p2][0], kl4[p2][1]);
                        mma16816(s[2 * p + 1], qh[q], kl4[p2][2], kl4[p2][3]);
                    }
#pragma unroll
                    for (int p2 = 0; p2 < 2; p2++) {
                        int p = pp * 2 + p2;
                        mma16816(s[2 * p], ql[q], kh4[p2][0], kh4[p2][1]);
                        mma16816(s[2 * p + 1], ql[q], kh4[p2][2], kh4[p2][3]);
                    }
                }
            }

            // ---- causal mask ----
            if (k0 + 63 > row_min) {
#pragma unroll
                for (int nt = 0; nt < 8; nt++) {
                    int key = k0 + nt * 8 + (lane & 3) * 2;
#pragma unroll
                    for (int j = 0; j < 4; j++) {
                        int r = row0 + (j >> 1) * 8;
                        if (key + (j & 1) > r) s[nt][j] = -1e30f;
                    }
                }
            }

            // ---- no-max softmax: P = 2^s (Q pre-scaled by log2e/8; bounded stats) ----
#pragma unroll
            for (int nt = 0; nt < 8; nt++) {
                s[nt][0] = ex2f(s[nt][0]);
                s[nt][1] = ex2f(s[nt][1]);
                s[nt][2] = ex2f(s[nt][2]);
                s[nt][3] = ex2f(s[nt][3]);
                l0 += s[nt][0] + s[nt][1];
                l1 += s[nt][2] + s[nt][3];
            }

            // ---- PV, 3-pass, pair-blocked pass-major ----
#pragma unroll
            for (int kk = 0; kk < 4; kk++) {
                uint32_t pah[4], pal[4];
                float r0, r1;
                pah[0] = pack_bf16_hi(s[2 * kk][0], s[2 * kk][1], r0, r1);
                pal[0] = pack_bf16(r0, r1);
                pah[1] = pack_bf16_hi(s[2 * kk][2], s[2 * kk][3], r0, r1);
                pal[1] = pack_bf16(r0, r1);
                pah[2] = pack_bf16_hi(s[2 * kk + 1][0], s[2 * kk + 1][1], r0, r1);
                pal[2] = pack_bf16(r0, r1);
                pah[3] = pack_bf16_hi(s[2 * kk + 1][2], s[2 * kk + 1][3], r0, r1);
                pal[3] = pack_bf16(r0, r1);
                const uint32_t vrow = stage + 2 * KVT + vBase + (uint32_t)(kk * 2048);
#pragma unroll
                for (int uu = 0; uu < 2; uu++) {
                    uint32_t vh4[2][4], vl4[2][4];
#pragma unroll
                    for (int u2 = 0; u2 < 2; u2++) {
                        int u = uu * 2 + u2;
                        uint32_t a = vrow + (uint32_t)((((2 * u) + tV) ^ sV) << 4);
                        ldm4t(vh4[u2], a);
                        ldm4t(vl4[u2], a + KVT);
                    }
#pragma unroll
                    for (int u2 = 0; u2 < 2; u2++) {
                        int u = uu * 2 + u2;
                        mma16816(o[2 * u], pah, vh4[u2][0], vh4[u2][1]);
                        mma16816(o[2 * u + 1], pah, vh4[u2][2], vh4[u2][3]);
                    }
#pragma unroll
                    for (int u2 = 0; u2 < 2; u2++) {
                        int u = uu * 2 + u2;
                        mma16816(o[2 * u], pah, vl4[u2][0], vl4[u2][1]);
                        mma16816(o[2 * u + 1], pah, vl4[u2][2], vl4[u2][3]);
                    }
#pragma unroll
                    for (int u2 = 0; u2 < 2; u2++) {
                        int u = uu * 2 + u2;
                        mma16816(o[2 * u], pal, vh4[u2][0], vh4[u2][1]);
                        mma16816(o[2 * u + 1], pal, vh4[u2][2], vh4[u2][3]);
                    }
                }
            }
        }
        __syncthreads();
    }

    // ---- finalize ----
    l0 += __shfl_xor_sync(0xffffffffu, l0, 1);
    l0 += __shfl_xor_sync(0xffffffffu, l0, 2);
    l1 += __shfl_xor_sync(0xffffffffu, l1, 1);
    l1 += __shfl_xor_sync(0xffffffffu, l1, 2);
    float inv0 = 1.0f / l0;
    float inv1 = 1.0f / l1;

    const int grow0 = b * SS + q0 + 16 * wid + (lane >> 2);
    const int gcol = h * HD + (lane & 3) * 2;
#pragma unroll
    for (int nt = 0; nt < 8; nt++) {
#pragma unroll
        for (int rh = 0; rh < 2; rh++) {
            float inv = rh ? inv1 : inv0;
            float v0 = o[nt][rh * 2 + 0] * inv;
            float v1 = o[nt][rh * 2 + 1] * inv;
            float r0, r1;
            uint32_t hp = pack_bf16_hi(v0, v1, r0, r1);
            uint32_t lp = pack_bf16(r0, r1);
            size_t off = (size_t)(grow0 + rh * 8) * DD + gcol + nt * 8;
            *(uint32_t*)&g_oahi[off] = hp;
            *(uint32_t*)&g_oalo[off] = lp;
        }
    }
}

// ---------------- launch ----------------
extern "C" void kernel_launch(void* const* d_in, const int* in_sizes, int n_in,
                              void* d_out, int out_size) {
    const float* x  = (const float*)d_in[0];
    const float* Wq = (const float*)d_in[1];
    const float* Wk = (const float*)d_in[2];
    const float* Wv = (const float*)d_in[3];
    const float* Wo = (const float*)d_in[4];
    float* out = (float*)d_out;

    cudaFuncSetAttribute(attn_kernel,
                         cudaFuncAttributeMaxDynamicSharedMemorySize, ATTN_SMEM);
    cudaFuncSetAttribute(gemm_qkv_kernel,
                         cudaFuncAttributeMaxDynamicSharedMemorySize, GSMEM_TOTAL);
    cudaFuncSetAttribute(gemm_out_kernel,
                         cudaFuncAttributeMaxDynamicSharedMemorySize, GSMEM_TOTAL);

    __nv_bfloat16 *p_xhi, *p_xlo, *p_wohi, *p_wolo;
    cudaGetSymbolAddress((void**)&p_xhi, g_xhi);
    cudaGetSymbolAddress((void**)&p_xlo, g_xlo);
    cudaGetSymbolAddress((void**)&p_wohi, g_wo_hi);
    cudaGetSymbolAddress((void**)&p_wolo, g_wo_lo);

    split_kernel<<<(MM * DD / 4 + 255) / 256, 256>>>(x, p_xhi, p_xlo, MM * DD / 4);
    split_kernel<<<(DD * DD / 4 + 255) / 256, 256>>>(Wo, p_wohi, p_wolo, DD * DD / 4);
    transpose_split_kernel<<<dim3(32, 32, 3), 256>>>(Wq, Wk, Wv);

    dim3 gq(DD / 128, MM / 128, 3);       // (8, 64, 3)
    gemm_qkv_kernel<<<gq, 256, GSMEM_TOTAL>>>();

    dim3 ga(SS / 128, BB * HH);           // (16, 64)
    attn_kernel<<<ga, 256, ATTN_SMEM>>>();

    dim3 go(DD / 128, MM / 128, 1);       // (8, 64)
    gemm_out_kernel<<<go, 256, GSMEM_TOTAL>>>(out);
}

// round 10
// speedup vs baseline: 4.0595x; 1.3930x over previous
#include <cuda_runtime.h>
#include <cuda_fp16.h>
#include <cstdint>

// Problem constants
#define BB 4
#define SS 2048
#define DD 1024
#define HH 16
#define HD 64
#define MM (BB * SS)   // 8192 rows

// ---------------- scratch (device globals; allocation-free rule) ----------------
// fp16 2-pass scheme: "A" operands single fp16; "B" operands split hi+lo fp16.
__device__ __half g_q[MM * DD];       // Q single fp16, pre-scaled by 0.125*log2e
__device__ __half g_kh[MM * DD];
__device__ __half g_kl[MM * DD];
__device__ __half g_vh[MM * DD];
__device__ __half g_vl[MM * DD];
__device__ __half g_x[MM * DD];       // x single fp16
__device__ __half g_oa[MM * DD];      // attention output single fp16

__device__ __half g_wq_hi[DD * DD];
__device__ __half g_wq_lo[DD * DD];
__device__ __half g_wk_hi[DD * DD];
__device__ __half g_wk_lo[DD * DD];
__device__ __half g_wv_hi[DD * DD];
__device__ __half g_wv_lo[DD * DD];
__device__ __half g_wo_hi[DD * DD];
__device__ __half g_wo_lo[DD * DD];

#define QSCALE (0.125f * 1.4426950408889634f)

// ---------------- PTX helpers ----------------
__device__ __forceinline__ uint32_t smem_u32(const void* p) {
    uint32_t a;
    asm("{ .reg .u64 t; cvta.to.shared.u64 t, %1; cvt.u32.u64 %0, t; }" : "=r"(a) : "l"(p));
    return a;
}
__device__ __forceinline__ void cp16(uint32_t dst, const void* src) {
    asm volatile("cp.async.cg.shared.global [%0], [%1], 16;" :: "r"(dst), "l"(src) : "memory");
}
#define CP_COMMIT() asm volatile("cp.async.commit_group;" ::: "memory")
#define CP_WAIT(n) asm volatile("cp.async.wait_group %0;" :: "n"(n) : "memory")

__device__ __forceinline__ void ldm4(uint32_t* d, uint32_t addr) {
    asm volatile("ldmatrix.sync.aligned.m8n8.x4.shared.b16 {%0,%1,%2,%3}, [%4];"
                 : "=r"(d[0]), "=r"(d[1]), "=r"(d[2]), "=r"(d[3]) : "r"(addr));
}
__device__ __forceinline__ void ldm4t(uint32_t* d, uint32_t addr) {
    asm volatile("ldmatrix.sync.aligned.m8n8.x4.trans.shared.b16 {%0,%1,%2,%3}, [%4];"
                 : "=r"(d[0]), "=r"(d[1]), "=r"(d[2]), "=r"(d[3]) : "r"(addr));
}
__device__ __forceinline__ void mma16816(float* c, const uint32_t* a, uint32_t b0, uint32_t b1) {
    asm volatile(
        "mma.sync.aligned.m16n8k16.row.col.f32.f16.f16.f32 "
        "{%0,%1,%2,%3}, {%4,%5,%6,%7}, {%8,%9}, {%0,%1,%2,%3};"
        : "+f"(c[0]), "+f"(c[1]), "+f"(c[2]), "+f"(c[3])
        : "r"(a[0]), "r"(a[1]), "r"(a[2]), "r"(a[3]), "r"(b0), "r"(b1));
}
__device__ __forceinline__ float ex2f(float x) {
    float r;
    asm("ex2.approx.f32 %0, %1;" : "=f"(r) : "f"(x));
    return r;
}
__device__ __forceinline__ uint32_t pack_h2(float x, float y) {
    __half2 h = __floats2half2_rn(x, y);
    return *(uint32_t*)&h;
}
__device__ __forceinline__ uint32_t pack_h2_hi(float x, float y, float& rx, float& ry) {
    __half2 h = __floats2half2_rn(x, y);
    float2 f = __half22float2(h);
    rx = x - f.x;
    ry = y - f.y;
    return *(uint32_t*)&h;
}

// ---------------- prep kernels ----------------
__global__ void __launch_bounds__(256)
convert_half_kernel(const float* __restrict__ src, __half* __restrict__ dst, int n4) {
    int i = blockIdx.x * 256 + threadIdx.x;
    if (i >= n4) return;
    float4 v = ((const float4*)src)[i];
    ushort4 o;
    __half h0 = __float2half_rn(v.x), h1 = __float2half_rn(v.y);
    __half h2 = __float2half_rn(v.z), h3 = __float2half_rn(v.w);
    o.x = __half_as_ushort(h0); o.y = __half_as_ushort(h1);
    o.z = __half_as_ushort(h2); o.w = __half_as_ushort(h3);
    ((ushort4*)dst)[i] = o;
}

__global__ void __launch_bounds__(256)
split_half_kernel(const float* __restrict__ src, __half* __restrict__ hi,
                  __half* __restrict__ lo, int n4) {
    int i = blockIdx.x * 256 + threadIdx.x;
    if (i >= n4) return;
    float4 v = ((const float4*)src)[i];
    __half h0 = __float2half_rn(v.x), h1 = __float2half_rn(v.y);
    __half h2 = __float2half_rn(v.z), h3 = __float2half_rn(v.w);
    __half l0 = __float2half_rn(v.x - __half2float(h0));
    __half l1 = __float2half_rn(v.y - __half2float(h1));
    __half l2 = __float2half_rn(v.z - __half2float(h2));
    __half l3 = __float2half_rn(v.w - __half2float(h3));
    ushort4 hv, lv;
    hv.x = __half_as_ushort(h0); hv.y = __half_as_ushort(h1);
    hv.z = __half_as_ushort(h2); hv.w = __half_as_ushort(h3);
    lv.x = __half_as_ushort(l0); lv.y = __half_as_ushort(l1);
    lv.z = __half_as_ushort(l2); lv.w = __half_as_ushort(l3);
    ((ushort4*)hi)[i] = hv;
    ((ushort4*)lo)[i] = lv;
}

__global__ void __launch_bounds__(256)
transpose_split_kernel(const float* __restrict__ Wq, const float* __restrict__ Wk,
                       const float* __restrict__ Wv) {
    const float* W = (blockIdx.z == 0) ? Wq : ((blockIdx.z == 1) ? Wk : Wv);
    __half* hi = (blockIdx.z == 0) ? g_wq_hi : ((blockIdx.z == 1) ? g_wk_hi : g_wv_hi);
    __half* lo = (blockIdx.z == 0) ? g_wq_lo : ((blockIdx.z == 1) ? g_wk_lo : g_wv_lo);
    __shared__ float t[32][33];
    int tx = threadIdx.x & 31;
    int ty = threadIdx.x >> 5;
    int k0 = blockIdx.y * 32;
    int n0 = blockIdx.x * 32;
#pragma unroll
    for (int i = 0; i < 4; i++)
        t[ty + i * 8][tx] = W[(size_t)(k0 + ty + i * 8) * DD + n0 + tx];
    __syncthreads();
#pragma unroll
    for (int i = 0; i < 4; i++) {
        int n = n0 + ty + i * 8;
        int k = k0 + tx;
        float v = t[tx][ty + i * 8];
        __half h = __float2half_rn(v);
        hi[(size_t)n * DD + k] = h;
        lo[(size_t)n * DD + k] = __float2half_rn(v - __half2float(h));
    }
}

// ---------------- HMMA fp16 2-pass GEMM (swizzled, 4-stage) ----------------
// C[M,N] = A @ B^T; A single fp16 [M,K], B split fp16 [N,K]. Tile 128x128, BK=32.
#define BK 32
#define MAT 8192                     // 128 rows x 64B (32 fp16)
#define OFF_A 0
#define OFF_BH (1 * MAT)
#define OFF_BL (2 * MAT)
#define STAGE_BYTES (3 * MAT)        // 24576
#define NPIPE 4
#define GSMEM_TOTAL (NPIPE * STAGE_BYTES)  // 98304

__device__ __forceinline__ void load_stage(uint32_t sb,
                                           const __half* __restrict__ A,
                                           const __half* __restrict__ Bh,
                                           const __half* __restrict__ Bl,
                                           int m0, int n0, int kt, int tid) {
#pragma unroll
    for (int i = 0; i < 2; i++) {
        int idx = tid + i * 256;
        int r = idx >> 2;
        int c = idx & 3;
        uint32_t so = (uint32_t)(r * 64 + ((c ^ ((r >> 1) & 3)) << 4));
        size_t goA = (size_t)(m0 + r) * DD + kt + c * 8;
        size_t goB = (size_t)(n0 + r) * DD + kt + c * 8;
        cp16(sb + OFF_A + so, A + goA);
        cp16(sb + OFF_BH + so, Bh + goB);
        cp16(sb + OFF_BL + so, Bl + goB);
    }
}

// OUT_MODE 0: fp32 C.  OUT_MODE 1: split hi/lo fp16 (scale).  OUT_MODE 2: single fp16 (scale).
template <int OUT_MODE>
__device__ __forceinline__ void gemm_core(const __half* __restrict__ A,
                                          const __half* __restrict__ Bh,
                                          const __half* __restrict__ Bl,
                                          float* __restrict__ C,
                                          __half* __restrict__ Chi,
                                          __half* __restrict__ Clo,
                                          float scale) {
    extern __shared__ char sm[];
    uint32_t sbase = smem_u32(sm);
    const int tid = threadIdx.x;
    const int wid = tid >> 5;
    const int lane = tid & 31;
    const int wm = wid & 3;
    const int wn = wid >> 2;
    const int m0 = blockIdx.y * 128;
    const int n0 = blockIdx.x * 128;

    const int g = lane >> 3;
    const int rr = lane & 7;
    const int rA = wm * 32 + (g & 1) * 8 + rr;
    const uint32_t aBase = (uint32_t)(rA * 64);
    const uint32_t aSw = (uint32_t)((((g >> 1) ^ ((rA >> 1) & 3)) << 4));
    const int rB = wn * 64 + (g >> 1) * 8 + rr;
    const uint32_t bBase = (uint32_t)(rB * 64);
    const uint32_t bSw = (uint32_t)((((g & 1) ^ ((rB >> 1) & 3)) << 4));

    float acc[2][8][4];
#pragma unroll
    for (int mi = 0; mi < 2; mi++)
#pragma unroll
        for (int ni = 0; ni < 8; ni++)
#pragma unroll
            for (int j = 0; j < 4; j++) acc[mi][ni][j] = 0.0f;

    const int NST = DD / BK;   // 32
    load_stage(sbase + 0 * STAGE_BYTES, A, Bh, Bl, m0, n0, 0, tid);
    CP_COMMIT();
    load_stage(sbase + 1 * STAGE_BYTES, A, Bh, Bl, m0, n0, BK, tid);
    CP_COMMIT();
    load_stage(sbase + 2 * STAGE_BYTES, A, Bh, Bl, m0, n0, 2 * BK, tid);
    CP_COMMIT();

    for (int s = 0; s < NST; s++) {
        if (s < NST - 2)      { CP_WAIT(2); }
        else if (s == NST - 2){ CP_WAIT(1); }
        else                  { CP_WAIT(0); }
        __syncthreads();
        if (s + 3 < NST) {
            load_stage(sbase + ((s + 3) & 3) * STAGE_BYTES, A, Bh, Bl, m0, n0, (s + 3) * BK, tid);
            CP_COMMIT();
        }
        uint32_t sb = sbase + (s & 3) * STAGE_BYTES;

#pragma unroll
        for (int kk = 0; kk < 2; kk++) {
            uint32_t ah[2][4], bh[4][4], bl[4][4];
            const uint32_t asw = kk ? (aSw ^ 32u) : aSw;
            const uint32_t bsw = kk ? (bSw ^ 32u) : bSw;
#pragma unroll
            for (int mi = 0; mi < 2; mi++)
                ldm4(ah[mi], sb + aBase + (uint32_t)(mi * 1024) + asw + OFF_A);
#pragma unroll
            for (int np = 0; np < 4; np++) {
                uint32_t bo = sb + bBase + (uint32_t)(np * 1024) + bsw;
                ldm4(bh[np], bo + OFF_BH);
                ldm4(bl[np], bo + OFF_BL);
            }
#pragma unroll
            for (int mi = 0; mi < 2; mi++)
#pragma unroll
                for (int ni = 0; ni < 8; ni++)
                    mma16816(acc[mi][ni], ah[mi], bh[ni >> 1][(ni & 1) * 2], bh[ni >> 1][(ni & 1) * 2 + 1]);
#pragma unroll
            for (int mi = 0; mi < 2; mi++)
#pragma unroll
                for (int ni = 0; ni < 8; ni++)
                    mma16816(acc[mi][ni], ah[mi], bl[ni >> 1][(ni & 1) * 2], bl[ni >> 1][(ni & 1) * 2 + 1]);
        }
    }

    const int row_b = m0 + wm * 32 + (lane >> 2);
    const int col_b = n0 + wn * 64 + (lane & 3) * 2;
#pragma unroll
    for (int mi = 0; mi < 2; mi++)
#pragma unroll
        for (int ni = 0; ni < 8; ni++) {
            int row = row_b + mi * 16;
            int col = col_b + ni * 8;
            if (OUT_MODE == 0) {
                *(float2*)&C[(size_t)row * DD + col] =
                    make_float2(acc[mi][ni][0], acc[mi][ni][1]);
                *(float2*)&C[(size_t)(row + 8) * DD + col] =
                    make_float2(acc[mi][ni][2], acc[mi][ni][3]);
            } else {
#pragma unroll
                for (int rh = 0; rh < 2; rh++) {
                    float v0 = acc[mi][ni][rh * 2 + 0] * scale;
                    float v1 = acc[mi][ni][rh * 2 + 1] * scale;
                    size_t off = (size_t)(row + rh * 8) * DD + col;
                    if (OUT_MODE == 2) {
                        *(uint32_t*)&Chi[off] = pack_h2(v0, v1);
                    } else {
                        float r0, r1;
                        uint32_t hp = pack_h2_hi(v0, v1, r0, r1);
                        *(uint32_t*)&Chi[off] = hp;
                        *(uint32_t*)&Clo[off] = pack_h2(r0, r1);
                    }
                }
            }
        }
}

__global__ void __launch_bounds__(256, 2)
gemm_qkv_kernel() {
    if (blockIdx.z == 0) {
        gemm_core<2>(g_x, g_wq_hi, g_wq_lo, nullptr, g_q, nullptr, QSCALE);
    } else if (blockIdx.z == 1) {
        gemm_core<1>(g_x, g_wk_hi, g_wk_lo, nullptr, g_kh, g_kl, 1.0f);
    } else {
        gemm_core<1>(g_x, g_wv_hi, g_wv_lo, nullptr, g_vh, g_vl, 1.0f);
    }
}

__global__ void __launch_bounds__(256, 2)
gemm_out_kernel(float* __restrict__ out) {
    gemm_core<0>(g_oa, g_wo_hi, g_wo_lo, out, nullptr, nullptr, 1.0f);
}

// ---------------- HMMA fp16 flash attention (no-max softmax, 2-pass, 2 CTA/SM) ----------------
// BM=128 (8 warps x 16 rows), BN=64. 128B rows, SW128 swizzle (c' = c ^ (r&7)).
#define QT 16384                     // 128 x 64 fp16 = 128B rows
#define KVT 8192                     // 64 x 64 fp16
#define OFF_Q 0
#define OFF_ST QT                    // 16384
#define STG (4 * KVT)                // 32768
#define ATTN_SMEM (OFF_ST + 2 * STG) // 81920

__device__ __forceinline__ void kv_load(uint32_t stage, size_t gkv, int k0, int tid) {
#pragma unroll
    for (int i = 0; i < 8; i++) {
        int tile = i >> 1;
        int r = (i & 1) * 32 + (tid >> 3);
        int c = tid & 7;
        const __half* src = (tile == 0) ? g_kh : (tile == 1) ? g_kl
                          : (tile == 2) ? g_vh : g_vl;
        cp16(stage + (uint32_t)(tile * KVT + r * 128 + ((c ^ (r & 7)) << 4)),
             src + gkv + (size_t)(k0 + r) * DD + c * 8);
    }
}

__global__ void __launch_bounds__(256, 2)
attn_kernel() {
    extern __shared__ char sm[];
    uint32_t sb = smem_u32(sm);
    const int tid = threadIdx.x;
    const int wid = tid >> 5;
    const int lane = tid & 31;
    const int bh_idx = blockIdx.y;
    const int b = bh_idx >> 4;
    const int h = bh_idx & 15;
    // reversed order: longest blocks (largest q0) launch first
    const int q0 = ((int)gridDim.x - 1 - (int)blockIdx.x) * 128;

    const size_t gq = (size_t)(b * SS + q0) * DD + h * HD;
    const size_t gkv = (size_t)(b * SS) * DD + h * HD;

    // load Q tile (single fp16), swizzled
#pragma unroll
    for (int i = 0; i < 4; i++) {
        int r = i * 32 + (tid >> 3);
        int c = tid & 7;
        cp16(sb + (uint32_t)(OFF_Q + r * 128 + ((c ^ (r & 7)) << 4)),
             g_q + gq + (size_t)r * DD + c * 8);
    }
    kv_load(sb + OFF_ST, gkv, 0, tid);
    CP_COMMIT();
    CP_WAIT(0);
    __syncthreads();

    // Q A-fragments (registers for whole kernel)
    uint32_t qh[4][4];
    {
        const int rQ = 16 * wid + (lane & 15);
        const int tQ = lane >> 4;
        const uint32_t qrow = sb + OFF_Q + (uint32_t)(rQ * 128);
        const int sQ = rQ & 7;
#pragma unroll
        for (int q = 0; q < 4; q++)
            ldm4(qh[q], qrow + (uint32_t)(((tQ + 2 * q) ^ sQ) << 4));
    }

    const int rK = ((lane >> 4) << 3) + (lane & 7);
    const int tK = (lane >> 3) & 1;
    const int sK = rK & 7;
    const uint32_t kBase = (uint32_t)(rK * 128);
    const int rV = lane & 15;
    const int tV = lane >> 4;
    const int sV = rV & 7;
    const uint32_t vBase = (uint32_t)(rV * 128);

    float o[8][4];
#pragma unroll
    for (int nt = 0; nt < 8; nt++)
#pragma unroll
        for (int j = 0; j < 4; j++) o[nt][j] = 0.0f;
    float l0 = 0.0f, l1 = 0.0f;

    const int row0 = q0 + 16 * wid + (lane >> 2);
    const int row_min = q0 + 16 * wid;
    const int qrow_hi = q0 + 16 * wid + 15;
    const int ntiles = q0 / 64 + 2;

    for (int it = 0; it < ntiles; it++) {
        const int k0 = it * 64;
        if (it + 1 < ntiles) {
            kv_load(sb + OFF_ST + ((it + 1) & 1) * STG, gkv, (it + 1) * 64, tid);
            CP_COMMIT();
            CP_WAIT(1);
        } else {
            CP_WAIT(0);
        }
        __syncthreads();

        if (k0 <= qrow_hi) {
            const uint32_t stage = sb + OFF_ST + (it & 1) * STG;

            // ---- S = Q K^T, 2-pass, pair-blocked pass-major ----
            float s[8][4];
#pragma unroll
            for (int nt = 0; nt < 8; nt++)
#pragma unroll
                for (int j = 0; j < 4; j++) s[nt][j] = 0.0f;

#pragma unroll
            for (int q = 0; q < 4; q++) {
                const uint32_t kc = (uint32_t)((((2 * q) + tK) ^ sK) << 4);
#pragma unroll
                for (int pp = 0; pp < 2; pp++) {
                    uint32_t kh4[2][4], kl4[2][4];
#pragma unroll
                    for (int p2 = 0; p2 < 2; p2++) {
                        int p = pp * 2 + p2;
                        uint32_t a = stage + kBase + (uint32_t)(p * 2048) + kc;
                        ldm4(kh4[p2], a);
                        ldm4(kl4[p2], a + KVT);
                    }
#pragma unroll
                    for (int p2 = 0; p2 < 2; p2++) {
                        int p = pp * 2 + p2;
                        mma16816(s[2 * p], qh[q], kh4[p2][0], kh4[p2][1]);
                        mma16816(s[2 * p + 1], qh[q], kh4[p2][2], kh4[p2][3]);
                    }
#pragma unroll
                    for (int p2 = 0; p2 < 2; p2++) {
                        int p = pp * 2 + p2;
                        mma16816(s[2 * p], qh[q], kl4[p2][0], kl4[p2][1]);
                        mma16816(s[2 * p + 1], qh[q], kl4[p2][2], kl4[p2][3]);
                    }
                }
            }

            // ---- causal mask ----
            if (k0 + 63 > row_min) {
#pragma unroll
                for (int nt = 0; nt < 8; nt++) {
                    int key = k0 + nt * 8 + (lane & 3) * 2;
#pragma unroll
                    for (int j = 0; j < 4; j++) {
                        int r = row0 + (j >> 1) * 8;
                        if (key + (j & 1) > r) s[nt][j] = -1e30f;
                    }
                }
            }

            // ---- no-max softmax: P = 2^s ----
#pragma unroll
            for (int nt = 0; nt < 8; nt++) {
                s[nt][0] = ex2f(s[nt][0]);
                s[nt][1] = ex2f(s[nt][1]);
                s[nt][2] = ex2f(s[nt][2]);
                s[nt][3] = ex2f(s[nt][3]);
                l0 += s[nt][0] + s[nt][1];
                l1 += s[nt][2] + s[nt][3];
            }

            // ---- PV, 2-pass (P single fp16), pair-blocked ----
#pragma unroll
            for (int kk = 0; kk < 4; kk++) {
                uint32_t pah[4];
                pah[0] = pack_h2(s[2 * kk][0], s[2 * kk][1]);
                pah[1] = pack_h2(s[2 * kk][2], s[2 * kk][3]);
                pah[2] = pack_h2(s[2 * kk + 1][0], s[2 * kk + 1][1]);
                pah[3] = pack_h2(s[2 * kk + 1][2], s[2 * kk + 1][3]);
                const uint32_t vrow = stage + 2 * KVT + vBase + (uint32_t)(kk * 2048);
#pragma unroll
                for (int uu = 0; uu < 2; uu++) {
                    uint32_t vh4[2][4], vl4[2][4];
#pragma unroll
                    for (int u2 = 0; u2 < 2; u2++) {
                        int u = uu * 2 + u2;
                        uint32_t a = vrow + (uint32_t)((((2 * u) + tV) ^ sV) << 4);
                        ldm4t(vh4[u2], a);
                        ldm4t(vl4[u2], a + KVT);
                    }
#pragma unroll
                    for (int u2 = 0; u2 < 2; u2++) {
                        int u = uu * 2 + u2;
                        mma16816(o[2 * u], pah, vh4[u2][0], vh4[u2][1]);
                        mma16816(o[2 * u + 1], pah, vh4[u2][2], vh4[u2][3]);
                    }
#pragma unroll
                    for (int u2 = 0; u2 < 2; u2++) {
                        int u = uu * 2 + u2;
                        mma16816(o[2 * u], pah, vl4[u2][0], vl4[u2][1]);
                        mma16816(o[2 * u + 1], pah, vl4[u2][2], vl4[u2][3]);
                    }
                }
            }
        }
        __syncthreads();
    }

    // ---- finalize: normalize, single fp16 out ----
    l0 += __shfl_xor_sync(0xffffffffu, l0, 1);
    l0 += __shfl_xor_sync(0xffffffffu, l0, 2);
    l1 += __shfl_xor_sync(0xffffffffu, l1, 1);
    l1 += __shfl_xor_sync(0xffffffffu, l1, 2);
    float inv0 = 1.0f / l0;
    float inv1 = 1.0f / l1;

    const int grow0 = b * SS + q0 + 16 * wid + (lane >> 2);
    const int gcol = h * HD + (lane & 3) * 2;
#pragma unroll
    for (int nt = 0; nt < 8; nt++) {
#pragma unroll
        for (int rh = 0; rh < 2; rh++) {
            float inv = rh ? inv1 : inv0;
            float v0 = o[nt][rh * 2 + 0] * inv;
            float v1 = o[nt][rh * 2 + 1] * inv;
            size_t off = (size_t)(grow0 + rh * 8) * DD + gcol + nt * 8;
            *(uint32_t*)&g_oa[off] = pack_h2(v0, v1);
        }
    }
}

// ---------------- launch ----------------
extern "C" void kernel_launch(void* const* d_in, const int* in_sizes, int n_in,
                              void* d_out, int out_size) {
    const float* x  = (const float*)d_in[0];
    const float* Wq = (const float*)d_in[1];
    const float* Wk = (const float*)d_in[2];
    const float* Wv = (const float*)d_in[3];
    const float* Wo = (const float*)d_in[4];
    float* out = (float*)d_out;

    cudaFuncSetAttribute(attn_kernel,
                         cudaFuncAttributeMaxDynamicSharedMemorySize, ATTN_SMEM);
    cudaFuncSetAttribute(gemm_qkv_kernel,
                         cudaFuncAttributeMaxDynamicSharedMemorySize, GSMEM_TOTAL);
    cudaFuncSetAttribute(gemm_out_kernel,
                         cudaFuncAttributeMaxDynamicSharedMemorySize, GSMEM_TOTAL);

    __half *p_x, *p_wohi, *p_wolo;
    cudaGetSymbolAddress((void**)&p_x, g_x);
    cudaGetSymbolAddress((void**)&p_wohi, g_wo_hi);
    cudaGetSymbolAddress((void**)&p_wolo, g_wo_lo);

    convert_half_kernel<<<(MM * DD / 4 + 255) / 256, 256>>>(x, p_x, MM * DD / 4);
    split_half_kernel<<<(DD * DD / 4 + 255) / 256, 256>>>(Wo, p_wohi, p_wolo, DD * DD / 4);
    transpose_split_kernel<<<dim3(32, 32, 3), 256>>>(Wq, Wk, Wv);

    dim3 gq(DD / 128, MM / 128, 3);       // (8, 64, 3)
    gemm_qkv_kernel<<<gq, 256, GSMEM_TOTAL>>>();

    dim3 ga(SS / 128, BB * HH);           // (16, 64)
    attn_kernel<<<ga, 256, ATTN_SMEM>>>();

    dim3 go(DD / 128, MM / 128, 1);       // (8, 64)
    gemm_out_kernel<<<go, 256, GSMEM_TOTAL>>>(out);
}

// round 11
// speedup vs baseline: 4.5307x; 1.1161x over previous
#include <cuda_runtime.h>
#include <cuda_fp16.h>
#include <cstdint>

// Problem constants
#define BB 4
#define SS 2048
#define DD 1024
#define HH 16
#define HD 64
#define MM (BB * SS)   // 8192 rows

// ---------------- scratch (device globals; allocation-free rule) ----------------
__device__ __half g_q[MM * DD];       // Q single fp16, pre-scaled by 0.125*log2e
__device__ __half g_kh[MM * DD];
__device__ __half g_kl[MM * DD];
__device__ __half g_vh[MM * DD];      // V single fp16
__device__ __half g_x[MM * DD];
__device__ __half g_oa[MM * DD];

__device__ __half g_wq_hi[DD * DD];
__device__ __half g_wq_lo[DD * DD];
__device__ __half g_wk_hi[DD * DD];
__device__ __half g_wk_lo[DD * DD];
__device__ __half g_wv_hi[DD * DD];
__device__ __half g_wv_lo[DD * DD];
__device__ __half g_wo_hi[DD * DD];
__device__ __half g_wo_lo[DD * DD];

#define QSCALE (0.125f * 1.4426950408889634f)

// ---------------- PTX helpers ----------------
__device__ __forceinline__ uint32_t smem_u32(const void* p) {
    uint32_t a;
    asm("{ .reg .u64 t; cvta.to.shared.u64 t, %1; cvt.u32.u64 %0, t; }" : "=r"(a) : "l"(p));
    return a;
}
__device__ __forceinline__ void cp16(uint32_t dst, const void* src) {
    asm volatile("cp.async.cg.shared.global [%0], [%1], 16;" :: "r"(dst), "l"(src) : "memory");
}
#define CP_COMMIT() asm volatile("cp.async.commit_group;" ::: "memory")
#define CP_WAIT(n) asm volatile("cp.async.wait_group %0;" :: "n"(n) : "memory")

__device__ __forceinline__ void ldm4(uint32_t* d, uint32_t addr) {
    asm volatile("ldmatrix.sync.aligned.m8n8.x4.shared.b16 {%0,%1,%2,%3}, [%4];"
                 : "=r"(d[0]), "=r"(d[1]), "=r"(d[2]), "=r"(d[3]) : "r"(addr));
}
__device__ __forceinline__ void ldm4t(uint32_t* d, uint32_t addr) {
    asm volatile("ldmatrix.sync.aligned.m8n8.x4.trans.shared.b16 {%0,%1,%2,%3}, [%4];"
                 : "=r"(d[0]), "=r"(d[1]), "=r"(d[2]), "=r"(d[3]) : "r"(addr));
}
__device__ __forceinline__ void mma16816(float* c, const uint32_t* a, uint32_t b0, uint32_t b1) {
    asm volatile(
        "mma.sync.aligned.m16n8k16.row.col.f32.f16.f16.f32 "
        "{%0,%1,%2,%3}, {%4,%5,%6,%7}, {%8,%9}, {%0,%1,%2,%3};"
        : "+f"(c[0]), "+f"(c[1]), "+f"(c[2]), "+f"(c[3])
        : "r"(a[0]), "r"(a[1]), "r"(a[2]), "r"(a[3]), "r"(b0), "r"(b1));
}
__device__ __forceinline__ float ex2f(float x) {
    float r;
    asm("ex2.approx.f32 %0, %1;" : "=f"(r) : "f"(x));
    return r;
}
__device__ __forceinline__ uint32_t pack_h2(float x, float y) {
    __half2 h = __floats2half2_rn(x, y);
    return *(uint32_t*)&h;
}
__device__ __forceinline__ uint32_t pack_h2_hi(float x, float y, float& rx, float& ry) {
    __half2 h = __floats2half2_rn(x, y);
    float2 f = __half22float2(h);
    rx = x - f.x;
    ry = y - f.y;
    return *(uint32_t*)&h;
}

// ---------------- prep kernels ----------------
__global__ void __launch_bounds__(256)
convert_half_kernel(const float* __restrict__ src, __half* __restrict__ dst, int n4) {
    int i = blockIdx.x * 256 + threadIdx.x;
    if (i >= n4) return;
    float4 v = ((const float4*)src)[i];
    ushort4 o;
    o.x = __half_as_ushort(__float2half_rn(v.x));
    o.y = __half_as_ushort(__float2half_rn(v.y));
    o.z = __half_as_ushort(__float2half_rn(v.z));
    o.w = __half_as_ushort(__float2half_rn(v.w));
    ((ushort4*)dst)[i] = o;
}

__global__ void __launch_bounds__(256)
split_half_kernel(const float* __restrict__ src, __half* __restrict__ hi,
                  __half* __restrict__ lo, int n4) {
    int i = blockIdx.x * 256 + threadIdx.x;
    if (i >= n4) return;
    float4 v = ((const float4*)src)[i];
    __half h0 = __float2half_rn(v.x), h1 = __float2half_rn(v.y);
    __half h2 = __float2half_rn(v.z), h3 = __float2half_rn(v.w);
    ushort4 hv, lv;
    hv.x = __half_as_ushort(h0); hv.y = __half_as_ushort(h1);
    hv.z = __half_as_ushort(h2); hv.w = __half_as_ushort(h3);
    lv.x = __half_as_ushort(__float2half_rn(v.x - __half2float(h0)));
    lv.y = __half_as_ushort(__float2half_rn(v.y - __half2float(h1)));
    lv.z = __half_as_ushort(__float2half_rn(v.z - __half2float(h2)));
    lv.w = __half_as_ushort(__float2half_rn(v.w - __half2float(h3)));
    ((ushort4*)hi)[i] = hv;
    ((ushort4*)lo)[i] = lv;
}

__global__ void __launch_bounds__(256)
transpose_split_kernel(const float* __restrict__ Wq, const float* __restrict__ Wk,
                       const float* __restrict__ Wv) {
    const float* W = (blockIdx.z == 0) ? Wq : ((blockIdx.z == 1) ? Wk : Wv);
    __half* hi = (blockIdx.z == 0) ? g_wq_hi : ((blockIdx.z == 1) ? g_wk_hi : g_wv_hi);
    __half* lo = (blockIdx.z == 0) ? g_wq_lo : ((blockIdx.z == 1) ? g_wk_lo : g_wv_lo);
    __shared__ float t[32][33];
    int tx = threadIdx.x & 31;
    int ty = threadIdx.x >> 5;
    int k0 = blockIdx.y * 32;
    int n0 = blockIdx.x * 32;
#pragma unroll
    for (int i = 0; i < 4; i++)
        t[ty + i * 8][tx] = W[(size_t)(k0 + ty + i * 8) * DD + n0 + tx];
    __syncthreads();
#pragma unroll
    for (int i = 0; i < 4; i++) {
        int n = n0 + ty + i * 8;
        int k = k0 + tx;
        float v = t[tx][ty + i * 8];
        __half h = __float2half_rn(v);
        hi[(size_t)n * DD + k] = h;
        lo[(size_t)n * DD + k] = __float2half_rn(v - __half2float(h));
    }
}

// ---------------- HMMA fp16 2-pass GEMM (swizzled, 4-stage) ----------------
#define BK 32
#define MAT 8192                     // 128 rows x 64B (32 fp16)
#define OFF_A 0
#define OFF_BH (1 * MAT)
#define OFF_BL (2 * MAT)
#define STAGE_BYTES (3 * MAT)        // 24576
#define NPIPE 4
#define GSMEM_TOTAL (NPIPE * STAGE_BYTES)  // 98304

__device__ __forceinline__ void load_stage(uint32_t sb,
                                           const __half* __restrict__ A,
                                           const __half* __restrict__ Bh,
                                           const __half* __restrict__ Bl,
                                           int m0, int n0, int kt, int tid) {
#pragma unroll
    for (int i = 0; i < 2; i++) {
        int idx = tid + i * 256;
        int r = idx >> 2;
        int c = idx & 3;
        uint32_t so = (uint32_t)(r * 64 + ((c ^ ((r >> 1) & 3)) << 4));
        size_t goA = (size_t)(m0 + r) * DD + kt + c * 8;
        size_t goB = (size_t)(n0 + r) * DD + kt + c * 8;
        cp16(sb + OFF_A + so, A + goA);
        cp16(sb + OFF_BH + so, Bh + goB);
        cp16(sb + OFF_BL + so, Bl + goB);
    }
}

// OUT_MODE 0: fp32 C.  OUT_MODE 1: split hi/lo fp16 (scale).  OUT_MODE 2: single fp16 (scale).
template <int OUT_MODE>
__device__ __forceinline__ void gemm_core(const __half* __restrict__ A,
                                          const __half* __restrict__ Bh,
                                          const __half* __restrict__ Bl,
                                          float* __restrict__ C,
                                          __half* __restrict__ Chi,
                                          __half* __restrict__ Clo,
                                          float scale) {
    extern __shared__ char sm[];
    uint32_t sbase = smem_u32(sm);
    const int tid = threadIdx.x;
    const int wid = tid >> 5;
    const int lane = tid & 31;
    const int wm = wid & 3;
    const int wn = wid >> 2;
    const int m0 = blockIdx.y * 128;
    const int n0 = blockIdx.x * 128;

    const int g = lane >> 3;
    const int rr = lane & 7;
    const int rA = wm * 32 + (g & 1) * 8 + rr;
    const uint32_t aBase = (uint32_t)(rA * 64);
    const uint32_t aSw = (uint32_t)((((g >> 1) ^ ((rA >> 1) & 3)) << 4));
    const int rB = wn * 64 + (g >> 1) * 8 + rr;
    const uint32_t bBase = (uint32_t)(rB * 64);
    const uint32_t bSw = (uint32_t)((((g & 1) ^ ((rB >> 1) & 3)) << 4));

    float acc[2][8][4];
#pragma unroll
    for (int mi = 0; mi < 2; mi++)
#pragma unroll
        for (int ni = 0; ni < 8; ni++)
#pragma unroll
            for (int j = 0; j < 4; j++) acc[mi][ni][j] = 0.0f;

    const int NST = DD / BK;   // 32
    load_stage(sbase + 0 * STAGE_BYTES, A, Bh, Bl, m0, n0, 0, tid);
    CP_COMMIT();
    load_stage(sbase + 1 * STAGE_BYTES, A, Bh, Bl, m0, n0, BK, tid);
    CP_COMMIT();
    load_stage(sbase + 2 * STAGE_BYTES, A, Bh, Bl, m0, n0, 2 * BK, tid);
    CP_COMMIT();

    for (int s = 0; s < NST; s++) {
        if (s < NST - 2)      { CP_WAIT(2); }
        else if (s == NST - 2){ CP_WAIT(1); }
        else                  { CP_WAIT(0); }
        __syncthreads();
        if (s + 3 < NST) {
            load_stage(sbase + ((s + 3) & 3) * STAGE_BYTES, A, Bh, Bl, m0, n0, (s + 3) * BK, tid);
            CP_COMMIT();
        }
        uint32_t sb = sbase + (s & 3) * STAGE_BYTES;

#pragma unroll
        for (int kk = 0; kk < 2; kk++) {
            uint32_t ah[2][4], bf[4][4];
            const uint32_t asw = kk ? (aSw ^ 32u) : aSw;
            const uint32_t bsw = kk ? (bSw ^ 32u) : bSw;
#pragma unroll
            for (int mi = 0; mi < 2; mi++)
                ldm4(ah[mi], sb + aBase + (uint32_t)(mi * 1024) + asw + OFF_A);
            // pass 1: Bh (bf live only within the pass -> lower peak regs)
#pragma unroll
            for (int np = 0; np < 4; np++)
                ldm4(bf[np], sb + bBase + (uint32_t)(np * 1024) + bsw + OFF_BH);
#pragma unroll
            for (int mi = 0; mi < 2; mi++)
#pragma unroll
                for (int ni = 0; ni < 8; ni++)
                    mma16816(acc[mi][ni], ah[mi], bf[ni >> 1][(ni & 1) * 2], bf[ni >> 1][(ni & 1) * 2 + 1]);
            // pass 2: Bl
#pragma unroll
            for (int np = 0; np < 4; np++)
                ldm4(bf[np], sb + bBase + (uint32_t)(np * 1024) + bsw + OFF_BL);
#pragma unroll
            for (int mi = 0; mi < 2; mi++)
#pragma unroll
                for (int ni = 0; ni < 8; ni++)
                    mma16816(acc[mi][ni], ah[mi], bf[ni >> 1][(ni & 1) * 2], bf[ni >> 1][(ni & 1) * 2 + 1]);
        }
    }

    const int row_b = m0 + wm * 32 + (lane >> 2);
    const int col_b = n0 + wn * 64 + (lane & 3) * 2;
#pragma unroll
    for (int mi = 0; mi < 2; mi++)
#pragma unroll
        for (int ni = 0; ni < 8; ni++) {
            int row = row_b + mi * 16;
            int col = col_b + ni * 8;
            if (OUT_MODE == 0) {
                *(float2*)&C[(size_t)row * DD + col] =
                    make_float2(acc[mi][ni][0], acc[mi][ni][1]);
                *(float2*)&C[(size_t)(row + 8) * DD + col] =
                    make_float2(acc[mi][ni][2], acc[mi][ni][3]);
            } else {
#pragma unroll
                for (int rh = 0; rh < 2; rh++) {
                    float v0 = acc[mi][ni][rh * 2 + 0] * scale;
                    float v1 = acc[mi][ni][rh * 2 + 1] * scale;
                    size_t off = (size_t)(row + rh * 8) * DD + col;
                    if (OUT_MODE == 2) {
                        *(uint32_t*)&Chi[off] = pack_h2(v0, v1);
                    } else {
                        float r0, r1;
                        uint32_t hp = pack_h2_hi(v0, v1, r0, r1);
                        *(uint32_t*)&Chi[off] = hp;
                        *(uint32_t*)&Clo[off] = pack_h2(r0, r1);
                    }
                }
            }
        }
}

__global__ void __launch_bounds__(256, 2)
gemm_qkv_kernel() {
    if (blockIdx.z == 0) {
        gemm_core<2>(g_x, g_wq_hi, g_wq_lo, nullptr, g_q, nullptr, QSCALE);
    } else if (blockIdx.z == 1) {
        gemm_core<1>(g_x, g_wk_hi, g_wk_lo, nullptr, g_kh, g_kl, 1.0f);
    } else {
        gemm_core<2>(g_x, g_wv_hi, g_wv_lo, nullptr, g_vh, nullptr, 1.0f);
    }
}

__global__ void __launch_bounds__(256, 2)
gemm_out_kernel(float* __restrict__ out) {
    gemm_core<0>(g_oa, g_wo_hi, g_wo_lo, out, nullptr, nullptr, 1.0f);
}

// ---------------- HMMA fp16 flash attention ----------------
// BM=128 (8 warps x 16 rows), BN=64. QK^T 2-pass (K split), PV 1-pass (V single).
#define QT 16384                     // 128 x 64 fp16 = 128B rows
#define KVT 8192                     // 64 x 64 fp16
#define OFF_Q 0
#define OFF_ST QT                    // 16384
#define STG (3 * KVT)                // 24576 (kh, kl, vh)
#define ATTN_SMEM (OFF_ST + 2 * STG) // 65536

__device__ __forceinline__ void kv_load(uint32_t stage, size_t gkv, int k0, int tid) {
#pragma unroll
    for (int i = 0; i < 6; i++) {
        int tile = i >> 1;
        int r = (i & 1) * 32 + (tid >> 3);
        int c = tid & 7;
        const __half* src = (tile == 0) ? g_kh : (tile == 1) ? g_kl : g_vh;
        cp16(stage + (uint32_t)(tile * KVT + r * 128 + ((c ^ (r & 7)) << 4)),
             src + gkv + (size_t)(k0 + r) * DD + c * 8);
    }
}

__global__ void __launch_bounds__(256, 2)
attn_kernel() {
    extern __shared__ char sm[];
    uint32_t sb = smem_u32(sm);
    const int tid = threadIdx.x;
    const int wid = tid >> 5;
    const int lane = tid & 31;
    const int bh_idx = blockIdx.y;
    const int b = bh_idx >> 4;
    const int h = bh_idx & 15;
    const int q0 = ((int)gridDim.x - 1 - (int)blockIdx.x) * 128;

    const size_t gq = (size_t)(b * SS + q0) * DD + h * HD;
    const size_t gkv = (size_t)(b * SS) * DD + h * HD;

    // load Q tile (single fp16), swizzled
#pragma unroll
    for (int i = 0; i < 4; i++) {
        int r = i * 32 + (tid >> 3);
        int c = tid & 7;
        cp16(sb + (uint32_t)(OFF_Q + r * 128 + ((c ^ (r & 7)) << 4)),
             g_q + gq + (size_t)r * DD + c * 8);
    }
    kv_load(sb + OFF_ST, gkv, 0, tid);
    CP_COMMIT();
    CP_WAIT(0);
    __syncthreads();

    // Q A-fragments
    uint32_t qh[4][4];
    {
        const int rQ = 16 * wid + (lane & 15);
        const int tQ = lane >> 4;
        const uint32_t qrow = sb + OFF_Q + (uint32_t)(rQ * 128);
        const int sQ = rQ & 7;
#pragma unroll
        for (int q = 0; q < 4; q++)
            ldm4(qh[q], qrow + (uint32_t)(((tQ + 2 * q) ^ sQ) << 4));
    }

    const int rK = ((lane >> 4) << 3) + (lane & 7);
    const int tK = (lane >> 3) & 1;
    const int sK = rK & 7;
    const uint32_t kBase = (uint32_t)(rK * 128);
    const int rV = lane & 15;
    const int tV = lane >> 4;
    const int sV = rV & 7;
    const uint32_t vBase = (uint32_t)(rV * 128);

    float o[8][4];
#pragma unroll
    for (int nt = 0; nt < 8; nt++)
#pragma unroll
        for (int j = 0; j < 4; j++) o[nt][j] = 0.0f;
    float l0 = 0.0f, l1 = 0.0f;

    const int row0 = q0 + 16 * wid + (lane >> 2);
    const int row_min = q0 + 16 * wid;
    const int qrow_hi = q0 + 16 * wid + 15;
    const int ntiles = q0 / 64 + 2;

    for (int it = 0; it < ntiles; it++) {
        const int k0 = it * 64;
        if (it + 1 < ntiles) {
            kv_load(sb + OFF_ST + ((it + 1) & 1) * STG, gkv, (it + 1) * 64, tid);
            CP_COMMIT();
            CP_WAIT(1);
        } else {
            CP_WAIT(0);
        }
        __syncthreads();

        if (k0 <= qrow_hi) {
            const uint32_t stage = sb + OFF_ST + (it & 1) * STG;

            // ---- S = Q K^T, 2-pass (sequential kh then kl liveness) ----
            float s[8][4];
#pragma unroll
            for (int nt = 0; nt < 8; nt++)
#pragma unroll
                for (int j = 0; j < 4; j++) s[nt][j] = 0.0f;

#pragma unroll
            for (int q = 0; q < 4; q++) {
                const uint32_t kc = (uint32_t)((((2 * q) + tK) ^ sK) << 4);
#pragma unroll
                for (int pp = 0; pp < 2; pp++) {
                    uint32_t kf[2][4];
#pragma unroll
                    for (int p2 = 0; p2 < 2; p2++)
                        ldm4(kf[p2], stage + kBase + (uint32_t)((pp * 2 + p2) * 2048) + kc);
#pragma unroll
                    for (int p2 = 0; p2 < 2; p2++) {
                        int p = pp * 2 + p2;
                        mma16816(s[2 * p], qh[q], kf[p2][0], kf[p2][1]);
                        mma16816(s[2 * p + 1], qh[q], kf[p2][2], kf[p2][3]);
                    }
#pragma unroll
                    for (int p2 = 0; p2 < 2; p2++)
                        ldm4(kf[p2], stage + KVT + kBase + (uint32_t)((pp * 2 + p2) * 2048) + kc);
#pragma unroll
                    for (int p2 = 0; p2 < 2; p2++) {
                        int p = pp * 2 + p2;
                        mma16816(s[2 * p], qh[q], kf[p2][0], kf[p2][1]);
                        mma16816(s[2 * p + 1], qh[q], kf[p2][2], kf[p2][3]);
                    }
                }
            }

            // ---- causal mask ----
            if (k0 + 63 > row_min) {
#pragma unroll
                for (int nt = 0; nt < 8; nt++) {
                    int key = k0 + nt * 8 + (lane & 3) * 2;
#pragma unroll
                    for (int j = 0; j < 4; j++) {
                        int r = row0 + (j >> 1) * 8;
                        if (key + (j & 1) > r) s[nt][j] = -1e30f;
                    }
                }
            }

            // ---- no-max softmax: P = 2^s ----
#pragma unroll
            for (int nt = 0; nt < 8; nt++) {
                s[nt][0] = ex2f(s[nt][0]);
                s[nt][1] = ex2f(s[nt][1]);
                s[nt][2] = ex2f(s[nt][2]);
                s[nt][3] = ex2f(s[nt][3]);
                l0 += s[nt][0] + s[nt][1];
                l1 += s[nt][2] + s[nt][3];
            }

            // ---- PV, single pass (V single fp16) ----
#pragma unroll
            for (int kk = 0; kk < 4; kk++) {
                uint32_t pah[4];
                pah[0] = pack_h2(s[2 * kk][0], s[2 * kk][1]);
                pah[1] = pack_h2(s[2 * kk][2], s[2 * kk][3]);
                pah[2] = pack_h2(s[2 * kk + 1][0], s[2 * kk + 1][1]);
                pah[3] = pack_h2(s[2 * kk + 1][2], s[2 * kk + 1][3]);
                const uint32_t vrow = stage + 2 * KVT + vBase + (uint32_t)(kk * 2048);
#pragma unroll
                for (int uu = 0; uu < 2; uu++) {
                    uint32_t vf[2][4];
#pragma unroll
                    for (int u2 = 0; u2 < 2; u2++)
                        ldm4t(vf[u2], vrow + (uint32_t)((((2 * (uu * 2 + u2)) + tV) ^ sV) << 4));
#pragma unroll
                    for (int u2 = 0; u2 < 2; u2++) {
                        int u = uu * 2 + u2;
                        mma16816(o[2 * u], pah, vf[u2][0], vf[u2][1]);
                        mma16816(o[2 * u + 1], pah, vf[u2][2], vf[u2][3]);
                    }
                }
            }
        }
        __syncthreads();
    }

    // ---- finalize: normalize, single fp16 out ----
    l0 += __shfl_xor_sync(0xffffffffu, l0, 1);
    l0 += __shfl_xor_sync(0xffffffffu, l0, 2);
    l1 += __shfl_xor_sync(0xffffffffu, l1, 1);
    l1 += __shfl_xor_sync(0xffffffffu, l1, 2);
    float inv0 = 1.0f / l0;
    float inv1 = 1.0f / l1;

    const int grow0 = b * SS + q0 + 16 * wid + (lane >> 2);
    const int gcol = h * HD + (lane & 3) * 2;
#pragma unroll
    for (int nt = 0; nt < 8; nt++) {
#pragma unroll
        for (int rh = 0; rh < 2; rh++) {
            float inv = rh ? inv1 : inv0;
            float v0 = o[nt][rh * 2 + 0] * inv;
            float v1 = o[nt][rh * 2 + 1] * inv;
            size_t off = (size_t)(grow0 + rh * 8) * DD + gcol + nt * 8;
            *(uint32_t*)&g_oa[off] = pack_h2(v0, v1);
        }
    }
}

// ---------------- launch ----------------
extern "C" void kernel_launch(void* const* d_in, const int* in_sizes, int n_in,
                              void* d_out, int out_size) {
    const float* x  = (const float*)d_in[0];
    const float* Wq = (const float*)d_in[1];
    const float* Wk = (const float*)d_in[2];
    const float* Wv = (const float*)d_in[3];
    const float* Wo = (const float*)d_in[4];
    float* out = (float*)d_out;

    cudaFuncSetAttribute(attn_kernel,
                         cudaFuncAttributeMaxDynamicSharedMemorySize, ATTN_SMEM);
    cudaFuncSetAttribute(gemm_qkv_kernel,
                         cudaFuncAttributeMaxDynamicSharedMemorySize, GSMEM_TOTAL);
    cudaFuncSetAttribute(gemm_out_kernel,
                         cudaFuncAttributeMaxDynamicSharedMemorySize, GSMEM_TOTAL);

    __half *p_x, *p_wohi, *p_wolo;
    cudaGetSymbolAddress((void**)&p_x, g_x);
    cudaGetSymbolAddress((void**)&p_wohi, g_wo_hi);
    cudaGetSymbolAddress((void**)&p_wolo, g_wo_lo);

    convert_half_kernel<<<(MM * DD / 4 + 255) / 256, 256>>>(x, p_x, MM * DD / 4);
    split_half_kernel<<<(DD * DD / 4 + 255) / 256, 256>>>(Wo, p_wohi, p_wolo, DD * DD / 4);
    transpose_split_kernel<<<dim3(32, 32, 3), 256>>>(Wq, Wk, Wv);

    dim3 gq(DD / 128, MM / 128, 3);       // (8, 64, 3)
    gemm_qkv_kernel<<<gq, 256, GSMEM_TOTAL>>>();

    dim3 ga(SS / 128, BB * HH);           // (16, 64)
    attn_kernel<<<ga, 256, ATTN_SMEM>>>();

    dim3 go(DD / 128, MM / 128, 1);       // (8, 64)
    gemm_out_kernel<<<go, 256, GSMEM_TOTAL>>>(out);
}

// round 12
// speedup vs baseline: 6.9645x; 1.5372x over previous
#include <cuda_runtime.h>
#include <cuda_fp16.h>
#include <cstdint>

// Problem constants
#define BB 4
#define SS 2048
#define DD 1024
#define HH 16
#define HD 64
#define MM (BB * SS)   // 8192 rows

// ---------------- scratch (device globals; allocation-free rule) ----------------
__device__ __half g_q[MM * DD];       // Q fp16, pre-scaled by 0.125*log2e
__device__ __half g_k[MM * DD];
__device__ __half g_v[MM * DD];
__device__ __half g_x[MM * DD];
__device__ __half g_oa[MM * DD];

__device__ __half g_wq[DD * DD];      // transposed [n][k]
__device__ __half g_wk[DD * DD];
__device__ __half g_wv[DD * DD];
__device__ __half g_wo[DD * DD];      // row-major Wo == [n][k]

#define QSCALE (0.125f * 1.4426950408889634f)

// ---------------- PTX helpers ----------------
__device__ __forceinline__ uint32_t smem_u32(const void* p) {
    uint32_t a;
    asm("{ .reg .u64 t; cvta.to.shared.u64 t, %1; cvt.u32.u64 %0, t; }" : "=r"(a) : "l"(p));
    return a;
}
__device__ __forceinline__ void cp16(uint32_t dst, const void* src) {
    asm volatile("cp.async.cg.shared.global [%0], [%1], 16;" :: "r"(dst), "l"(src) : "memory");
}
#define CP_COMMIT() asm volatile("cp.async.commit_group;" ::: "memory")
#define CP_WAIT(n) asm volatile("cp.async.wait_group %0;" :: "n"(n) : "memory")

__device__ __forceinline__ void ldm4(uint32_t* d, uint32_t addr) {
    asm volatile("ldmatrix.sync.aligned.m8n8.x4.shared.b16 {%0,%1,%2,%3}, [%4];"
                 : "=r"(d[0]), "=r"(d[1]), "=r"(d[2]), "=r"(d[3]) : "r"(addr));
}
__device__ __forceinline__ void ldm4t(uint32_t* d, uint32_t addr) {
    asm volatile("ldmatrix.sync.aligned.m8n8.x4.trans.shared.b16 {%0,%1,%2,%3}, [%4];"
                 : "=r"(d[0]), "=r"(d[1]), "=r"(d[2]), "=r"(d[3]) : "r"(addr));
}
__device__ __forceinline__ void mma16816(float* c, const uint32_t* a, uint32_t b0, uint32_t b1) {
    asm volatile(
        "mma.sync.aligned.m16n8k16.row.col.f32.f16.f16.f32 "
        "{%0,%1,%2,%3}, {%4,%5,%6,%7}, {%8,%9}, {%0,%1,%2,%3};"
        : "+f"(c[0]), "+f"(c[1]), "+f"(c[2]), "+f"(c[3])
        : "r"(a[0]), "r"(a[1]), "r"(a[2]), "r"(a[3]), "r"(b0), "r"(b1));
}
__device__ __forceinline__ float ex2f(float x) {
    float r;
    asm("ex2.approx.f32 %0, %1;" : "=f"(r) : "f"(x));
    return r;
}
__device__ __forceinline__ uint32_t pack_h2(float x, float y) {
    __half2 h = __floats2half2_rn(x, y);
    return *(uint32_t*)&h;
}

// ---------------- prep kernels ----------------
__global__ void __launch_bounds__(256)
convert_half_kernel(const float* __restrict__ src, __half* __restrict__ dst, int n4) {
    int i = blockIdx.x * 256 + threadIdx.x;
    if (i >= n4) return;
    float4 v = ((const float4*)src)[i];
    ushort4 o;
    o.x = __half_as_ushort(__float2half_rn(v.x));
    o.y = __half_as_ushort(__float2half_rn(v.y));
    o.z = __half_as_ushort(__float2half_rn(v.z));
    o.w = __half_as_ushort(__float2half_rn(v.w));
    ((ushort4*)dst)[i] = o;
}

__global__ void __launch_bounds__(256)
transpose_convert_kernel(const float* __restrict__ Wq, const float* __restrict__ Wk,
                         const float* __restrict__ Wv) {
    const float* W = (blockIdx.z == 0) ? Wq : ((blockIdx.z == 1) ? Wk : Wv);
    __half* dst = (blockIdx.z == 0) ? g_wq : ((blockIdx.z == 1) ? g_wk : g_wv);
    __shared__ float t[32][33];
    int tx = threadIdx.x & 31;
    int ty = threadIdx.x >> 5;
    int k0 = blockIdx.y * 32;
    int n0 = blockIdx.x * 32;
#pragma unroll
    for (int i = 0; i < 4; i++)
        t[ty + i * 8][tx] = W[(size_t)(k0 + ty + i * 8) * DD + n0 + tx];
    __syncthreads();
#pragma unroll
    for (int i = 0; i < 4; i++) {
        int n = n0 + ty + i * 8;
        int k = k0 + tx;
        dst[(size_t)n * DD + k] = __float2half_rn(t[tx][ty + i * 8]);
    }
}

// ---------------- HMMA fp16 1-pass GEMM (swizzled, 4-stage) ----------------
#define BK 32
#define MAT 8192                     // 128 rows x 64B (32 fp16)
#define OFF_A 0
#define OFF_B (1 * MAT)
#define STAGE_BYTES (2 * MAT)        // 16384
#define NPIPE 4
#define GSMEM_TOTAL (NPIPE * STAGE_BYTES)  // 65536

__device__ __forceinline__ void load_stage(uint32_t sb,
                                           const __half* __restrict__ A,
                                           const __half* __restrict__ B,
                                           int m0, int n0, int kt, int tid) {
#pragma unroll
    for (int i = 0; i < 2; i++) {
        int idx = tid + i * 256;
        int r = idx >> 2;
        int c = idx & 3;
        uint32_t so = (uint32_t)(r * 64 + ((c ^ ((r >> 1) & 3)) << 4));
        cp16(sb + OFF_A + so, A + (size_t)(m0 + r) * DD + kt + c * 8);
        cp16(sb + OFF_B + so, B + (size_t)(n0 + r) * DD + kt + c * 8);
    }
}

// OUT_MODE 0: fp32 C.  OUT_MODE 2: single fp16 (scale).
template <int OUT_MODE>
__device__ __forceinline__ void gemm_core(const __half* __restrict__ A,
                                          const __half* __restrict__ B,
                                          float* __restrict__ C,
                                          __half* __restrict__ Ch,
                                          float scale) {
    extern __shared__ char sm[];
    uint32_t sbase = smem_u32(sm);
    const int tid = threadIdx.x;
    const int wid = tid >> 5;
    const int lane = tid & 31;
    const int wm = wid & 3;
    const int wn = wid >> 2;
    const int m0 = blockIdx.y * 128;
    const int n0 = blockIdx.x * 128;

    const int g = lane >> 3;
    const int rr = lane & 7;
    const int rA = wm * 32 + (g & 1) * 8 + rr;
    const uint32_t aBase = (uint32_t)(rA * 64);
    const uint32_t aSw = (uint32_t)((((g >> 1) ^ ((rA >> 1) & 3)) << 4));
    const int rB = wn * 64 + (g >> 1) * 8 + rr;
    const uint32_t bBase = (uint32_t)(rB * 64);
    const uint32_t bSw = (uint32_t)((((g & 1) ^ ((rB >> 1) & 3)) << 4));

    float acc[2][8][4];
#pragma unroll
    for (int mi = 0; mi < 2; mi++)
#pragma unroll
        for (int ni = 0; ni < 8; ni++)
#pragma unroll
            for (int j = 0; j < 4; j++) acc[mi][ni][j] = 0.0f;

    const int NST = DD / BK;   // 32
    load_stage(sbase + 0 * STAGE_BYTES, A, B, m0, n0, 0, tid);
    CP_COMMIT();
    load_stage(sbase + 1 * STAGE_BYTES, A, B, m0, n0, BK, tid);
    CP_COMMIT();
    load_stage(sbase + 2 * STAGE_BYTES, A, B, m0, n0, 2 * BK, tid);
    CP_COMMIT();

    for (int s = 0; s < NST; s++) {
        if (s < NST - 2)      { CP_WAIT(2); }
        else if (s == NST - 2){ CP_WAIT(1); }
        else                  { CP_WAIT(0); }
        __syncthreads();
        if (s + 3 < NST) {
            load_stage(sbase + ((s + 3) & 3) * STAGE_BYTES, A, B, m0, n0, (s + 3) * BK, tid);
            CP_COMMIT();
        }
        uint32_t sb = sbase + (s & 3) * STAGE_BYTES;

#pragma unroll
        for (int kk = 0; kk < 2; kk++) {
            uint32_t ah[2][4], bf[4][4];
            const uint32_t asw = kk ? (aSw ^ 32u) : aSw;
            const uint32_t bsw = kk ? (bSw ^ 32u) : bSw;
#pragma unroll
            for (int mi = 0; mi < 2; mi++)
                ldm4(ah[mi], sb + aBase + (uint32_t)(mi * 1024) + asw + OFF_A);
#pragma unroll
            for (int np = 0; np < 4; np++)
                ldm4(bf[np], sb + bBase + (uint32_t)(np * 1024) + bsw + OFF_B);
#pragma unroll
            for (int mi = 0; mi < 2; mi++)
#pragma unroll
                for (int ni = 0; ni < 8; ni++)
                    mma16816(acc[mi][ni], ah[mi], bf[ni >> 1][(ni & 1) * 2], bf[ni >> 1][(ni & 1) * 2 + 1]);
        }
    }

    const int row_b = m0 + wm * 32 + (lane >> 2);
    const int col_b = n0 + wn * 64 + (lane & 3) * 2;
#pragma unroll
    for (int mi = 0; mi < 2; mi++)
#pragma unroll
        for (int ni = 0; ni < 8; ni++) {
            int row = row_b + mi * 16;
            int col = col_b + ni * 8;
            if (OUT_MODE == 0) {
                *(float2*)&C[(size_t)row * DD + col] =
                    make_float2(acc[mi][ni][0], acc[mi][ni][1]);
                *(float2*)&C[(size_t)(row + 8) * DD + col] =
                    make_float2(acc[mi][ni][2], acc[mi][ni][3]);
            } else {
#pragma unroll
                for (int rh = 0; rh < 2; rh++) {
                    float v0 = acc[mi][ni][rh * 2 + 0] * scale;
                    float v1 = acc[mi][ni][rh * 2 + 1] * scale;
                    *(uint32_t*)&Ch[(size_t)(row + rh * 8) * DD + col] = pack_h2(v0, v1);
                }
            }
        }
}

__global__ void __launch_bounds__(256, 2)
gemm_qkv_kernel() {
    if (blockIdx.z == 0) {
        gemm_core<2>(g_x, g_wq, nullptr, g_q, QSCALE);
    } else if (blockIdx.z == 1) {
        gemm_core<2>(g_x, g_wk, nullptr, g_k, 1.0f);
    } else {
        gemm_core<2>(g_x, g_wv, nullptr, g_v, 1.0f);
    }
}

__global__ void __launch_bounds__(256, 2)
gemm_out_kernel(float* __restrict__ out) {
    gemm_core<0>(g_oa, g_wo, out, nullptr, 1.0f);
}

// ---------------- HMMA fp16 flash attention (1-pass QK^T and PV) ----------------
// BM=128 (8 warps x 16 rows), BN=64.
#define QT 16384                     // 128 x 64 fp16 = 128B rows
#define KVT 8192                     // 64 x 64 fp16
#define OFF_Q 0
#define OFF_ST QT                    // 16384
#define STG (2 * KVT)                // 16384 (k, v)
#define ATTN_SMEM (OFF_ST + 2 * STG) // 49152

__device__ __forceinline__ void kv_load(uint32_t stage, size_t gkv, int k0, int tid) {
#pragma unroll
    for (int i = 0; i < 4; i++) {
        int tile = i >> 1;
        int r = (i & 1) * 32 + (tid >> 3);
        int c = tid & 7;
        const __half* src = tile ? g_v : g_k;
        cp16(stage + (uint32_t)(tile * KVT + r * 128 + ((c ^ (r & 7)) << 4)),
             src + gkv + (size_t)(k0 + r) * DD + c * 8);
    }
}

__global__ void __launch_bounds__(256, 2)
attn_kernel() {
    extern __shared__ char sm[];
    uint32_t sb = smem_u32(sm);
    const int tid = threadIdx.x;
    const int wid = tid >> 5;
    const int lane = tid & 31;
    const int bh_idx = blockIdx.y;
    const int b = bh_idx >> 4;
    const int h = bh_idx & 15;
    const int q0 = ((int)gridDim.x - 1 - (int)blockIdx.x) * 128;

    const size_t gq = (size_t)(b * SS + q0) * DD + h * HD;
    const size_t gkv = (size_t)(b * SS) * DD + h * HD;

    // load Q tile, swizzled
#pragma unroll
    for (int i = 0; i < 4; i++) {
        int r = i * 32 + (tid >> 3);
        int c = tid & 7;
        cp16(sb + (uint32_t)(OFF_Q + r * 128 + ((c ^ (r & 7)) << 4)),
             g_q + gq + (size_t)r * DD + c * 8);
    }
    kv_load(sb + OFF_ST, gkv, 0, tid);
    CP_COMMIT();
    CP_WAIT(0);
    __syncthreads();

    // Q A-fragments
    uint32_t qh[4][4];
    {
        const int rQ = 16 * wid + (lane & 15);
        const int tQ = lane >> 4;
        const uint32_t qrow = sb + OFF_Q + (uint32_t)(rQ * 128);
        const int sQ = rQ & 7;
#pragma unroll
        for (int q = 0; q < 4; q++)
            ldm4(qh[q], qrow + (uint32_t)(((tQ + 2 * q) ^ sQ) << 4));
    }

    const int rK = ((lane >> 4) << 3) + (lane & 7);
    const int tK = (lane >> 3) & 1;
    const int sK = rK & 7;
    const uint32_t kBase = (uint32_t)(rK * 128);
    const int rV = lane & 15;
    const int tV = lane >> 4;
    const int sV = rV & 7;
    const uint32_t vBase = (uint32_t)(rV * 128);

    float o[8][4];
#pragma unroll
    for (int nt = 0; nt < 8; nt++)
#pragma unroll
        for (int j = 0; j < 4; j++) o[nt][j] = 0.0f;
    float l0 = 0.0f, l1 = 0.0f;

    const int row0 = q0 + 16 * wid + (lane >> 2);
    const int row_min = q0 + 16 * wid;
    const int qrow_hi = q0 + 16 * wid + 15;
    const int ntiles = q0 / 64 + 2;

    for (int it = 0; it < ntiles; it++) {
        const int k0 = it * 64;
        if (it + 1 < ntiles) {
            kv_load(sb + OFF_ST + ((it + 1) & 1) * STG, gkv, (it + 1) * 64, tid);
            CP_COMMIT();
            CP_WAIT(1);
        } else {
            CP_WAIT(0);
        }
        __syncthreads();

        if (k0 <= qrow_hi) {
            const uint32_t stage = sb + OFF_ST + (it & 1) * STG;

            // ---- S = Q K^T, single pass ----
            float s[8][4];
#pragma unroll
            for (int nt = 0; nt < 8; nt++)
#pragma unroll
                for (int j = 0; j < 4; j++) s[nt][j] = 0.0f;

#pragma unroll
            for (int q = 0; q < 4; q++) {
                const uint32_t kc = (uint32_t)((((2 * q) + tK) ^ sK) << 4);
#pragma unroll
                for (int pp = 0; pp < 2; pp++) {
                    uint32_t kf[2][4];
#pragma unroll
                    for (int p2 = 0; p2 < 2; p2++)
                        ldm4(kf[p2], stage + kBase + (uint32_t)((pp * 2 + p2) * 2048) + kc);
#pragma unroll
                    for (int p2 = 0; p2 < 2; p2++) {
                        int p = pp * 2 + p2;
                        mma16816(s[2 * p], qh[q], kf[p2][0], kf[p2][1]);
                        mma16816(s[2 * p + 1], qh[q], kf[p2][2], kf[p2][3]);
                    }
                }
            }

            // ---- causal mask ----
            if (k0 + 63 > row_min) {
#pragma unroll
                for (int nt = 0; nt < 8; nt++) {
                    int key = k0 + nt * 8 + (lane & 3) * 2;
#pragma unroll
                    for (int j = 0; j < 4; j++) {
                        int r = row0 + (j >> 1) * 8;
                        if (key + (j & 1) > r) s[nt][j] = -1e30f;
                    }
                }
            }

            // ---- no-max softmax: P = 2^s ----
#pragma unroll
            for (int nt = 0; nt < 8; nt++) {
                s[nt][0] = ex2f(s[nt][0]);
                s[nt][1] = ex2f(s[nt][1]);
                s[nt][2] = ex2f(s[nt][2]);
                s[nt][3] = ex2f(s[nt][3]);
                l0 += s[nt][0] + s[nt][1];
                l1 += s[nt][2] + s[nt][3];
            }

            // ---- PV, single pass ----
#pragma unroll
            for (int kk = 0; kk < 4; kk++) {
                uint32_t pah[4];
                pah[0] = pack_h2(s[2 * kk][0], s[2 * kk][1]);
                pah[1] = pack_h2(s[2 * kk][2], s[2 * kk][3]);
                pah[2] = pack_h2(s[2 * kk + 1][0], s[2 * kk + 1][1]);
                pah[3] = pack_h2(s[2 * kk + 1][2], s[2 * kk + 1][3]);
                const uint32_t vrow = stage + KVT + vBase + (uint32_t)(kk * 2048);
#pragma unroll
                for (int uu = 0; uu < 2; uu++) {
                    uint32_t vf[2][4];
#pragma unroll
                    for (int u2 = 0; u2 < 2; u2++)
                        ldm4t(vf[u2], vrow + (uint32_t)((((2 * (uu * 2 + u2)) + tV) ^ sV) << 4));
#pragma unroll
                    for (int u2 = 0; u2 < 2; u2++) {
                        int u = uu * 2 + u2;
                        mma16816(o[2 * u], pah, vf[u2][0], vf[u2][1]);
                        mma16816(o[2 * u + 1], pah, vf[u2][2], vf[u2][3]);
                    }
                }
            }
        }
        __syncthreads();
    }

    // ---- finalize: normalize, fp16 out ----
    l0 += __shfl_xor_sync(0xffffffffu, l0, 1);
    l0 += __shfl_xor_sync(0xffffffffu, l0, 2);
    l1 += __shfl_xor_sync(0xffffffffu, l1, 1);
    l1 += __shfl_xor_sync(0xffffffffu, l1, 2);
    float inv0 = 1.0f / l0;
    float inv1 = 1.0f / l1;

    const int grow0 = b * SS + q0 + 16 * wid + (lane >> 2);
    const int gcol = h * HD + (lane & 3) * 2;
#pragma unroll
    for (int nt = 0; nt < 8; nt++) {
#pragma unroll
        for (int rh = 0; rh < 2; rh++) {
            float inv = rh ? inv1 : inv0;
            float v0 = o[nt][rh * 2 + 0] * inv;
            float v1 = o[nt][rh * 2 + 1] * inv;
            size_t off = (size_t)(grow0 + rh * 8) * DD + gcol + nt * 8;
            *(uint32_t*)&g_oa[off] = pack_h2(v0, v1);
        }
    }
}

// ---------------- launch ----------------
extern "C" void kernel_launch(void* const* d_in, const int* in_sizes, int n_in,
                              void* d_out, int out_size) {
    const float* x  = (const float*)d_in[0];
    const float* Wq = (const float*)d_in[1];
    const float* Wk = (const float*)d_in[2];
    const float* Wv = (const float*)d_in[3];
    const float* Wo = (const float*)d_in[4];
    float* out = (float*)d_out;

    cudaFuncSetAttribute(attn_kernel,
                         cudaFuncAttributeMaxDynamicSharedMemorySize, ATTN_SMEM);
    cudaFuncSetAttribute(gemm_qkv_kernel,
                         cudaFuncAttributeMaxDynamicSharedMemorySize, GSMEM_TOTAL);
    cudaFuncSetAttribute(gemm_out_kernel,
                         cudaFuncAttributeMaxDynamicSharedMemorySize, GSMEM_TOTAL);

    __half *p_x, *p_wo;
    cudaGetSymbolAddress((void**)&p_x, g_x);
    cudaGetSymbolAddress((void**)&p_wo, g_wo);

    convert_half_kernel<<<(MM * DD / 4 + 255) / 256, 256>>>(x, p_x, MM * DD / 4);
    convert_half_kernel<<<(DD * DD / 4 + 255) / 256, 256>>>(Wo, p_wo, DD * DD / 4);
    transpose_convert_kernel<<<dim3(32, 32, 3), 256>>>(Wq, Wk, Wv);

    dim3 gq(DD / 128, MM / 128, 3);       // (8, 64, 3)
    gemm_qkv_kernel<<<gq, 256, GSMEM_TOTAL>>>();

    dim3 ga(SS / 128, BB * HH);           // (16, 64)
    attn_kernel<<<ga, 256, ATTN_SMEM>>>();

    dim3 go(DD / 128, MM / 128, 1);       // (8, 64)
    gemm_out_kernel<<<go, 256, GSMEM_TOTAL>>>(out);
}

// round 13
// speedup vs baseline: 7.2134x; 1.0357x over previous
#include <cuda_runtime.h>
#include <cuda_fp16.h>
#include <cstdint>

// Problem constants
#define BB 4
#define SS 2048
#define DD 1024
#define HH 16
#define HD 64
#define MM (BB * SS)   // 8192 rows

// ---------------- scratch (device globals; allocation-free rule) ----------------
__device__ __half g_q[MM * DD];       // Q fp16, pre-scaled by 0.125*log2e
__device__ __half g_k[MM * DD];
__device__ __half g_v[MM * DD];
__device__ __half g_x[MM * DD];
__device__ __half g_oa[MM * DD];

__device__ __half g_wq[DD * DD];      // transposed [n][k]
__device__ __half g_wk[DD * DD];
__device__ __half g_wv[DD * DD];
__device__ __half g_wo[DD * DD];      // row-major Wo == [n][k]

#define QSCALE (0.125f * 1.4426950408889634f)

// ---------------- PTX helpers ----------------
__device__ __forceinline__ uint32_t smem_u32(const void* p) {
    uint32_t a;
    asm("{ .reg .u64 t; cvta.to.shared.u64 t, %1; cvt.u32.u64 %0, t; }" : "=r"(a) : "l"(p));
    return a;
}
__device__ __forceinline__ void cp16(uint32_t dst, const void* src) {
    asm volatile("cp.async.cg.shared.global [%0], [%1], 16;" :: "r"(dst), "l"(src) : "memory");
}
#define CP_COMMIT() asm volatile("cp.async.commit_group;" ::: "memory")
#define CP_WAIT(n) asm volatile("cp.async.wait_group %0;" :: "n"(n) : "memory")

__device__ __forceinline__ void ldm4(uint32_t* d, uint32_t addr) {
    asm volatile("ldmatrix.sync.aligned.m8n8.x4.shared.b16 {%0,%1,%2,%3}, [%4];"
                 : "=r"(d[0]), "=r"(d[1]), "=r"(d[2]), "=r"(d[3]) : "r"(addr));
}
__device__ __forceinline__ void ldm4t(uint32_t* d, uint32_t addr) {
    asm volatile("ldmatrix.sync.aligned.m8n8.x4.trans.shared.b16 {%0,%1,%2,%3}, [%4];"
                 : "=r"(d[0]), "=r"(d[1]), "=r"(d[2]), "=r"(d[3]) : "r"(addr));
}
__device__ __forceinline__ void mma16816(float* c, const uint32_t* a, uint32_t b0, uint32_t b1) {
    asm volatile(
        "mma.sync.aligned.m16n8k16.row.col.f32.f16.f16.f32 "
        "{%0,%1,%2,%3}, {%4,%5,%6,%7}, {%8,%9}, {%0,%1,%2,%3};"
        : "+f"(c[0]), "+f"(c[1]), "+f"(c[2]), "+f"(c[3])
        : "r"(a[0]), "r"(a[1]), "r"(a[2]), "r"(a[3]), "r"(b0), "r"(b1));
}
__device__ __forceinline__ float ex2f(float x) {
    float r;
    asm("ex2.approx.f32 %0, %1;" : "=f"(r) : "f"(x));
    return r;
}
__device__ __forceinline__ uint32_t pack_h2(float x, float y) {
    __half2 h = __floats2half2_rn(x, y);
    return *(uint32_t*)&h;
}

// ---------------- prep kernels ----------------
__global__ void __launch_bounds__(256)
convert_half_kernel(const float* __restrict__ src, __half* __restrict__ dst, int n4) {
    int i = blockIdx.x * 256 + threadIdx.x;
    if (i >= n4) return;
    float4 v = ((const float4*)src)[i];
    ushort4 o;
    o.x = __half_as_ushort(__float2half_rn(v.x));
    o.y = __half_as_ushort(__float2half_rn(v.y));
    o.z = __half_as_ushort(__float2half_rn(v.z));
    o.w = __half_as_ushort(__float2half_rn(v.w));
    ((ushort4*)dst)[i] = o;
}

__global__ void __launch_bounds__(256)
transpose_convert_kernel(const float* __restrict__ Wq, const float* __restrict__ Wk,
                         const float* __restrict__ Wv) {
    const float* W = (blockIdx.z == 0) ? Wq : ((blockIdx.z == 1) ? Wk : Wv);
    __half* dst = (blockIdx.z == 0) ? g_wq : ((blockIdx.z == 1) ? g_wk : g_wv);
    __shared__ float t[32][33];
    int tx = threadIdx.x & 31;
    int ty = threadIdx.x >> 5;
    int k0 = blockIdx.y * 32;
    int n0 = blockIdx.x * 32;
#pragma unroll
    for (int i = 0; i < 4; i++)
        t[ty + i * 8][tx] = W[(size_t)(k0 + ty + i * 8) * DD + n0 + tx];
    __syncthreads();
#pragma unroll
    for (int i = 0; i < 4; i++) {
        int n = n0 + ty + i * 8;
        int k = k0 + tx;
        dst[(size_t)n * DD + k] = __float2half_rn(t[tx][ty + i * 8]);
    }
}

// ---------------- HMMA fp16 1-pass GEMM (BK=64, SW128 swizzle, 3-stage) ----------------
#define BK 64
#define MAT 16384                    // 128 rows x 128B (64 fp16)
#define OFF_A 0
#define OFF_B (1 * MAT)
#define STAGE_BYTES (2 * MAT)        // 32768
#define NPIPE 3
#define GSMEM_TOTAL (NPIPE * STAGE_BYTES)  // 98304

__device__ __forceinline__ void load_stage(uint32_t sb,
                                           const __half* __restrict__ A,
                                           const __half* __restrict__ B,
                                           int m0, int n0, int kt, int tid) {
#pragma unroll
    for (int i = 0; i < 4; i++) {
        int idx = tid + i * 256;          // 0..1023
        int r = idx >> 3;                 // 0..127
        int c = idx & 7;                  // 16B chunk 0..7
        uint32_t so = (uint32_t)(r * 128 + ((c ^ (r & 7)) << 4));
        cp16(sb + OFF_A + so, A + (size_t)(m0 + r) * DD + kt + c * 8);
        cp16(sb + OFF_B + so, B + (size_t)(n0 + r) * DD + kt + c * 8);
    }
}

// OUT_MODE 0: fp32 C.  OUT_MODE 2: single fp16 (scale).
template <int OUT_MODE>
__device__ __forceinline__ void gemm_core(const __half* __restrict__ A,
                                          const __half* __restrict__ B,
                                          float* __restrict__ C,
                                          __half* __restrict__ Ch,
                                          float scale) {
    extern __shared__ char sm[];
    uint32_t sbase = smem_u32(sm);
    const int tid = threadIdx.x;
    const int wid = tid >> 5;
    const int lane = tid & 31;
    const int wm = wid & 3;
    const int wn = wid >> 2;
    const int m0 = blockIdx.y * 128;
    const int n0 = blockIdx.x * 128;

    const int g = lane >> 3;
    const int rr = lane & 7;
    const int rA = wm * 32 + (g & 1) * 8 + rr;      // +mi*16 keeps (rA&7)
    const uint32_t aBase = (uint32_t)(rA * 128);
    const int swA = rA & 7;
    const int caBase = g >> 1;                       // + 2*kk
    const int rB = wn * 64 + (g >> 1) * 8 + rr;      // +np*16 keeps (rB&7)
    const uint32_t bBase = (uint32_t)(rB * 128);
    const int swB = rB & 7;
    const int cbBase = g & 1;                        // + 2*kk

    float acc[2][8][4];
#pragma unroll
    for (int mi = 0; mi < 2; mi++)
#pragma unroll
        for (int ni = 0; ni < 8; ni++)
#pragma unroll
            for (int j = 0; j < 4; j++) acc[mi][ni][j] = 0.0f;

    const int NST = DD / BK;   // 16
    load_stage(sbase + 0 * STAGE_BYTES, A, B, m0, n0, 0, tid);
    CP_COMMIT();
    load_stage(sbase + 1 * STAGE_BYTES, A, B, m0, n0, BK, tid);
    CP_COMMIT();

    int sidx = 0;
    for (int s = 0; s < NST; s++) {
        if (s < NST - 1) { CP_WAIT(1); } else { CP_WAIT(0); }
        __syncthreads();
        if (s + 2 < NST) {
            int nb = sidx + 2; if (nb >= 3) nb -= 3;
            load_stage(sbase + nb * STAGE_BYTES, A, B, m0, n0, (s + 2) * BK, tid);
            CP_COMMIT();
        }
        uint32_t sb = sbase + sidx * STAGE_BYTES;

#pragma unroll
        for (int kk = 0; kk < 4; kk++) {
            uint32_t ah[2][4], bf[4][4];
            const uint32_t aco = (uint32_t)(((caBase + 2 * kk) ^ swA) << 4);
            const uint32_t bco = (uint32_t)(((cbBase + 2 * kk) ^ swB) << 4);
#pragma unroll
            for (int mi = 0; mi < 2; mi++)
                ldm4(ah[mi], sb + OFF_A + aBase + (uint32_t)(mi * 2048) + aco);
#pragma unroll
            for (int np = 0; np < 4; np++)
                ldm4(bf[np], sb + OFF_B + bBase + (uint32_t)(np * 2048) + bco);
#pragma unroll
            for (int mi = 0; mi < 2; mi++)
#pragma unroll
                for (int ni = 0; ni < 8; ni++)
                    mma16816(acc[mi][ni], ah[mi], bf[ni >> 1][(ni & 1) * 2], bf[ni >> 1][(ni & 1) * 2 + 1]);
        }
        sidx++; if (sidx == 3) sidx = 0;
    }

    const int row_b = m0 + wm * 32 + (lane >> 2);
    const int col_b = n0 + wn * 64 + (lane & 3) * 2;
#pragma unroll
    for (int mi = 0; mi < 2; mi++)
#pragma unroll
        for (int ni = 0; ni < 8; ni++) {
            int row = row_b + mi * 16;
            int col = col_b + ni * 8;
            if (OUT_MODE == 0) {
                *(float2*)&C[(size_t)row * DD + col] =
                    make_float2(acc[mi][ni][0], acc[mi][ni][1]);
                *(float2*)&C[(size_t)(row + 8) * DD + col] =
                    make_float2(acc[mi][ni][2], acc[mi][ni][3]);
            } else {
#pragma unroll
                for (int rh = 0; rh < 2; rh++) {
                    float v0 = acc[mi][ni][rh * 2 + 0] * scale;
                    float v1 = acc[mi][ni][rh * 2 + 1] * scale;
                    *(uint32_t*)&Ch[(size_t)(row + rh * 8) * DD + col] = pack_h2(v0, v1);
                }
            }
        }
}

__global__ void __launch_bounds__(256, 2)
gemm_qkv_kernel() {
    if (blockIdx.z == 0) {
        gemm_core<2>(g_x, g_wq, nullptr, g_q, QSCALE);
    } else if (blockIdx.z == 1) {
        gemm_core<2>(g_x, g_wk, nullptr, g_k, 1.0f);
    } else {
        gemm_core<2>(g_x, g_wv, nullptr, g_v, 1.0f);
    }
}

__global__ void __launch_bounds__(256, 2)
gemm_out_kernel(float* __restrict__ out) {
    gemm_core<0>(g_oa, g_wo, out, nullptr, 1.0f);
}

// ---------------- HMMA fp16 flash attention (128-key stages, 64-key halves) --------
// BM=128 (8 warps x 16 rows). Stage holds K[128][64] + V[128][64].
#define QT 16384                     // Q: 128 x 64 fp16 = 128B rows
#define KT 16384                     // K tile: 128 rows x 128B
#define OFF_ST QT
#define STG (2 * KT)                 // 32768 (K, V)
#define ATTN_SMEM (QT + 2 * STG)     // 81920

__device__ __forceinline__ void kv_load(uint32_t stage, size_t gkv, int k0, int tid) {
#pragma unroll
    for (int i = 0; i < 8; i++) {
        int idx = tid + i * 256;          // 0..2047
        int tile = idx >> 10;             // 0=K, 1=V
        int rem = idx & 1023;
        int r = rem >> 3;                 // 0..127
        int c = rem & 7;
        const __half* src = tile ? g_v : g_k;
        cp16(stage + (uint32_t)(tile * KT + r * 128 + ((c ^ (r & 7)) << 4)),
             src + gkv + (size_t)(k0 + r) * DD + c * 8);
    }
}

__global__ void __launch_bounds__(256, 2)
attn_kernel() {
    extern __shared__ char sm[];
    uint32_t sb = smem_u32(sm);
    const int tid = threadIdx.x;
    const int wid = tid >> 5;
    const int lane = tid & 31;
    const int bh_idx = blockIdx.y;
    const int b = bh_idx >> 4;
    const int h = bh_idx & 15;
    const int q0 = ((int)gridDim.x - 1 - (int)blockIdx.x) * 128;

    const size_t gq = (size_t)(b * SS + q0) * DD + h * HD;
    const size_t gkv = (size_t)(b * SS) * DD + h * HD;

    // load Q tile, swizzled
#pragma unroll
    for (int i = 0; i < 4; i++) {
        int r = i * 32 + (tid >> 3);
        int c = tid & 7;
        cp16(sb + (uint32_t)(r * 128 + ((c ^ (r & 7)) << 4)),
             g_q + gq + (size_t)r * DD + c * 8);
    }
    kv_load(sb + OFF_ST, gkv, 0, tid);
    CP_COMMIT();
    CP_WAIT(0);
    __syncthreads();

    // Q A-fragments
    uint32_t qh[4][4];
    {
        const int rQ = 16 * wid + (lane & 15);
        const int tQ = lane >> 4;
        const uint32_t qrow = sb + (uint32_t)(rQ * 128);
        const int sQ = rQ & 7;
#pragma unroll
        for (int q = 0; q < 4; q++)
            ldm4(qh[q], qrow + (uint32_t)(((tQ + 2 * q) ^ sQ) << 4));
    }

    const int rK = ((lane >> 4) << 3) + (lane & 7);
    const int tK = (lane >> 3) & 1;
    const int sK = rK & 7;
    const uint32_t kBase = (uint32_t)(rK * 128);
    const int rV = lane & 15;
    const int tV = lane >> 4;
    const int sV = rV & 7;
    const uint32_t vBase = (uint32_t)(rV * 128);

    float o[8][4];
#pragma unroll
    for (int nt = 0; nt < 8; nt++)
#pragma unroll
        for (int j = 0; j < 4; j++) o[nt][j] = 0.0f;
    float l0 = 0.0f, l1 = 0.0f;

    const int row0 = q0 + 16 * wid + (lane >> 2);
    const int row_min = q0 + 16 * wid;
    const int qrow_hi = q0 + 16 * wid + 15;
    const int ntiles = q0 / 128 + 1;     // 128-key stages

    for (int it = 0; it < ntiles; it++) {
        if (it + 1 < ntiles) {
            kv_load(sb + OFF_ST + ((it + 1) & 1) * STG, gkv, (it + 1) * 128, tid);
            CP_COMMIT();
            CP_WAIT(1);
        } else {
            CP_WAIT(0);
        }
        __syncthreads();
        const uint32_t stage = sb + OFF_ST + (it & 1) * STG;

#pragma unroll
        for (int h2 = 0; h2 < 2; h2++) {
            const int k0 = it * 128 + h2 * 64;
            if (k0 > qrow_hi) break;
            const uint32_t kst = stage + (uint32_t)(h2 * 8192);
            const uint32_t vst = stage + KT + (uint32_t)(h2 * 8192);

            // ---- S = Q K^T, single pass ----
            float s[8][4];
#pragma unroll
            for (int nt = 0; nt < 8; nt++)
#pragma unroll
                for (int j = 0; j < 4; j++) s[nt][j] = 0.0f;

#pragma unroll
            for (int q = 0; q < 4; q++) {
                const uint32_t kc = (uint32_t)((((2 * q) + tK) ^ sK) << 4);
#pragma unroll
                for (int pp = 0; pp < 2; pp++) {
                    uint32_t kf[2][4];
#pragma unroll
                    for (int p2 = 0; p2 < 2; p2++)
                        ldm4(kf[p2], kst + kBase + (uint32_t)((pp * 2 + p2) * 2048) + kc);
#pragma unroll
                    for (int p2 = 0; p2 < 2; p2++) {
                        int p = pp * 2 + p2;
                        mma16816(s[2 * p], qh[q], kf[p2][0], kf[p2][1]);
                        mma16816(s[2 * p + 1], qh[q], kf[p2][2], kf[p2][3]);
                    }
                }
            }

            // ---- causal mask ----
            if (k0 + 63 > row_min) {
#pragma unroll
                for (int nt = 0; nt < 8; nt++) {
                    int key = k0 + nt * 8 + (lane & 3) * 2;
#pragma unroll
                    for (int j = 0; j < 4; j++) {
                        int r = row0 + (j >> 1) * 8;
                        if (key + (j & 1) > r) s[nt][j] = -1e30f;
                    }
                }
            }

            // ---- no-max softmax: P = 2^s ----
#pragma unroll
            for (int nt = 0; nt < 8; nt++) {
                s[nt][0] = ex2f(s[nt][0]);
                s[nt][1] = ex2f(s[nt][1]);
                s[nt][2] = ex2f(s[nt][2]);
                s[nt][3] = ex2f(s[nt][3]);
                l0 += s[nt][0] + s[nt][1];
                l1 += s[nt][2] + s[nt][3];
            }

            // ---- PV, single pass ----
#pragma unroll
            for (int kk = 0; kk < 4; kk++) {
                uint32_t pah[4];
                pah[0] = pack_h2(s[2 * kk][0], s[2 * kk][1]);
                pah[1] = pack_h2(s[2 * kk][2], s[2 * kk][3]);
                pah[2] = pack_h2(s[2 * kk + 1][0], s[2 * kk + 1][1]);
                pah[3] = pack_h2(s[2 * kk + 1][2], s[2 * kk + 1][3]);
                const uint32_t vrow = vst + vBase + (uint32_t)(kk * 2048);
#pragma unroll
                for (int uu = 0; uu < 2; uu++) {
                    uint32_t vf[2][4];
#pragma unroll
                    for (int u2 = 0; u2 < 2; u2++)
                        ldm4t(vf[u2], vrow + (uint32_t)((((2 * (uu * 2 + u2)) + tV) ^ sV) << 4));
#pragma unroll
                    for (int u2 = 0; u2 < 2; u2++) {
                        int u = uu * 2 + u2;
                        mma16816(o[2 * u], pah, vf[u2][0], vf[u2][1]);
                        mma16816(o[2 * u + 1], pah, vf[u2][2], vf[u2][3]);
                    }
                }
            }
        }
        __syncthreads();
    }

    // ---- finalize: normalize, fp16 out ----
    l0 += __shfl_xor_sync(0xffffffffu, l0, 1);
    l0 += __shfl_xor_sync(0xffffffffu, l0, 2);
    l1 += __shfl_xor_sync(0xffffffffu, l1, 1);
    l1 += __shfl_xor_sync(0xffffffffu, l1, 2);
    float inv0 = 1.0f / l0;
    float inv1 = 1.0f / l1;

    const int grow0 = b * SS + q0 + 16 * wid + (lane >> 2);
    const int gcol = h * HD + (lane & 3) * 2;
#pragma unroll
    for (int nt = 0; nt < 8; nt++) {
#pragma unroll
        for (int rh = 0; rh < 2; rh++) {
            float inv = rh ? inv1 : inv0;
            float v0 = o[nt][rh * 2 + 0] * inv;
            float v1 = o[nt][rh * 2 + 1] * inv;
            size_t off = (size_t)(grow0 + rh * 8) * DD + gcol + nt * 8;
            *(uint32_t*)&g_oa[off] = pack_h2(v0, v1);
        }
    }
}

// ---------------- launch ----------------
extern "C" void kernel_launch(void* const* d_in, const int* in_sizes, int n_in,
                              void* d_out, int out_size) {
    const float* x  = (const float*)d_in[0];
    const float* Wq = (const float*)d_in[1];
    const float* Wk = (const float*)d_in[2];
    const float* Wv = (const float*)d_in[3];
    const float* Wo = (const float*)d_in[4];
    float* out = (float*)d_out;

    cudaFuncSetAttribute(attn_kernel,
                         cudaFuncAttributeMaxDynamicSharedMemorySize, ATTN_SMEM);
    cudaFuncSetAttribute(gemm_qkv_kernel,
                         cudaFuncAttributeMaxDynamicSharedMemorySize, GSMEM_TOTAL);
    cudaFuncSetAttribute(gemm_out_kernel,
                         cudaFuncAttributeMaxDynamicSharedMemorySize, GSMEM_TOTAL);

    __half *p_x, *p_wo;
    cudaGetSymbolAddress((void**)&p_x, g_x);
    cudaGetSymbolAddress((void**)&p_wo, g_wo);

    convert_half_kernel<<<(MM * DD / 4 + 255) / 256, 256>>>(x, p_x, MM * DD / 4);
    convert_half_kernel<<<(DD * DD / 4 + 255) / 256, 256>>>(Wo, p_wo, DD * DD / 4);
    transpose_convert_kernel<<<dim3(32, 32, 3), 256>>>(Wq, Wk, Wv);

    dim3 gq(DD / 128, MM / 128, 3);       // (8, 64, 3)
    gemm_qkv_kernel<<<gq, 256, GSMEM_TOTAL>>>();

    dim3 ga(SS / 128, BB * HH);           // (16, 64)
    attn_kernel<<<ga, 256, ATTN_SMEM>>>();

    dim3 go(DD / 128, MM / 128, 1);       // (8, 64)
    gemm_out_kernel<<<go, 256, GSMEM_TOTAL>>>(out);
}

// round 14
// speedup vs baseline: 7.7470x; 1.0740x over previous
#include <cuda_runtime.h>
#include <cuda_fp16.h>
#include <cstdint>

// Problem constants
#define BB 4
#define SS 2048
#define DD 1024
#define HH 16
#define HD 64
#define MM (BB * SS)   // 8192 rows

// ---------------- scratch (device globals; allocation-free rule) ----------------
__device__ __half g_q[MM * DD];       // Q fp16, pre-scaled by 0.125*log2e
__device__ __half g_k[MM * DD];
__device__ __half g_v[MM * DD];
__device__ __half g_x[MM * DD];
__device__ __half g_oa[MM * DD];

__device__ __half g_wq[DD * DD];      // transposed [n][k]
__device__ __half g_wk[DD * DD];
__device__ __half g_wv[DD * DD];
__device__ __half g_wo[DD * DD];      // row-major Wo == [n][k]

__device__ int g_cnt[64];             // per-(b,qblock) attention completion counters

#define QSCALE (0.125f * 1.4426950408889634f)

// ---------------- PTX helpers ----------------
__device__ __forceinline__ uint32_t smem_u32(const void* p) {
    uint32_t a;
    asm("{ .reg .u64 t; cvta.to.shared.u64 t, %1; cvt.u32.u64 %0, t; }" : "=r"(a) : "l"(p));
    return a;
}
__device__ __forceinline__ void cp16(uint32_t dst, const void* src) {
    asm volatile("cp.async.cg.shared.global [%0], [%1], 16;" :: "r"(dst), "l"(src) : "memory");
}
#define CP_COMMIT() asm volatile("cp.async.commit_group;" ::: "memory")
#define CP_WAIT(n) asm volatile("cp.async.wait_group %0;" :: "n"(n) : "memory")

__device__ __forceinline__ void ldm4(uint32_t* d, uint32_t addr) {
    asm volatile("ldmatrix.sync.aligned.m8n8.x4.shared.b16 {%0,%1,%2,%3}, [%4];"
                 : "=r"(d[0]), "=r"(d[1]), "=r"(d[2]), "=r"(d[3]) : "r"(addr));
}
__device__ __forceinline__ void ldm4t(uint32_t* d, uint32_t addr) {
    asm volatile("ldmatrix.sync.aligned.m8n8.x4.trans.shared.b16 {%0,%1,%2,%3}, [%4];"
                 : "=r"(d[0]), "=r"(d[1]), "=r"(d[2]), "=r"(d[3]) : "r"(addr));
}
__device__ __forceinline__ void mma16816(float* c, const uint32_t* a, uint32_t b0, uint32_t b1) {
    asm volatile(
        "mma.sync.aligned.m16n8k16.row.col.f32.f16.f16.f32 "
        "{%0,%1,%2,%3}, {%4,%5,%6,%7}, {%8,%9}, {%0,%1,%2,%3};"
        : "+f"(c[0]), "+f"(c[1]), "+f"(c[2]), "+f"(c[3])
        : "r"(a[0]), "r"(a[1]), "r"(a[2]), "r"(a[3]), "r"(b0), "r"(b1));
}
__device__ __forceinline__ float ex2f(float x) {
    float r;
    asm("ex2.approx.f32 %0, %1;" : "=f"(r) : "f"(x));
    return r;
}
__device__ __forceinline__ uint32_t pack_h2(float x, float y) {
    __half2 h = __floats2half2_rn(x, y);
    return *(uint32_t*)&h;
}

// ---------------- prep kernels ----------------
__global__ void __launch_bounds__(256)
convert_half_kernel(const float* __restrict__ src, __half* __restrict__ dst, int n4) {
    if (blockIdx.x == 0 && threadIdx.x < 64) g_cnt[threadIdx.x] = 0;  // reset counters
    int i = blockIdx.x * 256 + threadIdx.x;
    if (i >= n4) return;
    float4 v = ((const float4*)src)[i];
    ushort4 o;
    o.x = __half_as_ushort(__float2half_rn(v.x));
    o.y = __half_as_ushort(__float2half_rn(v.y));
    o.z = __half_as_ushort(__float2half_rn(v.z));
    o.w = __half_as_ushort(__float2half_rn(v.w));
    ((ushort4*)dst)[i] = o;
}

__global__ void __launch_bounds__(256)
transpose_convert_kernel(const float* __restrict__ Wq, const float* __restrict__ Wk,
                         const float* __restrict__ Wv) {
    const float* W = (blockIdx.z == 0) ? Wq : ((blockIdx.z == 1) ? Wk : Wv);
    __half* dst = (blockIdx.z == 0) ? g_wq : ((blockIdx.z == 1) ? g_wk : g_wv);
    __shared__ float t[32][33];
    int tx = threadIdx.x & 31;
    int ty = threadIdx.x >> 5;
    int k0 = blockIdx.y * 32;
    int n0 = blockIdx.x * 32;
#pragma unroll
    for (int i = 0; i < 4; i++)
        t[ty + i * 8][tx] = W[(size_t)(k0 + ty + i * 8) * DD + n0 + tx];
    __syncthreads();
#pragma unroll
    for (int i = 0; i < 4; i++) {
        int n = n0 + ty + i * 8;
        int k = k0 + tx;
        dst[(size_t)n * DD + k] = __float2half_rn(t[tx][ty + i * 8]);
    }
}

// ---------------- HMMA fp16 1-pass GEMM core (BK=64, SW128 swizzle, 3-stage) ----------------
#define BK 64
#define MAT 16384                    // 128 rows x 128B (64 fp16)
#define OFF_A 0
#define OFF_B (1 * MAT)
#define STAGE_BYTES (2 * MAT)        // 32768
#define NPIPE 3
#define GSMEM_TOTAL (NPIPE * STAGE_BYTES)  // 98304

__device__ __forceinline__ void load_stage(uint32_t sb,
                                           const __half* __restrict__ A,
                                           const __half* __restrict__ B,
                                           int m0, int n0, int kt, int tid) {
#pragma unroll
    for (int i = 0; i < 4; i++) {
        int idx = tid + i * 256;          // 0..1023
        int r = idx >> 3;                 // 0..127
        int c = idx & 7;                  // 16B chunk 0..7
        uint32_t so = (uint32_t)(r * 128 + ((c ^ (r & 7)) << 4));
        cp16(sb + OFF_A + so, A + (size_t)(m0 + r) * DD + kt + c * 8);
        cp16(sb + OFF_B + so, B + (size_t)(n0 + r) * DD + kt + c * 8);
    }
}

// OUT_MODE 0: fp32 C.  OUT_MODE 2: single fp16 (scale).
template <int OUT_MODE>
__device__ __forceinline__ void gemm_core(const __half* __restrict__ A,
                                          const __half* __restrict__ B,
                                          float* __restrict__ C,
                                          __half* __restrict__ Ch,
                                          float scale, int m0, int n0) {
    extern __shared__ char sm[];
    uint32_t sbase = smem_u32(sm);
    const int tid = threadIdx.x;
    const int wid = tid >> 5;
    const int lane = tid & 31;
    const int wm = wid & 3;
    const int wn = wid >> 2;

    const int g = lane >> 3;
    const int rr = lane & 7;
    const int rA = wm * 32 + (g & 1) * 8 + rr;
    const uint32_t aBase = (uint32_t)(rA * 128);
    const int swA = rA & 7;
    const int caBase = g >> 1;
    const int rB = wn * 64 + (g >> 1) * 8 + rr;
    const uint32_t bBase = (uint32_t)(rB * 128);
    const int swB = rB & 7;
    const int cbBase = g & 1;

    float acc[2][8][4];
#pragma unroll
    for (int mi = 0; mi < 2; mi++)
#pragma unroll
        for (int ni = 0; ni < 8; ni++)
#pragma unroll
            for (int j = 0; j < 4; j++) acc[mi][ni][j] = 0.0f;

    const int NST = DD / BK;   // 16
    load_stage(sbase + 0 * STAGE_BYTES, A, B, m0, n0, 0, tid);
    CP_COMMIT();
    load_stage(sbase + 1 * STAGE_BYTES, A, B, m0, n0, BK, tid);
    CP_COMMIT();

    int sidx = 0;
    for (int s = 0; s < NST; s++) {
        if (s < NST - 1) { CP_WAIT(1); } else { CP_WAIT(0); }
        __syncthreads();
        if (s + 2 < NST) {
            int nb = sidx + 2; if (nb >= 3) nb -= 3;
            load_stage(sbase + nb * STAGE_BYTES, A, B, m0, n0, (s + 2) * BK, tid);
            CP_COMMIT();
        }
        uint32_t sb = sbase + sidx * STAGE_BYTES;

#pragma unroll
        for (int kk = 0; kk < 4; kk++) {
            uint32_t ah[2][4], bf[4][4];
            const uint32_t aco = (uint32_t)(((caBase + 2 * kk) ^ swA) << 4);
            const uint32_t bco = (uint32_t)(((cbBase + 2 * kk) ^ swB) << 4);
#pragma unroll
            for (int mi = 0; mi < 2; mi++)
                ldm4(ah[mi], sb + OFF_A + aBase + (uint32_t)(mi * 2048) + aco);
#pragma unroll
            for (int np = 0; np < 4; np++)
                ldm4(bf[np], sb + OFF_B + bBase + (uint32_t)(np * 2048) + bco);
#pragma unroll
            for (int mi = 0; mi < 2; mi++)
#pragma unroll
                for (int ni = 0; ni < 8; ni++)
                    mma16816(acc[mi][ni], ah[mi], bf[ni >> 1][(ni & 1) * 2], bf[ni >> 1][(ni & 1) * 2 + 1]);
        }
        sidx++; if (sidx == 3) sidx = 0;
    }

    const int row_b = m0 + wm * 32 + (lane >> 2);
    const int col_b = n0 + wn * 64 + (lane & 3) * 2;
#pragma unroll
    for (int mi = 0; mi < 2; mi++)
#pragma unroll
        for (int ni = 0; ni < 8; ni++) {
            int row = row_b + mi * 16;
            int col = col_b + ni * 8;
            if (OUT_MODE == 0) {
                *(float2*)&C[(size_t)row * DD + col] =
                    make_float2(acc[mi][ni][0], acc[mi][ni][1]);
                *(float2*)&C[(size_t)(row + 8) * DD + col] =
                    make_float2(acc[mi][ni][2], acc[mi][ni][3]);
            } else {
#pragma unroll
                for (int rh = 0; rh < 2; rh++) {
                    float v0 = acc[mi][ni][rh * 2 + 0] * scale;
                    float v1 = acc[mi][ni][rh * 2 + 1] * scale;
                    *(uint32_t*)&Ch[(size_t)(row + rh * 8) * DD + col] = pack_h2(v0, v1);
                }
            }
        }
}

__global__ void __launch_bounds__(256, 2)
gemm_qkv_kernel() {
    int m0 = blockIdx.y * 128;
    int n0 = blockIdx.x * 128;
    if (blockIdx.z == 0) {
        gemm_core<2>(g_x, g_wq, nullptr, g_q, QSCALE, m0, n0);
    } else if (blockIdx.z == 1) {
        gemm_core<2>(g_x, g_wk, nullptr, g_k, 1.0f, m0, n0);
    } else {
        gemm_core<2>(g_x, g_wv, nullptr, g_v, 1.0f, m0, n0);
    }
}

// ---------------- attention body (128-key stages, 64-key halves) ----------------
#define QT 16384                     // Q: 128 x 64 fp16 = 128B rows
#define KT 16384                     // K tile: 128 rows x 128B
#define OFF_ST QT
#define STG (2 * KT)                 // 32768 (K, V)
// attention uses QT + 2*STG = 81920 <= GSMEM_TOTAL (98304) of the fused kernel

__device__ __forceinline__ void kv_load(uint32_t stage, size_t gkv, int k0, int tid) {
#pragma unroll
    for (int i = 0; i < 8; i++) {
        int idx = tid + i * 256;          // 0..2047
        int tile = idx >> 10;             // 0=K, 1=V
        int rem = idx & 1023;
        int r = rem >> 3;                 // 0..127
        int c = rem & 7;
        const __half* src = tile ? g_v : g_k;
        cp16(stage + (uint32_t)(tile * KT + r * 128 + ((c ^ (r & 7)) << 4)),
             src + gkv + (size_t)(k0 + r) * DD + c * 8);
    }
}

__device__ __forceinline__ void attn_body(int abid) {
    extern __shared__ char sm[];
    uint32_t sb = smem_u32(sm);
    const int tid = threadIdx.x;
    const int wid = tid >> 5;
    const int lane = tid & 31;
    const int bh_idx = abid >> 4;         // 0..63
    const int b = bh_idx >> 4;
    const int h = bh_idx & 15;
    const int qx = abid & 15;
    const int q0 = (15 - qx) * 128;       // reversed: longest first

    const size_t gq = (size_t)(b * SS + q0) * DD + h * HD;
    const size_t gkv = (size_t)(b * SS) * DD + h * HD;

    // load Q tile, swizzled
#pragma unroll
    for (int i = 0; i < 4; i++) {
        int r = i * 32 + (tid >> 3);
        int c = tid & 7;
        cp16(sb + (uint32_t)(r * 128 + ((c ^ (r & 7)) << 4)),
             g_q + gq + (size_t)r * DD + c * 8);
    }
    kv_load(sb + OFF_ST, gkv, 0, tid);
    CP_COMMIT();
    CP_WAIT(0);
    __syncthreads();

    // Q A-fragments
    uint32_t qh[4][4];
    {
        const int rQ = 16 * wid + (lane & 15);
        const int tQ = lane >> 4;
        const uint32_t qrow = sb + (uint32_t)(rQ * 128);
        const int sQ = rQ & 7;
#pragma unroll
        for (int q = 0; q < 4; q++)
            ldm4(qh[q], qrow + (uint32_t)(((tQ + 2 * q) ^ sQ) << 4));
    }

    const int rK = ((lane >> 4) << 3) + (lane & 7);
    const int tK = (lane >> 3) & 1;
    const int sK = rK & 7;
    const uint32_t kBase = (uint32_t)(rK * 128);
    const int rV = lane & 15;
    const int tV = lane >> 4;
    const int sV = rV & 7;
    const uint32_t vBase = (uint32_t)(rV * 128);

    float o[8][4];
#pragma unroll
    for (int nt = 0; nt < 8; nt++)
#pragma unroll
        for (int j = 0; j < 4; j++) o[nt][j] = 0.0f;
    float l0 = 0.0f, l1 = 0.0f;

    const int row0 = q0 + 16 * wid + (lane >> 2);
    const int row_min = q0 + 16 * wid;
    const int qrow_hi = q0 + 16 * wid + 15;
    const int ntiles = q0 / 128 + 1;     // 128-key stages

    for (int it = 0; it < ntiles; it++) {
        if (it + 1 < ntiles) {
            kv_load(sb + OFF_ST + ((it + 1) & 1) * STG, gkv, (it + 1) * 128, tid);
            CP_COMMIT();
            CP_WAIT(1);
        } else {
            CP_WAIT(0);
        }
        __syncthreads();
        const uint32_t stage = sb + OFF_ST + (it & 1) * STG;

#pragma unroll
        for (int h2 = 0; h2 < 2; h2++) {
            const int k0 = it * 128 + h2 * 64;
            if (k0 > qrow_hi) break;
            const uint32_t kst = stage + (uint32_t)(h2 * 8192);
            const uint32_t vst = stage + KT + (uint32_t)(h2 * 8192);

            // ---- S = Q K^T, single pass ----
            float s[8][4];
#pragma unroll
            for (int nt = 0; nt < 8; nt++)
#pragma unroll
                for (int j = 0; j < 4; j++) s[nt][j] = 0.0f;

#pragma unroll
            for (int q = 0; q < 4; q++) {
                const uint32_t kc = (uint32_t)((((2 * q) + tK) ^ sK) << 4);
#pragma unroll
                for (int pp = 0; pp < 2; pp++) {
                    uint32_t kf[2][4];
#pragma unroll
                    for (int p2 = 0; p2 < 2; p2++)
                        ldm4(kf[p2], kst + kBase + (uint32_t)((pp * 2 + p2) * 2048) + kc);
#pragma unroll
                    for (int p2 = 0; p2 < 2; p2++) {
                        int p = pp * 2 + p2;
                        mma16816(s[2 * p], qh[q], kf[p2][0], kf[p2][1]);
                        mma16816(s[2 * p + 1], qh[q], kf[p2][2], kf[p2][3]);
                    }
                }
            }

            // ---- causal mask ----
            if (k0 + 63 > row_min) {
#pragma unroll
                for (int nt = 0; nt < 8; nt++) {
                    int key = k0 + nt * 8 + (lane & 3) * 2;
#pragma unroll
                    for (int j = 0; j < 4; j++) {
                        int r = row0 + (j >> 1) * 8;
                        if (key + (j & 1) > r) s[nt][j] = -1e30f;
                    }
                }
            }

            // ---- no-max softmax: P = 2^s ----
#pragma unroll
            for (int nt = 0; nt < 8; nt++) {
                s[nt][0] = ex2f(s[nt][0]);
                s[nt][1] = ex2f(s[nt][1]);
                s[nt][2] = ex2f(s[nt][2]);
                s[nt][3] = ex2f(s[nt][3]);
                l0 += s[nt][0] + s[nt][1];
                l1 += s[nt][2] + s[nt][3];
            }

            // ---- PV, single pass ----
#pragma unroll
            for (int kk = 0; kk < 4; kk++) {
                uint32_t pah[4];
                pah[0] = pack_h2(s[2 * kk][0], s[2 * kk][1]);
                pah[1] = pack_h2(s[2 * kk][2], s[2 * kk][3]);
                pah[2] = pack_h2(s[2 * kk + 1][0], s[2 * kk + 1][1]);
                pah[3] = pack_h2(s[2 * kk + 1][2], s[2 * kk + 1][3]);
                const uint32_t vrow = vst + vBase + (uint32_t)(kk * 2048);
#pragma unroll
                for (int uu = 0; uu < 2; uu++) {
                    uint32_t vf[2][4];
#pragma unroll
                    for (int u2 = 0; u2 < 2; u2++)
                        ldm4t(vf[u2], vrow + (uint32_t)((((2 * (uu * 2 + u2)) + tV) ^ sV) << 4));
#pragma unroll
                    for (int u2 = 0; u2 < 2; u2++) {
                        int u = uu * 2 + u2;
                        mma16816(o[2 * u], pah, vf[u2][0], vf[u2][1]);
                        mma16816(o[2 * u + 1], pah, vf[u2][2], vf[u2][3]);
                    }
                }
            }
        }
        __syncthreads();
    }

    // ---- finalize: normalize, fp16 out ----
    l0 += __shfl_xor_sync(0xffffffffu, l0, 1);
    l0 += __shfl_xor_sync(0xffffffffu, l0, 2);
    l1 += __shfl_xor_sync(0xffffffffu, l1, 1);
    l1 += __shfl_xor_sync(0xffffffffu, l1, 2);
    float inv0 = 1.0f / l0;
    float inv1 = 1.0f / l1;

    const int grow0 = b * SS + q0 + 16 * wid + (lane >> 2);
    const int gcol = h * HD + (lane & 3) * 2;
#pragma unroll
    for (int nt = 0; nt < 8; nt++) {
#pragma unroll
        for (int rh = 0; rh < 2; rh++) {
            float inv = rh ? inv1 : inv0;
            float v0 = o[nt][rh * 2 + 0] * inv;
            float v1 = o[nt][rh * 2 + 1] * inv;
            size_t off = (size_t)(grow0 + rh * 8) * DD + gcol + nt * 8;
            *(uint32_t*)&g_oa[off] = pack_h2(v0, v1);
        }
    }

    // ---- publish completion for this (b, qblock) m-tile ----
    __syncthreads();
    __threadfence();
    if (tid == 0)
        atomicAdd(&g_cnt[(b << 4) + (q0 >> 7)], 1);
}

// ---------------- fused attention + out-projection ----------------
// bids 0..1023: attention (dispatched first). bids 1024..1535: out-proj tiles,
// each spin-waits until its 16 producer attention blocks have published.
__global__ void __launch_bounds__(256, 2)
attn_out_kernel(float* __restrict__ out) {
    const int bid = blockIdx.x;
    if (bid < 1024) {
        attn_body(bid);
    } else {
        const int obid = bid - 1024;
        const int mt = obid >> 3;               // m-tile 0..63
        const int m0 = mt * 128;
        const int n0 = (obid & 7) * 128;
        if (threadIdx.x == 0) {
            while (atomicAdd(&g_cnt[mt], 0) < 16)
                __nanosleep(256);
        }
        __syncthreads();
        gemm_core<0>(g_oa, g_wo, out, nullptr, 1.0f, m0, n0);
    }
}

// ---------------- launch ----------------
extern "C" void kernel_launch(void* const* d_in, const int* in_sizes, int n_in,
                              void* d_out, int out_size) {
    const float* x  = (const float*)d_in[0];
    const float* Wq = (const float*)d_in[1];
    const float* Wk = (const float*)d_in[2];
    const float* Wv = (const float*)d_in[3];
    const float* Wo = (const float*)d_in[4];
    float* out = (float*)d_out;

    cudaFuncSetAttribute(gemm_qkv_kernel,
                         cudaFuncAttributeMaxDynamicSharedMemorySize, GSMEM_TOTAL);
    cudaFuncSetAttribute(attn_out_kernel,
                         cudaFuncAttributeMaxDynamicSharedMemorySize, GSMEM_TOTAL);

    __half *p_x, *p_wo;
    cudaGetSymbolAddress((void**)&p_x, g_x);
    cudaGetSymbolAddress((void**)&p_wo, g_wo);

    convert_half_kernel<<<(MM * DD / 4 + 255) / 256, 256>>>(x, p_x, MM * DD / 4);
    convert_half_kernel<<<(DD * DD / 4 + 255) / 256, 256>>>(Wo, p_wo, DD * DD / 4);
    transpose_convert_kernel<<<dim3(32, 32, 3), 256>>>(Wq, Wk, Wv);

    dim3 gq(DD / 128, MM / 128, 3);       // (8, 64, 3)
    gemm_qkv_kernel<<<gq, 256, GSMEM_TOTAL>>>();

    attn_out_kernel<<<1536, 256, GSMEM_TOTAL>>>(out);
}

// round 15
// speedup vs baseline: 7.8423x; 1.0123x over previous
#include <cuda_runtime.h>
#include <cuda_fp16.h>
#include <cstdint>

// Problem constants
#define BB 4
#define SS 2048
#define DD 1024
#define HH 16
#define HD 64
#define MM (BB * SS)   // 8192 rows

// ---------------- scratch (device globals; allocation-free rule) ----------------
__device__ __half g_q[MM * DD];       // Q fp16, pre-scaled by 0.125*log2e
__device__ __half g_k[MM * DD];
__device__ __half g_v[MM * DD];
__device__ __half g_x[MM * DD];
__device__ __half g_oa[MM * DD];

__device__ __half g_wq[DD * DD];      // transposed [n][k]
__device__ __half g_wk[DD * DD];
__device__ __half g_wv[DD * DD];
__device__ __half g_wo[DD * DD];      // row-major Wo == [n][k]

// [0..63] q m-tiles (target 8), [64..127] k+v m-tiles (target 16), [128..191] oa (target 16)
__device__ int g_cnt[192];

#define QSCALE (0.125f * 1.4426950408889634f)

// ---------------- PTX helpers ----------------
__device__ __forceinline__ uint32_t smem_u32(const void* p) {
    uint32_t a;
    asm("{ .reg .u64 t; cvta.to.shared.u64 t, %1; cvt.u32.u64 %0, t; }" : "=r"(a) : "l"(p));
    return a;
}
__device__ __forceinline__ void cp16(uint32_t dst, const void* src) {
    asm volatile("cp.async.cg.shared.global [%0], [%1], 16;" :: "r"(dst), "l"(src) : "memory");
}
#define CP_COMMIT() asm volatile("cp.async.commit_group;" ::: "memory")
#define CP_WAIT(n) asm volatile("cp.async.wait_group %0;" :: "n"(n) : "memory")

__device__ __forceinline__ void ldm4(uint32_t* d, uint32_t addr) {
    asm volatile("ldmatrix.sync.aligned.m8n8.x4.shared.b16 {%0,%1,%2,%3}, [%4];"
                 : "=r"(d[0]), "=r"(d[1]), "=r"(d[2]), "=r"(d[3]) : "r"(addr));
}
__device__ __forceinline__ void ldm4t(uint32_t* d, uint32_t addr) {
    asm volatile("ldmatrix.sync.aligned.m8n8.x4.trans.shared.b16 {%0,%1,%2,%3}, [%4];"
                 : "=r"(d[0]), "=r"(d[1]), "=r"(d[2]), "=r"(d[3]) : "r"(addr));
}
__device__ __forceinline__ void mma16816(float* c, const uint32_t* a, uint32_t b0, uint32_t b1) {
    asm volatile(
        "mma.sync.aligned.m16n8k16.row.col.f32.f16.f16.f32 "
        "{%0,%1,%2,%3}, {%4,%5,%6,%7}, {%8,%9}, {%0,%1,%2,%3};"
        : "+f"(c[0]), "+f"(c[1]), "+f"(c[2]), "+f"(c[3])
        : "r"(a[0]), "r"(a[1]), "r"(a[2]), "r"(a[3]), "r"(b0), "r"(b1));
}
__device__ __forceinline__ float ex2f(float x) {
    float r;
    asm("ex2.approx.f32 %0, %1;" : "=f"(r) : "f"(x));
    return r;
}
__device__ __forceinline__ uint32_t pack_h2(float x, float y) {
    __half2 h = __floats2half2_rn(x, y);
    return *(uint32_t*)&h;
}
__device__ __forceinline__ void spin_until(int* p, int target) {
    while (atomicAdd(p, 0) < target)
        __nanosleep(128);
}

// ---------------- fused prep kernel ----------------
// bids [0,8192): convert x.  [8192,9216): convert Wo.  [9216,12288): transpose Wq/Wk/Wv.
__global__ void __launch_bounds__(256)
prep_kernel(const float* __restrict__ x, const float* __restrict__ Wq,
            const float* __restrict__ Wk, const float* __restrict__ Wv,
            const float* __restrict__ Wo) {
    const int bid = blockIdx.x;
    if (bid == 0 && threadIdx.x < 192) g_cnt[threadIdx.x] = 0;

    if (bid < 9216) {
        const float* src = (bid < 8192) ? x : Wo;
        __half* dst = (bid < 8192) ? g_x : g_wo;
        int i = ((bid < 8192) ? bid : (bid - 8192)) * 256 + threadIdx.x;
        float4 v = ((const float4*)src)[i];
        ushort4 o;
        o.x = __half_as_ushort(__float2half_rn(v.x));
        o.y = __half_as_ushort(__float2half_rn(v.y));
        o.z = __half_as_ushort(__float2half_rn(v.z));
        o.w = __half_as_ushort(__float2half_rn(v.w));
        ((ushort4*)dst)[i] = o;
    } else {
        int t = bid - 9216;                 // 0..3071
        int z = t >> 10;
        int rem = t & 1023;
        int bx = rem & 31, by = rem >> 5;
        const float* W = (z == 0) ? Wq : ((z == 1) ? Wk : Wv);
        __half* dst = (z == 0) ? g_wq : ((z == 1) ? g_wk : g_wv);
        __shared__ float tt[32][33];
        int tx = threadIdx.x & 31;
        int ty = threadIdx.x >> 5;
        int k0 = by * 32;
        int n0 = bx * 32;
#pragma unroll
        for (int i = 0; i < 4; i++)
            tt[ty + i * 8][tx] = W[(size_t)(k0 + ty + i * 8) * DD + n0 + tx];
        __syncthreads();
#pragma unroll
        for (int i = 0; i < 4; i++)
            dst[(size_t)(n0 + ty + i * 8) * DD + k0 + tx] =
                __float2half_rn(tt[tx][ty + i * 8]);
    }
}

// ---------------- HMMA fp16 1-pass GEMM core (BK=64, SW128 swizzle, 3-stage) ----------------
#define BK 64
#define MAT 16384                    // 128 rows x 128B (64 fp16)
#define OFF_A 0
#define OFF_B (1 * MAT)
#define STAGE_BYTES (2 * MAT)        // 32768
#define NPIPE 3
#define GSMEM_TOTAL (NPIPE * STAGE_BYTES)  // 98304

__device__ __forceinline__ void load_stage(uint32_t sb,
                                           const __half* __restrict__ A,
                                           const __half* __restrict__ B,
                                           int m0, int n0, int kt, int tid) {
#pragma unroll
    for (int i = 0; i < 4; i++) {
        int idx = tid + i * 256;          // 0..1023
        int r = idx >> 3;                 // 0..127
        int c = idx & 7;                  // 16B chunk 0..7
        uint32_t so = (uint32_t)(r * 128 + ((c ^ (r & 7)) << 4));
        cp16(sb + OFF_A + so, A + (size_t)(m0 + r) * DD + kt + c * 8);
        cp16(sb + OFF_B + so, B + (size_t)(n0 + r) * DD + kt + c * 8);
    }
}

// OUT_MODE 0: fp32 C.  OUT_MODE 2: single fp16 (scale).
template <int OUT_MODE>
__device__ __forceinline__ void gemm_core(const __half* __restrict__ A,
                                          const __half* __restrict__ B,
                                          float* __restrict__ C,
                                          __half* __restrict__ Ch,
                                          float scale, int m0, int n0) {
    extern __shared__ char sm[];
    uint32_t sbase = smem_u32(sm);
    const int tid = threadIdx.x;
    const int wid = tid >> 5;
    const int lane = tid & 31;
    const int wm = wid & 3;
    const int wn = wid >> 2;

    const int g = lane >> 3;
    const int rr = lane & 7;
    const int rA = wm * 32 + (g & 1) * 8 + rr;
    const uint32_t aBase = (uint32_t)(rA * 128);
    const int swA = rA & 7;
    const int caBase = g >> 1;
    const int rB = wn * 64 + (g >> 1) * 8 + rr;
    const uint32_t bBase = (uint32_t)(rB * 128);
    const int swB = rB & 7;
    const int cbBase = g & 1;

    float acc[2][8][4];
#pragma unroll
    for (int mi = 0; mi < 2; mi++)
#pragma unroll
        for (int ni = 0; ni < 8; ni++)
#pragma unroll
            for (int j = 0; j < 4; j++) acc[mi][ni][j] = 0.0f;

    const int NST = DD / BK;   // 16
    load_stage(sbase + 0 * STAGE_BYTES, A, B, m0, n0, 0, tid);
    CP_COMMIT();
    load_stage(sbase + 1 * STAGE_BYTES, A, B, m0, n0, BK, tid);
    CP_COMMIT();

    int sidx = 0;
    for (int s = 0; s < NST; s++) {
        if (s < NST - 1) { CP_WAIT(1); } else { CP_WAIT(0); }
        __syncthreads();
        if (s + 2 < NST) {
            int nb = sidx + 2; if (nb >= 3) nb -= 3;
            load_stage(sbase + nb * STAGE_BYTES, A, B, m0, n0, (s + 2) * BK, tid);
            CP_COMMIT();
        }
        uint32_t sb = sbase + sidx * STAGE_BYTES;

#pragma unroll
        for (int kk = 0; kk < 4; kk++) {
            uint32_t ah[2][4], bf[4][4];
            const uint32_t aco = (uint32_t)(((caBase + 2 * kk) ^ swA) << 4);
            const uint32_t bco = (uint32_t)(((cbBase + 2 * kk) ^ swB) << 4);
#pragma unroll
            for (int mi = 0; mi < 2; mi++)
                ldm4(ah[mi], sb + OFF_A + aBase + (uint32_t)(mi * 2048) + aco);
#pragma unroll
            for (int np = 0; np < 4; np++)
                ldm4(bf[np], sb + OFF_B + bBase + (uint32_t)(np * 2048) + bco);
#pragma unroll
            for (int mi = 0; mi < 2; mi++)
#pragma unroll
                for (int ni = 0; ni < 8; ni++)
                    mma16816(acc[mi][ni], ah[mi], bf[ni >> 1][(ni & 1) * 2], bf[ni >> 1][(ni & 1) * 2 + 1]);
        }
        sidx++; if (sidx == 3) sidx = 0;
    }

    const int row_b = m0 + wm * 32 + (lane >> 2);
    const int col_b = n0 + wn * 64 + (lane & 3) * 2;
#pragma unroll
    for (int mi = 0; mi < 2; mi++)
#pragma unroll
        for (int ni = 0; ni < 8; ni++) {
            int row = row_b + mi * 16;
            int col = col_b + ni * 8;
            if (OUT_MODE == 0) {
                *(float2*)&C[(size_t)row * DD + col] =
                    make_float2(acc[mi][ni][0], acc[mi][ni][1]);
                *(float2*)&C[(size_t)(row + 8) * DD + col] =
                    make_float2(acc[mi][ni][2], acc[mi][ni][3]);
            } else {
#pragma unroll
                for (int rh = 0; rh < 2; rh++) {
                    float v0 = acc[mi][ni][rh * 2 + 0] * scale;
                    float v1 = acc[mi][ni][rh * 2 + 1] * scale;
                    *(uint32_t*)&Ch[(size_t)(row + rh * 8) * DD + col] = pack_h2(v0, v1);
                }
            }
        }
}

// ---------------- attention body (128-key stages, 64-key halves, gated) ----------------
#define QT 16384                     // Q: 128 x 64 fp16 = 128B rows
#define KT 16384                     // K tile: 128 rows x 128B
#define OFF_ST QT
#define STG (2 * KT)                 // 32768 (K, V)

__device__ __forceinline__ void kv_load(uint32_t stage, size_t gkv, int k0, int tid) {
#pragma unroll
    for (int i = 0; i < 8; i++) {
        int idx = tid + i * 256;          // 0..2047
        int tile = idx >> 10;             // 0=K, 1=V
        int rem = idx & 1023;
        int r = rem >> 3;                 // 0..127
        int c = rem & 7;
        const __half* src = tile ? g_v : g_k;
        cp16(stage + (uint32_t)(tile * KT + r * 128 + ((c ^ (r & 7)) << 4)),
             src + gkv + (size_t)(k0 + r) * DD + c * 8);
    }
}

__device__ __forceinline__ void attn_body(int abid) {
    extern __shared__ char sm[];
    uint32_t sb = smem_u32(sm);
    const int tid = threadIdx.x;
    const int wid = tid >> 5;
    const int lane = tid & 31;
    const int bh_idx = abid >> 4;         // 0..63
    const int b = bh_idx >> 4;
    const int h = bh_idx & 15;
    const int qx = abid & 15;
    const int q0 = (15 - qx) * 128;       // reversed: longest first
    const int mt0 = b << 4;

    // gate: Q tile and first KV tile ready
    if (tid == 0) {
        spin_until(&g_cnt[mt0 + (q0 >> 7)], 8);
        spin_until(&g_cnt[64 + mt0], 16);
    }
    __syncthreads();

    const size_t gq = (size_t)(b * SS + q0) * DD + h * HD;
    const size_t gkv = (size_t)(b * SS) * DD + h * HD;

    // load Q tile, swizzled
#pragma unroll
    for (int i = 0; i < 4; i++) {
        int r = i * 32 + (tid >> 3);
        int c = tid & 7;
        cp16(sb + (uint32_t)(r * 128 + ((c ^ (r & 7)) << 4)),
             g_q + gq + (size_t)r * DD + c * 8);
    }
    kv_load(sb + OFF_ST, gkv, 0, tid);
    CP_COMMIT();
    CP_WAIT(0);
    __syncthreads();

    // Q A-fragments
    uint32_t qh[4][4];
    {
        const int rQ = 16 * wid + (lane & 15);
        const int tQ = lane >> 4;
        const uint32_t qrow = sb + (uint32_t)(rQ * 128);
        const int sQ = rQ & 7;
#pragma unroll
        for (int q = 0; q < 4; q++)
            ldm4(qh[q], qrow + (uint32_t)(((tQ + 2 * q) ^ sQ) << 4));
    }

    const int rK = ((lane >> 4) << 3) + (lane & 7);
    const int tK = (lane >> 3) & 1;
    const int sK = rK & 7;
    const uint32_t kBase = (uint32_t)(rK * 128);
    const int rV = lane & 15;
    const int tV = lane >> 4;
    const int sV = rV & 7;
    const uint32_t vBase = (uint32_t)(rV * 128);

    float o[8][4];
#pragma unroll
    for (int nt = 0; nt < 8; nt++)
#pragma unroll
        for (int j = 0; j < 4; j++) o[nt][j] = 0.0f;
    float l0 = 0.0f, l1 = 0.0f;

    const int row0 = q0 + 16 * wid + (lane >> 2);
    const int row_min = q0 + 16 * wid;
    const int qrow_hi = q0 + 16 * wid + 15;
    const int ntiles = q0 / 128 + 1;     // 128-key stages

    for (int it = 0; it < ntiles; it++) {
        if (it + 1 < ntiles) {
            // gate next KV tile, then prefetch it
            if (tid == 0) spin_until(&g_cnt[64 + mt0 + it + 1], 16);
            __syncthreads();
            kv_load(sb + OFF_ST + ((it + 1) & 1) * STG, gkv, (it + 1) * 128, tid);
            CP_COMMIT();
            CP_WAIT(1);
        } else {
            CP_WAIT(0);
        }
        __syncthreads();
        const uint32_t stage = sb + OFF_ST + (it & 1) * STG;

#pragma unroll
        for (int h2 = 0; h2 < 2; h2++) {
            const int k0 = it * 128 + h2 * 64;
            if (k0 > qrow_hi) break;
            const uint32_t kst = stage + (uint32_t)(h2 * 8192);
            const uint32_t vst = stage + KT + (uint32_t)(h2 * 8192);

            // ---- S = Q K^T, single pass ----
            float s[8][4];
#pragma unroll
            for (int nt = 0; nt < 8; nt++)
#pragma unroll
                for (int j = 0; j < 4; j++) s[nt][j] = 0.0f;

#pragma unroll
            for (int q = 0; q < 4; q++) {
                const uint32_t kc = (uint32_t)((((2 * q) + tK) ^ sK) << 4);
#pragma unroll
                for (int pp = 0; pp < 2; pp++) {
                    uint32_t kf[2][4];
#pragma unroll
                    for (int p2 = 0; p2 < 2; p2++)
                        ldm4(kf[p2], kst + kBase + (uint32_t)((pp * 2 + p2) * 2048) + kc);
#pragma unroll
                    for (int p2 = 0; p2 < 2; p2++) {
                        int p = pp * 2 + p2;
                        mma16816(s[2 * p], qh[q], kf[p2][0], kf[p2][1]);
                        mma16816(s[2 * p + 1], qh[q], kf[p2][2], kf[p2][3]);
                    }
                }
            }

            // ---- causal mask ----
            if (k0 + 63 > row_min) {
#pragma unroll
                for (int nt = 0; nt < 8; nt++) {
                    int key = k0 + nt * 8 + (lane & 3) * 2;
#pragma unroll
                    for (int j = 0; j < 4; j++) {
                        int r = row0 + (j >> 1) * 8;
                        if (key + (j & 1) > r) s[nt][j] = -1e30f;
                    }
                }
            }

            // ---- no-max softmax: P = 2^s ----
#pragma unroll
            for (int nt = 0; nt < 8; nt++) {
                s[nt][0] = ex2f(s[nt][0]);
                s[nt][1] = ex2f(s[nt][1]);
                s[nt][2] = ex2f(s[nt][2]);
                s[nt][3] = ex2f(s[nt][3]);
                l0 += s[nt][0] + s[nt][1];
                l1 += s[nt][2] + s[nt][3];
            }

            // ---- PV, single pass ----
#pragma unroll
            for (int kk = 0; kk < 4; kk++) {
                uint32_t pah[4];
                pah[0] = pack_h2(s[2 * kk][0], s[2 * kk][1]);
                pah[1] = pack_h2(s[2 * kk][2], s[2 * kk][3]);
                pah[2] = pack_h2(s[2 * kk + 1][0], s[2 * kk + 1][1]);
                pah[3] = pack_h2(s[2 * kk + 1][2], s[2 * kk + 1][3]);
                const uint32_t vrow = vst + vBase + (uint32_t)(kk * 2048);
#pragma unroll
                for (int uu = 0; uu < 2; uu++) {
                    uint32_t vf[2][4];
#pragma unroll
                    for (int u2 = 0; u2 < 2; u2++)
                        ldm4t(vf[u2], vrow + (uint32_t)((((2 * (uu * 2 + u2)) + tV) ^ sV) << 4));
#pragma unroll
                    for (int u2 = 0; u2 < 2; u2++) {
                        int u = uu * 2 + u2;
                        mma16816(o[2 * u], pah, vf[u2][0], vf[u2][1]);
                        mma16816(o[2 * u + 1], pah, vf[u2][2], vf[u2][3]);
                    }
                }
            }
        }
        __syncthreads();
    }

    // ---- finalize: normalize, fp16 out ----
    l0 += __shfl_xor_sync(0xffffffffu, l0, 1);
    l0 += __shfl_xor_sync(0xffffffffu, l0, 2);
    l1 += __shfl_xor_sync(0xffffffffu, l1, 1);
    l1 += __shfl_xor_sync(0xffffffffu, l1, 2);
    float inv0 = 1.0f / l0;
    float inv1 = 1.0f / l1;

    const int grow0 = b * SS + q0 + 16 * wid + (lane >> 2);
    const int gcol = h * HD + (lane & 3) * 2;
#pragma unroll
    for (int nt = 0; nt < 8; nt++) {
#pragma unroll
        for (int rh = 0; rh < 2; rh++) {
            float inv = rh ? inv1 : inv0;
            float v0 = o[nt][rh * 2 + 0] * inv;
            float v1 = o[nt][rh * 2 + 1] * inv;
            size_t off = (size_t)(grow0 + rh * 8) * DD + gcol + nt * 8;
            *(uint32_t*)&g_oa[off] = pack_h2(v0, v1);
        }
    }

    // ---- publish completion for this (b, qblock) m-tile ----
    __threadfence();
    __syncthreads();
    if (tid == 0)
        atomicAdd(&g_cnt[128 + mt0 + (q0 >> 7)], 1);
}

// ---------------- mega kernel: QKV + attention + out-projection ----------------
// bids [0,512): Q tiles. [512,1536): K/V interleaved per m-tile.
// bids [1536,2560): attention. [2560,3072): out-proj.
__global__ void __launch_bounds__(256, 2)
mega_kernel(float* __restrict__ out) {
    const int bid = blockIdx.x;
    if (bid < 1536) {
        int z, mt, n;
        if (bid < 512) { z = 0; mt = bid >> 3; n = bid & 7; }
        else {
            int t = bid - 512;            // 0..1023
            mt = t >> 4;
            int sub = t & 15;
            z = 1 + (sub >> 3);
            n = sub & 7;
        }
        const int m0 = mt * 128, n0 = n * 128;
        if (z == 0)      gemm_core<2>(g_x, g_wq, nullptr, g_q, QSCALE, m0, n0);
        else if (z == 1) gemm_core<2>(g_x, g_wk, nullptr, g_k, 1.0f, m0, n0);
        else             gemm_core<2>(g_x, g_wv, nullptr, g_v, 1.0f, m0, n0);
        __threadfence();
        __syncthreads();
        if (threadIdx.x == 0)
            atomicAdd(&g_cnt[(z == 0 ? 0 : 64) + mt], 1);
    } else if (bid < 2560) {
        attn_body(bid - 1536);
    } else {
        const int obid = bid - 2560;
        const int mt = obid >> 3;               // m-tile 0..63
        const int m0 = mt * 128;
        const int n0 = (obid & 7) * 128;
        if (threadIdx.x == 0) spin_until(&g_cnt[128 + mt], 16);
        __syncthreads();
        gemm_core<0>(g_oa, g_wo, out, nullptr, 1.0f, m0, n0);
    }
}

// ---------------- launch ----------------
extern "C" void kernel_launch(void* const* d_in, const int* in_sizes, int n_in,
                              void* d_out, int out_size) {
    const float* x  = (const float*)d_in[0];
    const float* Wq = (const float*)d_in[1];
    const float* Wk = (const float*)d_in[2];
    const float* Wv = (const float*)d_in[3];
    const float* Wo = (const float*)d_in[4];
    float* out = (float*)d_out;

    cudaFuncSetAttribute(mega_kernel,
                         cudaFuncAttributeMaxDynamicSharedMemorySize, GSMEM_TOTAL);

    prep_kernel<<<12288, 256>>>(x, Wq, Wk, Wv, Wo);
    mega_kernel<<<3072, 256, GSMEM_TOTAL>>>(out);
}